// round 13
// baseline (speedup 1.0000x reference)
#include <cuda_runtime.h>
#include <cuda_bf16.h>
#include <cuda_fp16.h>
#include <math.h>
#include <float.h>
#include <stdint.h>

#define Bn 16
#define Tn 750
#define Fd 2048
#define NC 20
#define K6 6144
#define M_EMB 12000
#define SROWS 592
#define TOKROWS 5920
#define AOROWS 14208

#define OUT_VS   0
#define OUT_ACT  320
#define OUT_A2   12320
#define OUT_CAS  24320
#define OUT_RH   264320
#define OUT_EA   264512
#define OUT_EB   5179712
#define OUT_HA   10094912
#define OUT_HB   11307328

// ---------------- scratch (device globals) ----------------
__device__ float g_emb [(size_t)M_EMB * Fd];
__device__ float g_qkv [(size_t)TOKROWS * K6];
__device__ float g_c1o [(size_t)AOROWS * 128];
__device__ float g_sel [4 * Bn * Tn];
__device__ float g_med [Bn];
__device__ int   g_idx [5984];
__device__ float g_vmean[Bn * NC];

// fp16 split-2 planes for embed GEMM (hh product)
__device__ __half g_xh  [2 * (size_t)M_EMB * Fd];          // x: h, l(*2048)
__device__ __half g_wkh [2 * (size_t)3 * Fd * Fd];         // w_embed: [split][sh][o][e]
// bf16 copies for the residual products (hl, lh) — run at full bf16 mma rate
__device__ __nv_bfloat16 g_xb  [2 * (size_t)M_EMB * Fd];   // bf16(x_h), bf16(x_l*2048)
__device__ __nv_bfloat16 g_wkb [2 * (size_t)3 * Fd * Fd];  // bf16(w_h), bf16(w_l*2048)

// bf16 split-2 planes for trio GEMMs
__device__ __nv_bfloat16 g_tok2 [2 * (size_t)TOKROWS * Fd];
__device__ __nv_bfloat16 g_inw2 [2 * (size_t)K6 * Fd];
__device__ __nv_bfloat16 g_aop2 [2 * (size_t)AOROWS * Fd];
__device__ __nv_bfloat16 g_outw2[2 * (size_t)Fd * Fd];
__device__ __nv_bfloat16 g_ao2  [2 * (size_t)AOROWS * Fd];
__device__ __nv_bfloat16 g_c1w2 [2 * (size_t)3 * 128 * Fd];

__device__ __constant__ int d_aset[12] = {1,3,0,5,7,4,9,3,8,3,6,2};
__device__ __constant__ int d_bset[12] = {8,2,3,9,6,7,8,9,7,7,3,7};

// ================= MMA helpers (sm_80+ base features) =================
__device__ __forceinline__ uint32_t smem_to_u32(const void* p) {
    uint32_t a;
    asm("{ .reg .u64 t; cvta.to.shared.u64 t, %1; cvt.u32.u64 %0, t; }" : "=r"(a) : "l"(p));
    return a;
}
__device__ __forceinline__ void ldmatrix_x4(uint32_t* r, uint32_t addr) {
    asm volatile("ldmatrix.sync.aligned.m8n8.x4.shared.b16 {%0,%1,%2,%3}, [%4];"
        : "=r"(r[0]), "=r"(r[1]), "=r"(r[2]), "=r"(r[3]) : "r"(addr));
}
__device__ __forceinline__ void mma_bf16(float* d, const uint32_t* a, uint32_t b0, uint32_t b1) {
    asm volatile("mma.sync.aligned.m16n8k16.row.col.f32.bf16.bf16.f32 "
        "{%0,%1,%2,%3}, {%4,%5,%6,%7}, {%8,%9}, {%0,%1,%2,%3};"
        : "+f"(d[0]), "+f"(d[1]), "+f"(d[2]), "+f"(d[3])
        : "r"(a[0]), "r"(a[1]), "r"(a[2]), "r"(a[3]), "r"(b0), "r"(b1));
}
__device__ __forceinline__ void mma_bf16_z(float* d, const uint32_t* a, uint32_t b0, uint32_t b1) {
    asm volatile("mma.sync.aligned.m16n8k16.row.col.f32.bf16.bf16.f32 "
        "{%0,%1,%2,%3}, {%4,%5,%6,%7}, {%8,%9}, {%10,%11,%12,%13};"
        : "=f"(d[0]), "=f"(d[1]), "=f"(d[2]), "=f"(d[3])
        : "r"(a[0]), "r"(a[1]), "r"(a[2]), "r"(a[3]), "r"(b0), "r"(b1),
          "f"(0.f), "f"(0.f), "f"(0.f), "f"(0.f));
}
__device__ __forceinline__ void mma_f16(float* d, const uint32_t* a, uint32_t b0, uint32_t b1) {
    asm volatile("mma.sync.aligned.m16n8k16.row.col.f32.f16.f16.f32 "
        "{%0,%1,%2,%3}, {%4,%5,%6,%7}, {%8,%9}, {%0,%1,%2,%3};"
        : "+f"(d[0]), "+f"(d[1]), "+f"(d[2]), "+f"(d[3])
        : "r"(a[0]), "r"(a[1]), "r"(a[2]), "r"(a[3]), "r"(b0), "r"(b1));
}
__device__ __forceinline__ void mma_f16_z(float* d, const uint32_t* a, uint32_t b0, uint32_t b1) {
    asm volatile("mma.sync.aligned.m16n8k16.row.col.f32.f16.f16.f32 "
        "{%0,%1,%2,%3}, {%4,%5,%6,%7}, {%8,%9}, {%10,%11,%12,%13};"
        : "=f"(d[0]), "=f"(d[1]), "=f"(d[2]), "=f"(d[3])
        : "r"(a[0]), "r"(a[1]), "r"(a[2]), "r"(a[3]), "r"(b0), "r"(b1),
          "f"(0.f), "f"(0.f), "f"(0.f), "f"(0.f));
}
__device__ __forceinline__ void cp_async16(uint32_t dst, const void* src, int srcsize) {
    asm volatile("cp.async.ca.shared.global [%0], [%1], 16, %2;"
        :: "r"(dst), "l"(src), "r"(srcsize));
}

// ================= trio GEMM: bf16, undrained (R6/R9-proven) =================
struct Seg { const __nv_bfloat16* A; const __nv_bfloat16* B; int shift; };
struct GArgs {
    Seg segs[9];
    int nseg, M, N, Tper, act, ldc;
    float* C; const float* bias;
    __nv_bfloat16* So_h; __nv_bfloat16* So_l;
};

#define TG_SMEM 65536

__device__ __forceinline__ void tg_load(const GArgs& ga, uint32_t smb, int ci, int p,
                                        int bm, int bn, int tid) {
    const Seg s = ga.segs[ci >> 5];
    const int k0 = (ci & 31) * 64;
    const uint32_t abase = smb + p * 32768;
    const uint32_t bbase = abase + 16384;
#pragma unroll
    for (int g = 0; g < 4; ++g) {
        int id = tid + g * 256;
        int row = id >> 3, c = id & 7;
        uint32_t soff = row * 128 + ((c ^ (row & 7)) * 16);
        {
            int m = bm + row;
            const void* src = s.A;
            int sz = 0;
            if (m < ga.M) {
                int srow = m;
                bool ok = true;
                if (ga.Tper) {
                    int t = m % ga.Tper; int ts = t + s.shift;
                    ok = (ts >= 0 && ts < ga.Tper);
                    srow = m + s.shift;
                }
                if (ok) { src = s.A + (size_t)srow * 2048 + k0 + c * 8; sz = 16; }
            }
            cp_async16(abase + soff, src, sz);
        }
        {
            int n = bn + row;
            const void* src = s.B;
            int sz = 0;
            if (n < ga.N) { src = s.B + (size_t)n * 2048 + k0 + c * 8; sz = 16; }
            cp_async16(bbase + soff, src, sz);
        }
    }
    asm volatile("cp.async.commit_group;" ::: "memory");
}

__global__ void __launch_bounds__(256) tgemm(GArgs ga) {
    extern __shared__ char gsm[];
    const uint32_t smb = smem_to_u32(gsm);
    const int tid = threadIdx.x;
    const int wid = tid >> 5, lane = tid & 31;
    const int bm = blockIdx.y * 128;
    const int bn = blockIdx.x * 128;
    const int mw = (wid & 3) * 32;
    const int nw = (wid >> 2) * 64;
    const int nchunk = ga.nseg * 32;

    float acc[2][8][4];
#pragma unroll
    for (int i = 0; i < 2; ++i)
#pragma unroll
        for (int j = 0; j < 8; ++j)
#pragma unroll
            for (int q = 0; q < 4; ++q) acc[i][j][q] = 0.f;

    tg_load(ga, smb, 0, 0, bm, bn, tid);

    const int quad = lane >> 3, ri = lane & 7;

    for (int ci = 0; ci < nchunk; ++ci) {
        if (ci + 1 < nchunk) {
            tg_load(ga, smb, ci + 1, (ci + 1) & 1, bm, bn, tid);
            asm volatile("cp.async.wait_group 1;" ::: "memory");
        } else {
            asm volatile("cp.async.wait_group 0;" ::: "memory");
        }
        __syncthreads();

        const uint32_t abase = smb + (ci & 1) * 32768;
        const uint32_t bbase = abase + 16384;
#pragma unroll
        for (int ks = 0; ks < 4; ++ks) {
            const int kc = ks * 2;
            uint32_t afr[2][4];
#pragma unroll
            for (int mt = 0; mt < 2; ++mt) {
                int row = mw + mt * 16 + ri + (quad & 1) * 8;
                int ch = (kc + (quad >> 1)) ^ (row & 7);
                ldmatrix_x4(afr[mt], abase + row * 128 + ch * 16);
            }
#pragma unroll
            for (int np = 0; np < 4; ++np) {
                uint32_t bfr[4];
                int nrow = nw + np * 16 + ri + (quad >> 1) * 8;
                int ch = (kc + (quad & 1)) ^ (nrow & 7);
                ldmatrix_x4(bfr, bbase + nrow * 128 + ch * 16);
#pragma unroll
                for (int mt = 0; mt < 2; ++mt) {
                    mma_bf16(acc[mt][np * 2],     afr[mt], bfr[0], bfr[1]);
                    mma_bf16(acc[mt][np * 2 + 1], afr[mt], bfr[2], bfr[3]);
                }
            }
        }
        __syncthreads();
    }

#pragma unroll
    for (int mt = 0; mt < 2; ++mt) {
#pragma unroll
        for (int nt = 0; nt < 8; ++nt) {
            int col = bn + nw + nt * 8 + (lane & 3) * 2;
            if (col >= ga.N) continue;
#pragma unroll
            for (int h = 0; h < 2; ++h) {
                int row = bm + mw + mt * 16 + (lane >> 2) + h * 8;
                if (row >= ga.M) continue;
#pragma unroll
                for (int q = 0; q < 2; ++q) {
                    int c = col + q;
                    float v = acc[mt][nt][h * 2 + q];
                    if (ga.bias) v += ga.bias[c];
                    if (ga.act == 1) v = fmaxf(v, 0.f);
                    else if (ga.act == 2) v = (v >= 0.f) ? v : 0.2f * v;
                    size_t off = (size_t)row * ga.ldc + c;
                    if (ga.C) ga.C[off] = v;
                    if (ga.So_h) {
                        __nv_bfloat16 hh = __float2bfloat16(v);
                        ga.So_h[off] = hh;
                        ga.So_l[off] = __float2bfloat16(v - __bfloat162float(hh));
                    }
                }
            }
        }
    }
}

// ===== embed GEMM: mixed fp16/bf16 split-2, drained every 4 chunks (R9 base) =====
// hh product in fp16 (exact operands required); hl/lh residual products in bf16
// (full-rate; operand rounding perturbs result by ~2^-21 — negligible).
struct SegH { const __half* A; const __half* B; int shift; float scale; int bf; };
struct HArgs { SegH segs[9]; const float* bias; float* C; };

__device__ __forceinline__ void tg_load_h(const HArgs& ha, uint32_t smb, int ci, int p,
                                          int bm, int bn, int tid) {
    const SegH s = ha.segs[ci >> 5];
    const int k0 = (ci & 31) * 64;
    const uint32_t abase = smb + p * 32768;
    const uint32_t bbase = abase + 16384;
#pragma unroll
    for (int g = 0; g < 2; ++g) {
        int id = tid + g * 512;
        int row = id >> 3, c = id & 7;
        uint32_t soff = row * 128 + ((c ^ (row & 7)) * 16);
        {
            int m = bm + row;
            const void* src = s.A;
            int sz = 0;
            if (m < M_EMB) {
                int t = m % Tn;
                int ts = t + s.shift;
                if (ts >= 0 && ts < Tn) { src = s.A + (size_t)(m + s.shift) * 2048 + k0 + c * 8; sz = 16; }
            }
            cp_async16(abase + soff, src, sz);
        }
        {
            int n = bn + row;    // N = 2048, always in range
            cp_async16(bbase + soff, s.B + (size_t)n * 2048 + k0 + c * 8, 16);
        }
    }
    asm volatile("cp.async.commit_group;" ::: "memory");
}

__global__ void __launch_bounds__(512) tgemm_emb(HArgs ha) {
    extern __shared__ char gsm[];
    const uint32_t smb = smem_to_u32(gsm);
    const int tid = threadIdx.x;
    const int wid = tid >> 5, lane = tid & 31;
    const int bm = blockIdx.y * 128;
    const int bn = blockIdx.x * 128;
    const int mw = (wid & 3) * 32;
    const int nw = (wid >> 2) * 32;
    const int nchunk = 9 * 32;

    float sum[2][4][4];
    float acc[2][4][4];
#pragma unroll
    for (int i = 0; i < 2; ++i)
#pragma unroll
        for (int j = 0; j < 4; ++j)
#pragma unroll
            for (int q = 0; q < 4; ++q) sum[i][j][q] = 0.f;

    tg_load_h(ha, smb, 0, 0, bm, bn, tid);

    const int quad = lane >> 3, ri = lane & 7;

    for (int ci = 0; ci < nchunk; ++ci) {
        if (ci + 1 < nchunk) {
            tg_load_h(ha, smb, ci + 1, (ci + 1) & 1, bm, bn, tid);
            asm volatile("cp.async.wait_group 1;" ::: "memory");
        } else {
            asm volatile("cp.async.wait_group 0;" ::: "memory");
        }
        __syncthreads();

        const uint32_t abase = smb + (ci & 1) * 32768;
        const uint32_t bbase = abase + 16384;
        const bool fresh = ((ci & 3) == 0);
        const int sbf = ha.segs[ci >> 5].bf;
#pragma unroll
        for (int ks = 0; ks < 4; ++ks) {
            const int kc = ks * 2;
            uint32_t afr[2][4];
#pragma unroll
            for (int mt = 0; mt < 2; ++mt) {
                int row = mw + mt * 16 + ri + (quad & 1) * 8;
                int ch = (kc + (quad >> 1)) ^ (row & 7);
                ldmatrix_x4(afr[mt], abase + row * 128 + ch * 16);
            }
#pragma unroll
            for (int bt = 0; bt < 2; ++bt) {
                uint32_t bfr[4];
                int nrow = nw + bt * 16 + ri + (quad >> 1) * 8;
                int ch = (kc + (quad & 1)) ^ (nrow & 7);
                ldmatrix_x4(bfr, bbase + nrow * 128 + ch * 16);
#pragma unroll
                for (int mt = 0; mt < 2; ++mt) {
                    if (fresh && ks == 0) {
                        if (sbf) {
                            mma_bf16_z(acc[mt][bt * 2],     afr[mt], bfr[0], bfr[1]);
                            mma_bf16_z(acc[mt][bt * 2 + 1], afr[mt], bfr[2], bfr[3]);
                        } else {
                            mma_f16_z(acc[mt][bt * 2],     afr[mt], bfr[0], bfr[1]);
                            mma_f16_z(acc[mt][bt * 2 + 1], afr[mt], bfr[2], bfr[3]);
                        }
                    } else {
                        if (sbf) {
                            mma_bf16(acc[mt][bt * 2],     afr[mt], bfr[0], bfr[1]);
                            mma_bf16(acc[mt][bt * 2 + 1], afr[mt], bfr[2], bfr[3]);
                        } else {
                            mma_f16(acc[mt][bt * 2],     afr[mt], bfr[0], bfr[1]);
                            mma_f16(acc[mt][bt * 2 + 1], afr[mt], bfr[2], bfr[3]);
                        }
                    }
                }
            }
        }
        // drain every 4 chunks (chain-16; R9-proven numerics)
        if ((ci & 3) == 3) {
            const float scl = ha.segs[ci >> 5].scale;
#pragma unroll
            for (int i = 0; i < 2; ++i)
#pragma unroll
                for (int j = 0; j < 4; ++j)
#pragma unroll
                    for (int q = 0; q < 4; ++q) sum[i][j][q] += acc[i][j][q] * scl;
        }
        __syncthreads();
    }

#pragma unroll
    for (int mt = 0; mt < 2; ++mt) {
#pragma unroll
        for (int nt = 0; nt < 4; ++nt) {
            int col = bn + nw + nt * 8 + (lane & 3) * 2;
#pragma unroll
            for (int h = 0; h < 2; ++h) {
                int row = bm + mw + mt * 16 + (lane >> 2) + h * 8;
                if (row >= M_EMB) continue;
#pragma unroll
                for (int q = 0; q < 2; ++q) {
                    int c = col + q;
                    float v = sum[mt][nt][h * 2 + q] + ha.bias[c];
                    ha.C[(size_t)row * Fd + c] = fmaxf(v, 0.f);
                }
            }
        }
    }
}

// ================= split kernels =================
#define RSCALE 2048.f
__global__ void split2h_x(const float* __restrict__ s, __half* h, __half* l,
                          __nv_bfloat16* bh, __nv_bfloat16* bl, long n) {
    for (long i = blockIdx.x * (long)blockDim.x + threadIdx.x; i < n;
         i += (long)gridDim.x * blockDim.x) {
        float x = s[i];
        __half a = __float2half(x);
        float xh = __half2float(a);
        float r = (x - xh) * RSCALE;
        __half lr = __float2half(r);
        h[i] = a; l[i] = lr;
        bh[i] = __float2bfloat16(xh);
        bl[i] = __float2bfloat16(__half2float(lr));
    }
}
__global__ void split2h_wk(const float* __restrict__ w, __half* h, __half* l,
                           __nv_bfloat16* bh, __nv_bfloat16* bl) {
    const long n = 3L * Fd * Fd;
    for (long i = blockIdx.x * (long)blockDim.x + threadIdx.x; i < n;
         i += (long)gridDim.x * blockDim.x) {
        long sh = i / ((long)Fd * Fd);
        long rem = i - sh * (long)Fd * Fd;
        float x = w[rem * 3 + sh];
        __half a = __float2half(x);
        float xh = __half2float(a);
        float r = (x - xh) * RSCALE;
        __half lr = __float2half(r);
        h[i] = a; l[i] = lr;
        bh[i] = __float2bfloat16(xh);
        bl[i] = __float2bfloat16(__half2float(lr));
    }
}
__global__ void split2_kernel(const float* __restrict__ s, __nv_bfloat16* h,
                              __nv_bfloat16* l, long n) {
    for (long i = blockIdx.x * (long)blockDim.x + threadIdx.x; i < n;
         i += (long)gridDim.x * blockDim.x) {
        float x = s[i];
        __nv_bfloat16 a = __float2bfloat16(x);
        h[i] = a; l[i] = __float2bfloat16(x - __bfloat162float(a));
    }
}
__global__ void split2_c1w_kernel(const float* __restrict__ w, __nv_bfloat16* h,
                                  __nv_bfloat16* l) {
    const long n = 3L * 128 * Fd;
    for (long i = blockIdx.x * (long)blockDim.x + threadIdx.x; i < n;
         i += (long)gridDim.x * blockDim.x) {
        long sh = i / (128L * Fd);
        long rem = i - sh * 128L * Fd;
        float x = w[rem * 3 + sh];
        __nv_bfloat16 a = __float2bfloat16(x);
        h[i] = a; l[i] = __float2bfloat16(x - __bfloat162float(a));
    }
}

// ================= CAS + actionness =================
__global__ void __launch_bounds__(320) cas_kernel(const float* __restrict__ wcls,
                                                  float* __restrict__ dout)
{
    __shared__ float embs[5 * Fd];
    __shared__ float cres[5 * NC];
    const int b  = blockIdx.x / 150;
    const int t0 = (blockIdx.x % 150) * 5;
    const float* src = g_emb + ((size_t)b * Tn + t0) * Fd;
    for (int i = threadIdx.x; i < 5 * Fd; i += 320) embs[i] = src[i];
    __syncthreads();

    const int w = threadIdx.x >> 5, lane = threadIdx.x & 31;
    const int tl = w >> 1, cg = (w & 1) * 10;
    for (int c = cg; c < cg + 10; ++c) {
        float acc = 0.f;
        const float* wr = wcls + (size_t)c * Fd;
        const float* er = embs + tl * Fd;
        for (int e = lane; e < Fd; e += 32) acc += er[e] * wr[e];
#pragma unroll
        for (int off = 16; off; off >>= 1) acc += __shfl_down_sync(0xffffffffu, acc, off);
        if (lane == 0) cres[tl * NC + c] = fmaxf(acc, 0.f);
    }
    __syncthreads();

    if (threadIdx.x < 100) {
        int tl2 = threadIdx.x / NC, c2 = threadIdx.x % NC;
        dout[OUT_CAS + ((size_t)(b * Tn + t0 + tl2)) * NC + c2] = cres[tl2 * NC + c2];
    }
    if (threadIdx.x < 5) {
        float s = 0.f;
        for (int c = 0; c < NC; ++c) s += cres[threadIdx.x * NC + c];
        dout[OUT_ACT + b * Tn + t0 + threadIdx.x] = s;
    }
}

// ================= a2 =================
__global__ void a2_kernel(const float* __restrict__ tf1w, const float* __restrict__ tf1b,
                          const float* __restrict__ tf2w, const float* __restrict__ tf2b,
                          float* __restrict__ dout)
{
    __shared__ float a[Tn], a1[Tn];
    const int b = blockIdx.x;
    for (int t = threadIdx.x; t < Tn; t += blockDim.x) a[t] = dout[OUT_ACT + b*Tn + t];
    __syncthreads();
    for (int t = threadIdx.x; t < Tn; t += blockDim.x) {
        float v = tf1b[0];
#pragma unroll
        for (int k = 0; k < 3; ++k) { int tt = t+k-1; if (tt>=0 && tt<Tn) v += tf1w[k]*a[tt]; }
        a1[t] = fmaxf(v, 0.f);
    }
    __syncthreads();
    for (int t = threadIdx.x; t < Tn; t += blockDim.x) {
        float v = tf2b[0];
#pragma unroll
        for (int k = 0; k < 3; ++k) { int tt = t+k-1; if (tt>=0 && tt<Tn) v += tf2w[k]*a1[tt]; }
        dout[OUT_A2 + b*Tn + t] = fmaxf(v, 0.f);
    }
}

// ================= sorting =================
__device__ __forceinline__ unsigned int fkey(float v) {
    unsigned int b = __float_as_uint(v);
    return (b & 0x80000000u) ? ~b : (b | 0x80000000u);
}
__device__ __forceinline__ float fdec(unsigned int u) {
    unsigned int b = (u & 0x80000000u) ? (u ^ 0x80000000u) : ~u;
    return __uint_as_float(b);
}
__device__ void bitonic1024_u64(unsigned long long* key, int tid) {
    for (int k = 2; k <= 1024; k <<= 1)
        for (int j = k >> 1; j > 0; j >>= 1) {
            __syncthreads();
            for (int i = tid; i < 1024; i += 512) {
                int ixj = i ^ j;
                if (ixj > i) {
                    bool up = ((i & k) == 0);
                    unsigned long long a = key[i], b2 = key[ixj];
                    bool sw = up ? (a > b2) : (a < b2);
                    if (sw) { key[i] = b2; key[ixj] = a; }
                }
            }
        }
    __syncthreads();
}
__device__ void bitonic1024_u32(unsigned int* key, int tid) {
    for (int k = 2; k <= 1024; k <<= 1)
        for (int j = k >> 1; j > 0; j >>= 1) {
            __syncthreads();
            for (int i = tid; i < 1024; i += 512) {
                int ixj = i ^ j;
                if (ixj > i) {
                    bool up = ((i & k) == 0);
                    unsigned int a = key[i], b2 = key[ixj];
                    bool sw = up ? (a > b2) : (a < b2);
                    if (sw) { key[i] = b2; key[ixj] = a; }
                }
            }
        }
    __syncthreads();
}

__global__ void __launch_bounds__(512) sort_act_kernel(const float* __restrict__ dout) {
    __shared__ unsigned long long key[1024];
    const int b = blockIdx.x, tid = threadIdx.x;
    for (int i = tid; i < 1024; i += 512) {
        if (i < Tn) {
            unsigned int nu = ~fkey(dout[OUT_ACT + b*Tn + i]);
            key[i] = ((unsigned long long)nu << 32) | (unsigned int)i;
        } else key[i] = 0xFFFFFFFFFFFFFFFFull;
    }
    bitonic1024_u64(key, tid);
    for (int i = tid; i < 150; i += 512) g_idx[b*150 + i] = (int)(key[i] & 0xffffffffu);
    if (tid == 0) {
        float v0 = fdec(~(unsigned int)(key[374] >> 32));
        float v1 = fdec(~(unsigned int)(key[375] >> 32));
        g_med[b] = 0.5f * (v0 + v1);
    }
}

__global__ void morph_kernel(const float* __restrict__ dout) {
    __shared__ float a[Tn];
    __shared__ float bin[Tn];
    __shared__ float red[256];
    const int b = blockIdx.x, tid = threadIdx.x;
    float lmax = -FLT_MAX;
    for (int t = tid; t < Tn; t += 256) { float v = dout[OUT_ACT + b*Tn + t]; a[t] = v; lmax = fmaxf(lmax, v); }
    red[tid] = lmax; __syncthreads();
    for (int s = 128; s > 0; s >>= 1) { if (tid < s) red[tid] = fmaxf(red[tid], red[tid+s]); __syncthreads(); }
    float amax = red[0];
    float med = g_med[b];
    for (int t = tid; t < Tn; t += 256) bin[t] = (a[t] > med) ? 1.f : 0.f;
    __syncthreads();
    for (int t = tid; t < Tn; t += 256) {
        float e3 = 1.f, e6 = 1.f, d6 = 0.f, d3 = 0.f;
#pragma unroll
        for (int o = -1; o <= 1; ++o) { int u = t+o; float v = (u>=0&&u<Tn)?bin[u]:0.f; e3 = fminf(e3,v); d3 = fmaxf(d3,v); }
#pragma unroll
        for (int o = -3; o <= 2; ++o) { int u = t+o; float v = (u>=0&&u<Tn)?bin[u]:0.f; e6 = fminf(e6,v); }
#pragma unroll
        for (int o = -2; o <= 3; ++o) { int u = t+o; float v = (u>=0&&u<Tn)?bin[u]:0.f; d6 = fmaxf(d6,v); }
        g_sel[1*Bn*Tn + b*Tn + t] = amax - a[t];
        g_sel[2*Bn*Tn + b*Tn + t] = a[t] * (e3 - e6);
        g_sel[3*Bn*Tn + b*Tn + t] = a[t] * (d6 - d3);
    }
}

__global__ void __launch_bounds__(512) sort_gen_kernel() {
    __shared__ unsigned long long key[1024];
    const int aid = blockIdx.x / 16 + 1;
    const int b = blockIdx.x % 16;
    const int tid = threadIdx.x;
    const float* sc = g_sel + aid*Bn*Tn + b*Tn;
    const unsigned int msk = (aid == 1) ? 0xFFFFFFF8u : 0xFFFFFFFFu;
    for (int i = tid; i < 1024; i += 512) {
        if (i < Tn) {
            unsigned int nu = ~(fkey(sc[i]) & msk);
            key[i] = ((unsigned long long)nu << 32) | (unsigned int)i;
        } else key[i] = 0xFFFFFFFFFFFFFFFFull;
    }
    bitonic1024_u64(key, tid);
    if (aid == 1) { for (int i = tid; i < 150; i += 512) g_idx[2400 + b*150 + i] = (int)(key[i] & 0xffffffffu); }
    else if (aid == 2) { if (tid < 37) g_idx[4800 + b*37 + tid] = (int)(key[tid] & 0xffffffffu); }
    else { if (tid < 37) g_idx[5392 + b*37 + tid] = (int)(key[tid] & 0xffffffffu); }
}

__global__ void __launch_bounds__(256) gather_kernel(float* __restrict__ dout) {
    const int r = blockIdx.x; // 0..5983
    int b, j, srcidx, set = -1;
    float* dst;
    if (r < 2400) {
        b = r/150; j = r%150; srcidx = g_idx[b*150 + j];
        dst = dout + OUT_EA + (size_t)r * Fd;
        if (j < 148) set = j / 37;
    } else if (r < 4800) {
        int rr = r - 2400; b = rr/150; j = rr%150; srcidx = g_idx[2400 + b*150 + j];
        dst = dout + OUT_EB + (size_t)rr * Fd;
        if (j < 148) set = 4 + j / 37;
    } else if (r < 5392) {
        int rr = r - 4800; b = rr/37; j = rr%37; srcidx = g_idx[4800 + rr];
        dst = dout + OUT_HA + (size_t)rr * Fd; set = 8;
    } else {
        int rr = r - 5392; b = rr/37; j = rr%37; srcidx = g_idx[5392 + rr];
        dst = dout + OUT_HB + (size_t)rr * Fd; set = 9;
    }
    const float4* src = reinterpret_cast<const float4*>(g_emb + ((size_t)b*Tn + srcidx)*Fd);
    float4* d4 = reinterpret_cast<float4*>(dst);
    __nv_bfloat16* th = nullptr; __nv_bfloat16* tl = nullptr;
    if (set >= 0) {
        size_t tb = ((size_t)set*SROWS + b*37 + (j % 37))*Fd;
        th = g_tok2 + tb;
        tl = g_tok2 + (size_t)TOKROWS*Fd + tb;
    }
    for (int i = threadIdx.x; i < Fd/4; i += 256) {
        float4 v = src[i];
        d4[i] = v;
        if (th) {
            float vv[4] = {v.x, v.y, v.z, v.w};
#pragma unroll
            for (int q = 0; q < 4; ++q) {
                __nv_bfloat16 h = __float2bfloat16(vv[q]);
                th[i*4 + q] = h;
                tl[i*4 + q] = __float2bfloat16(vv[q] - __bfloat162float(h));
            }
        }
    }
}

// ================= attention (writes aopre split-2 planes) =================
__global__ void __launch_bounds__(256) attn_kernel() {
    __shared__ float qt[37*64];
    __shared__ float kt[37*64];
    __shared__ float s[37*37];
    const int id = blockIdx.x;
    const int h = id & 3, b = (id >> 2) & 15, m = id >> 6;
    const int rh = m >> 1, role = m & 1;
    const int as = d_aset[rh], bs = d_bset[rh];
    const int qset = role ? as : bs;
    const int kvset = role ? bs : as;
    const int trowbase = role ? 37 : 0;
    const int tid = threadIdx.x;
    const float scale = 0.044194173824159216f; // 1/sqrt(512)

    const float* Qb = g_qkv + ((size_t)(qset*SROWS + b*37)) * K6 + h*512;
    const float* Kb = g_qkv + ((size_t)(kvset*SROWS + b*37)) * K6 + 2048 + h*512;
    const float* Vb = g_qkv + ((size_t)(kvset*SROWS + b*37)) * K6 + 4096 + h*512;

    for (int i = tid; i < 1369; i += 256) s[i] = 0.f;
    for (int dt = 0; dt < 8; ++dt) {
        __syncthreads();
        for (int i = tid; i < 2368; i += 256) {
            int q = i >> 6, d = i & 63;
            qt[i] = Qb[(size_t)q*K6 + dt*64 + d];
            kt[i] = Kb[(size_t)q*K6 + dt*64 + d];
        }
        __syncthreads();
        for (int p = tid; p < 1369; p += 256) {
            int q = p / 37, k = p % 37;
            const float* qr = qt + q*64;
            const float* kr = kt + k*64;
            float acc = 0.f;
#pragma unroll
            for (int d = 0; d < 64; ++d) acc += qr[d] * kr[d];
            s[p] += acc;
        }
    }
    __syncthreads();
    {
        const int w = tid >> 5, lane = tid & 31;
        for (int r = w; r < 37; r += 8) {
            float sv0 = s[r*37 + lane] * scale;
            float sv1 = (lane < 5) ? s[r*37 + 32 + lane] * scale : -FLT_MAX;
            float mx = fmaxf(sv0, sv1);
#pragma unroll
            for (int off = 16; off; off >>= 1) mx = fmaxf(mx, __shfl_xor_sync(0xffffffffu, mx, off));
            float e0 = expf(sv0 - mx);
            float e1 = (lane < 5) ? expf(sv1 - mx) : 0.f;
            float sum = e0 + e1;
#pragma unroll
            for (int off = 16; off; off >>= 1) sum += __shfl_xor_sync(0xffffffffu, sum, off);
            float inv = 1.f / sum;
            s[r*37 + lane] = e0 * inv;
            if (lane < 5) s[r*37 + 32 + lane] = e1 * inv;
        }
    }
    const size_t rowbase = (size_t)(rh*1184 + b*74 + trowbase);
    for (int dt = 0; dt < 8; ++dt) {
        __syncthreads();
        for (int i = tid; i < 2368; i += 256) {
            int k = i >> 6, d = i & 63;
            kt[i] = Vb[(size_t)k*K6 + dt*64 + d];
        }
        __syncthreads();
        for (int p = tid; p < 2368; p += 256) {
            int q = p >> 6, d = p & 63;
            const float* sr = s + q*37;
            float acc = 0.f;
#pragma unroll
            for (int k = 0; k < 37; ++k) acc += sr[k] * kt[k*64 + d];
            size_t off = (rowbase + q)*Fd + h*512 + dt*64 + d;
            __nv_bfloat16 hh = __float2bfloat16(acc);
            g_aop2[off] = hh;
            g_aop2[(size_t)AOROWS*Fd + off] = __float2bfloat16(acc - __bfloat162float(hh));
        }
    }
}

// ================= c2 + l1 + l2 fused =================
__global__ void __launch_bounds__(256) tail_kernel(
    const float* __restrict__ c2w, const float* __restrict__ c2b,
    const float* __restrict__ l1w, const float* __restrict__ l1b,
    const float* __restrict__ l2w, const float* __restrict__ l2b,
    float* __restrict__ dout)
{
    __shared__ float sm[74*128];
    const int rb = blockIdx.x;
    const int tid = threadIdx.x;
    for (int i = tid; i < 74*128; i += 256)
        sm[i] = g_c1o[(size_t)rb*74*128 + i];
    __syncthreads();

    const int o = tid & 31;
    const int tbase = tid >> 5;
    float r[10];
    int nt = 0;
    for (int t = tbase; t < 74; t += 8) {
        float v = c2b[o];
#pragma unroll
        for (int k = 0; k < 3; ++k) {
            int tt = t + k - 1;
            if (tt >= 0 && tt < 74) {
                const float* row = sm + tt*128;
                const float* w = c2w + o*384 + k;
#pragma unroll 16
                for (int c = 0; c < 128; ++c) v += row[c] * w[c*3];
            }
        }
        r[nt++] = (v >= 0.f) ? v : 0.2f * v;
    }
    __syncthreads();
    { int i = 0; for (int t = tbase; t < 74; t += 8) sm[o*74 + t] = r[i++]; }
    __syncthreads();

    for (int p = tid; p < 320; p += 256) {
        int c = p / 10, j = p % 10;
        float v = l1b[j];
        const float* y = sm + c*74;
        const float* w = l1w + j*74;
        for (int t = 0; t < 74; ++t) v += y[t] * w[t];
        sm[2368 + p] = (v >= 0.f) ? v : 0.2f * v;
    }
    __syncthreads();
    float ps = 0.f;
    for (int p = tid; p < 320; p += 256) ps += sm[2368 + p] * l2w[p];
    sm[3000 + tid] = ps;
    __syncthreads();
    for (int s = 128; s > 0; s >>= 1) { if (tid < s) sm[3000+tid] += sm[3000+tid+s]; __syncthreads(); }
    if (tid == 0) {
        float x = sm[3000] + l2b[0];
        dout[OUT_RH + rb] = 1.f / (1.f + expf(-x));
    }
}

// ================= video scores =================
__global__ void __launch_bounds__(512) vsort_kernel(const float* __restrict__ dout) {
    __shared__ unsigned int key[1024];
    const int bc = blockIdx.x;
    const int b = bc / NC, c = bc % NC;
    const int tid = threadIdx.x;
    for (int i = tid; i < 1024; i += 512)
        key[i] = (i < Tn) ? ~fkey(dout[OUT_CAS + (size_t)(b*Tn + i)*NC + c]) : 0xFFFFFFFFu;
    bitonic1024_u32(key, tid);
    if (tid == 0) {
        float s = 0.f;
        for (int i = 0; i < 150; ++i) s += fdec(~key[i]);
        g_vmean[bc] = s / 150.f;
    }
}
__global__ void vsoftmax_kernel(float* __restrict__ dout) {
    const int b = blockIdx.x, t = threadIdx.x;
    float v = (t < NC) ? g_vmean[b*NC + t] : -FLT_MAX;
    float mx = v;
#pragma unroll
    for (int off = 16; off; off >>= 1) mx = fmaxf(mx, __shfl_xor_sync(0xffffffffu, mx, off));
    float e = (t < NC) ? expf(v - mx) : 0.f;
    float sum = e;
#pragma unroll
    for (int off = 16; off; off >>= 1) sum += __shfl_xor_sync(0xffffffffu, sum, off);
    if (t < NC) dout[OUT_VS + b*NC + t] = e / sum;
}

// ================= launch =================
extern "C" void kernel_launch(void* const* d_in, const int* in_sizes, int n_in,
                              void* d_out, int out_size) {
    const float* x    = (const float*)d_in[0];
    const float* wemb = (const float*)d_in[1];
    const float* bemb = (const float*)d_in[2];
    const float* wcls = (const float*)d_in[3];
    const float* tf1w = (const float*)d_in[4];
    const float* tf1b = (const float*)d_in[5];
    const float* tf2w = (const float*)d_in[6];
    const float* tf2b = (const float*)d_in[7];
    const float* inw  = (const float*)d_in[8];
    const float* inb  = (const float*)d_in[9];
    const float* outw = (const float*)d_in[10];
    const float* outb = (const float*)d_in[11];
    const float* c1w  = (const float*)d_in[12];
    const float* c1b  = (const float*)d_in[13];
    const float* c2w  = (const float*)d_in[14];
    const float* c2b  = (const float*)d_in[15];
    const float* l1w  = (const float*)d_in[16];
    const float* l1b  = (const float*)d_in[17];
    const float* l2w  = (const float*)d_in[18];
    const float* l2b  = (const float*)d_in[19];
    float* dout = (float*)d_out;

    float *p_emb, *p_qkv, *p_c1o;
    __half *p_xh, *p_wkh;
    __nv_bfloat16 *p_xb, *p_wkb;
    __nv_bfloat16 *p_tok2, *p_inw2, *p_aop2, *p_outw2, *p_ao2, *p_c1w2;
    cudaGetSymbolAddress((void**)&p_emb,  g_emb);
    cudaGetSymbolAddress((void**)&p_qkv,  g_qkv);
    cudaGetSymbolAddress((void**)&p_c1o,  g_c1o);
    cudaGetSymbolAddress((void**)&p_xh,   g_xh);
    cudaGetSymbolAddress((void**)&p_wkh,  g_wkh);
    cudaGetSymbolAddress((void**)&p_xb,   g_xb);
    cudaGetSymbolAddress((void**)&p_wkb,  g_wkb);
    cudaGetSymbolAddress((void**)&p_tok2, g_tok2);
    cudaGetSymbolAddress((void**)&p_inw2, g_inw2);
    cudaGetSymbolAddress((void**)&p_aop2, g_aop2);
    cudaGetSymbolAddress((void**)&p_outw2,g_outw2);
    cudaGetSymbolAddress((void**)&p_c1w2, g_c1w2);
    cudaGetSymbolAddress((void**)&p_ao2,  g_ao2);

    cudaFuncSetAttribute(tgemm, cudaFuncAttributeMaxDynamicSharedMemorySize, TG_SMEM);
    cudaFuncSetAttribute(tgemm_emb, cudaFuncAttributeMaxDynamicSharedMemorySize, TG_SMEM);

    const size_t XP   = (size_t)M_EMB * Fd;
    const size_t WKP  = (size_t)3 * Fd * Fd;
    const size_t TOKP = (size_t)TOKROWS * Fd;
    const size_t INWP = (size_t)K6 * Fd;
    const size_t AOP  = (size_t)AOROWS * Fd;
    const size_t OWP  = (size_t)Fd * Fd;
    const size_t C1P  = (size_t)3 * 128 * Fd;

    // splits (fp16 planes + bf16 copies for residual products)
    split2h_x<<<2048, 256>>>(x, p_xh, p_xh + XP, p_xb, p_xb + XP, (long)XP);
    split2h_wk<<<2048, 256>>>(wemb, p_wkh, p_wkh + WKP, p_wkb, p_wkb + WKP);
    split2_kernel<<<2048, 256>>>(inw, p_inw2, p_inw2 + INWP, (long)INWP);
    split2_kernel<<<1024, 256>>>(outw, p_outw2, p_outw2 + OWP, (long)OWP);
    split2_c1w_kernel<<<256, 256>>>(c1w, p_c1w2, p_c1w2 + C1P);

    // embed conv GEMM: mixed precision — hh in fp16, hl/lh in bf16 (full rate),
    // 3 shifts each, drained every 4 chunks (R9 numerics)
    {
        HArgs ha = {};
        const float S = 1.f / RSCALE;
        int q = 0;
        // hh (fp16)
        for (int sh = 0; sh < 3; ++sh) {
            ha.segs[q].A = p_xh;
            ha.segs[q].B = p_wkh + (size_t)sh * Fd * Fd;
            ha.segs[q].shift = sh - 1; ha.segs[q].scale = 1.f; ha.segs[q].bf = 0; ++q;
        }
        // hl (bf16): bf16(x_h) * bf16(w_l*2048)
        for (int sh = 0; sh < 3; ++sh) {
            ha.segs[q].A = (const __half*)p_xb;
            ha.segs[q].B = (const __half*)(p_wkb + WKP + (size_t)sh * Fd * Fd);
            ha.segs[q].shift = sh - 1; ha.segs[q].scale = S; ha.segs[q].bf = 1; ++q;
        }
        // lh (bf16): bf16(x_l*2048) * bf16(w_h)
        for (int sh = 0; sh < 3; ++sh) {
            ha.segs[q].A = (const __half*)(p_xb + XP);
            ha.segs[q].B = (const __half*)(p_wkb + (size_t)sh * Fd * Fd);
            ha.segs[q].shift = sh - 1; ha.segs[q].scale = S; ha.segs[q].bf = 1; ++q;
        }
        ha.bias = bemb; ha.C = p_emb;
        tgemm_emb<<<dim3(Fd/128, (M_EMB + 127)/128), 512, TG_SMEM>>>(ha);
    }

    cas_kernel<<<Bn*150, 320>>>(wcls, dout);
    a2_kernel<<<Bn, 256>>>(tf1w, tf1b, tf2w, tf2b, dout);
    sort_act_kernel<<<Bn, 512>>>(dout);
    morph_kernel<<<Bn, 256>>>(dout);
    sort_gen_kernel<<<48, 512>>>();
    gather_kernel<<<5984, 256>>>(dout);

    // QKV GEMM: bf16 split-2 x 3 products (undrained, proven fast)
    {
        GArgs ga = {};
        const int pa[3] = {0,0,1}, pb[3] = {0,1,0};
        for (int pr = 0; pr < 3; ++pr) {
            ga.segs[pr].A = p_tok2 + (size_t)pa[pr]*TOKP;
            ga.segs[pr].B = p_inw2 + (size_t)pb[pr]*INWP;
            ga.segs[pr].shift = 0;
        }
        ga.nseg = 3; ga.M = TOKROWS; ga.N = K6; ga.Tper = 0;
        ga.C = p_qkv; ga.bias = inb; ga.act = 0; ga.ldc = K6;
        tgemm<<<dim3(K6/128, (TOKROWS+127)/128), 256, TG_SMEM>>>(ga);
    }

    attn_kernel<<<1536, 256>>>();

    // out-proj GEMM: bf16 split-2, epilogue writes split-2 planes
    {
        GArgs ga = {};
        const int pa[3] = {0,0,1}, pb[3] = {0,1,0};
        for (int pr = 0; pr < 3; ++pr) {
            ga.segs[pr].A = p_aop2 + (size_t)pa[pr]*AOP;
            ga.segs[pr].B = p_outw2 + (size_t)pb[pr]*OWP;
            ga.segs[pr].shift = 0;
        }
        ga.nseg = 3; ga.M = AOROWS; ga.N = Fd; ga.Tper = 0;
        ga.C = nullptr; ga.bias = outb; ga.act = 0; ga.ldc = Fd;
        ga.So_h = p_ao2; ga.So_l = p_ao2 + AOP;
        tgemm<<<dim3(Fd/128, AOROWS/128), 256, TG_SMEM>>>(ga);
    }

    // c1 conv GEMM: bf16 split-2 x 3 products x 3 shifts, N=128
    {
        GArgs ga = {};
        const int pa[3] = {0,0,1}, pb[3] = {0,1,0};
        int q = 0;
        for (int sh = 0; sh < 3; ++sh)
            for (int pr = 0; pr < 3; ++pr) {
                ga.segs[q].A = p_ao2 + (size_t)pa[pr]*AOP;
                ga.segs[q].B = p_c1w2 + (size_t)pb[pr]*C1P + (size_t)sh*128*Fd;
                ga.segs[q].shift = sh - 1;
                ++q;
            }
        ga.nseg = 9; ga.M = AOROWS; ga.N = 128; ga.Tper = 74;
        ga.C = p_c1o; ga.bias = c1b; ga.act = 2; ga.ldc = 128;
        tgemm<<<dim3(1, AOROWS/128), 256, TG_SMEM>>>(ga);
    }

    tail_kernel<<<192, 256>>>(c2w, c2b, l1w, l1b, l2w, l2b, dout);
    vsort_kernel<<<Bn*NC, 512>>>(dout);
    vsoftmax_kernel<<<Bn, 32>>>(dout);
}

// round 14
// speedup vs baseline: 1.7298x; 1.7298x over previous
#include <cuda_runtime.h>
#include <cuda_bf16.h>
#include <cuda_fp16.h>
#include <math.h>
#include <float.h>
#include <stdint.h>

#define Bn 16
#define Tn 750
#define Fd 2048
#define NC 20
#define K6 6144
#define M_EMB 12000
#define SROWS 592
#define TOKROWS 5920
#define AOROWS 14208

#define OUT_VS   0
#define OUT_ACT  320
#define OUT_A2   12320
#define OUT_CAS  24320
#define OUT_RH   264320
#define OUT_EA   264512
#define OUT_EB   5179712
#define OUT_HA   10094912
#define OUT_HB   11307328

// ---------------- scratch (device globals) ----------------
__device__ float g_emb [(size_t)M_EMB * Fd];
__device__ float g_qkv [(size_t)TOKROWS * K6];
__device__ float g_c1o [(size_t)AOROWS * 128];
__device__ float g_sel [4 * Bn * Tn];
__device__ float g_med [Bn];
__device__ int   g_idx [5984];
__device__ float g_vmean[Bn * NC];

// fp16 split-2 planes for embed GEMM (hh product)
__device__ __half g_xh  [2 * (size_t)M_EMB * Fd];          // x: h, l(*2048)
__device__ __half g_wkh [2 * (size_t)3 * Fd * Fd];         // w_embed: [split][sh][o][e]
// bf16 copies for the residual products (hl, lh) — full bf16 mma rate
__device__ __nv_bfloat16 g_xb  [2 * (size_t)M_EMB * Fd];
__device__ __nv_bfloat16 g_wkb [2 * (size_t)3 * Fd * Fd];

// bf16 split-2 planes for trio GEMMs
__device__ __nv_bfloat16 g_tok2 [2 * (size_t)TOKROWS * Fd];
__device__ __nv_bfloat16 g_inw2 [2 * (size_t)K6 * Fd];
__device__ __nv_bfloat16 g_aop2 [2 * (size_t)AOROWS * Fd];
__device__ __nv_bfloat16 g_outw2[2 * (size_t)Fd * Fd];
__device__ __nv_bfloat16 g_ao2  [2 * (size_t)AOROWS * Fd];
__device__ __nv_bfloat16 g_c1w2 [2 * (size_t)3 * 128 * Fd];

__device__ __constant__ int d_aset[12] = {1,3,0,5,7,4,9,3,8,3,6,2};
__device__ __constant__ int d_bset[12] = {8,2,3,9,6,7,8,9,7,7,3,7};

// ================= MMA helpers (sm_80+ base features) =================
__device__ __forceinline__ uint32_t smem_to_u32(const void* p) {
    uint32_t a;
    asm("{ .reg .u64 t; cvta.to.shared.u64 t, %1; cvt.u32.u64 %0, t; }" : "=r"(a) : "l"(p));
    return a;
}
__device__ __forceinline__ void ldmatrix_x4(uint32_t* r, uint32_t addr) {
    asm volatile("ldmatrix.sync.aligned.m8n8.x4.shared.b16 {%0,%1,%2,%3}, [%4];"
        : "=r"(r[0]), "=r"(r[1]), "=r"(r[2]), "=r"(r[3]) : "r"(addr));
}
__device__ __forceinline__ void mma_bf16(float* d, const uint32_t* a, uint32_t b0, uint32_t b1) {
    asm volatile("mma.sync.aligned.m16n8k16.row.col.f32.bf16.bf16.f32 "
        "{%0,%1,%2,%3}, {%4,%5,%6,%7}, {%8,%9}, {%0,%1,%2,%3};"
        : "+f"(d[0]), "+f"(d[1]), "+f"(d[2]), "+f"(d[3])
        : "r"(a[0]), "r"(a[1]), "r"(a[2]), "r"(a[3]), "r"(b0), "r"(b1));
}
__device__ __forceinline__ void mma_bf16_z(float* d, const uint32_t* a, uint32_t b0, uint32_t b1) {
    asm volatile("mma.sync.aligned.m16n8k16.row.col.f32.bf16.bf16.f32 "
        "{%0,%1,%2,%3}, {%4,%5,%6,%7}, {%8,%9}, {%10,%11,%12,%13};"
        : "=f"(d[0]), "=f"(d[1]), "=f"(d[2]), "=f"(d[3])
        : "r"(a[0]), "r"(a[1]), "r"(a[2]), "r"(a[3]), "r"(b0), "r"(b1),
          "f"(0.f), "f"(0.f), "f"(0.f), "f"(0.f));
}
__device__ __forceinline__ void mma_f16(float* d, const uint32_t* a, uint32_t b0, uint32_t b1) {
    asm volatile("mma.sync.aligned.m16n8k16.row.col.f32.f16.f16.f32 "
        "{%0,%1,%2,%3}, {%4,%5,%6,%7}, {%8,%9}, {%0,%1,%2,%3};"
        : "+f"(d[0]), "+f"(d[1]), "+f"(d[2]), "+f"(d[3])
        : "r"(a[0]), "r"(a[1]), "r"(a[2]), "r"(a[3]), "r"(b0), "r"(b1));
}
__device__ __forceinline__ void mma_f16_z(float* d, const uint32_t* a, uint32_t b0, uint32_t b1) {
    asm volatile("mma.sync.aligned.m16n8k16.row.col.f32.f16.f16.f32 "
        "{%0,%1,%2,%3}, {%4,%5,%6,%7}, {%8,%9}, {%10,%11,%12,%13};"
        : "=f"(d[0]), "=f"(d[1]), "=f"(d[2]), "=f"(d[3])
        : "r"(a[0]), "r"(a[1]), "r"(a[2]), "r"(a[3]), "r"(b0), "r"(b1),
          "f"(0.f), "f"(0.f), "f"(0.f), "f"(0.f));
}
__device__ __forceinline__ void cp_async16(uint32_t dst, const void* src, int srcsize) {
    asm volatile("cp.async.ca.shared.global [%0], [%1], 16, %2;"
        :: "r"(dst), "l"(src), "r"(srcsize));
}

// ================= trio GEMM: bf16, undrained (R6/R9-proven) =================
struct Seg { const __nv_bfloat16* A; const __nv_bfloat16* B; int shift; };
struct GArgs {
    Seg segs[9];
    int nseg, M, N, Tper, act, ldc;
    float* C; const float* bias;
    __nv_bfloat16* So_h; __nv_bfloat16* So_l;
};

#define TG_SMEM 65536

__device__ __forceinline__ void tg_load(const GArgs& ga, uint32_t smb, int ci, int p,
                                        int bm, int bn, int tid) {
    const Seg s = ga.segs[ci >> 5];
    const int k0 = (ci & 31) * 64;
    const uint32_t abase = smb + p * 32768;
    const uint32_t bbase = abase + 16384;
#pragma unroll
    for (int g = 0; g < 4; ++g) {
        int id = tid + g * 256;
        int row = id >> 3, c = id & 7;
        uint32_t soff = row * 128 + ((c ^ (row & 7)) * 16);
        {
            int m = bm + row;
            const void* src = s.A;
            int sz = 0;
            if (m < ga.M) {
                int srow = m;
                bool ok = true;
                if (ga.Tper) {
                    int t = m % ga.Tper; int ts = t + s.shift;
                    ok = (ts >= 0 && ts < ga.Tper);
                    srow = m + s.shift;
                }
                if (ok) { src = s.A + (size_t)srow * 2048 + k0 + c * 8; sz = 16; }
            }
            cp_async16(abase + soff, src, sz);
        }
        {
            int n = bn + row;
            const void* src = s.B;
            int sz = 0;
            if (n < ga.N) { src = s.B + (size_t)n * 2048 + k0 + c * 8; sz = 16; }
            cp_async16(bbase + soff, src, sz);
        }
    }
    asm volatile("cp.async.commit_group;" ::: "memory");
}

__global__ void __launch_bounds__(256) tgemm(GArgs ga) {
    extern __shared__ char gsm[];
    const uint32_t smb = smem_to_u32(gsm);
    const int tid = threadIdx.x;
    const int wid = tid >> 5, lane = tid & 31;
    const int bm = blockIdx.y * 128;
    const int bn = blockIdx.x * 128;
    const int mw = (wid & 3) * 32;
    const int nw = (wid >> 2) * 64;
    const int nchunk = ga.nseg * 32;

    float acc[2][8][4];
#pragma unroll
    for (int i = 0; i < 2; ++i)
#pragma unroll
        for (int j = 0; j < 8; ++j)
#pragma unroll
            for (int q = 0; q < 4; ++q) acc[i][j][q] = 0.f;

    tg_load(ga, smb, 0, 0, bm, bn, tid);

    const int quad = lane >> 3, ri = lane & 7;

    for (int ci = 0; ci < nchunk; ++ci) {
        if (ci + 1 < nchunk) {
            tg_load(ga, smb, ci + 1, (ci + 1) & 1, bm, bn, tid);
            asm volatile("cp.async.wait_group 1;" ::: "memory");
        } else {
            asm volatile("cp.async.wait_group 0;" ::: "memory");
        }
        __syncthreads();

        const uint32_t abase = smb + (ci & 1) * 32768;
        const uint32_t bbase = abase + 16384;
#pragma unroll
        for (int ks = 0; ks < 4; ++ks) {
            const int kc = ks * 2;
            uint32_t afr[2][4];
#pragma unroll
            for (int mt = 0; mt < 2; ++mt) {
                int row = mw + mt * 16 + ri + (quad & 1) * 8;
                int ch = (kc + (quad >> 1)) ^ (row & 7);
                ldmatrix_x4(afr[mt], abase + row * 128 + ch * 16);
            }
#pragma unroll
            for (int np = 0; np < 4; ++np) {
                uint32_t bfr[4];
                int nrow = nw + np * 16 + ri + (quad >> 1) * 8;
                int ch = (kc + (quad & 1)) ^ (nrow & 7);
                ldmatrix_x4(bfr, bbase + nrow * 128 + ch * 16);
#pragma unroll
                for (int mt = 0; mt < 2; ++mt) {
                    mma_bf16(acc[mt][np * 2],     afr[mt], bfr[0], bfr[1]);
                    mma_bf16(acc[mt][np * 2 + 1], afr[mt], bfr[2], bfr[3]);
                }
            }
        }
        __syncthreads();
    }

#pragma unroll
    for (int mt = 0; mt < 2; ++mt) {
#pragma unroll
        for (int nt = 0; nt < 8; ++nt) {
            int col = bn + nw + nt * 8 + (lane & 3) * 2;
            if (col >= ga.N) continue;
#pragma unroll
            for (int h = 0; h < 2; ++h) {
                int row = bm + mw + mt * 16 + (lane >> 2) + h * 8;
                if (row >= ga.M) continue;
#pragma unroll
                for (int q = 0; q < 2; ++q) {
                    int c = col + q;
                    float v = acc[mt][nt][h * 2 + q];
                    if (ga.bias) v += ga.bias[c];
                    if (ga.act == 1) v = fmaxf(v, 0.f);
                    else if (ga.act == 2) v = (v >= 0.f) ? v : 0.2f * v;
                    size_t off = (size_t)row * ga.ldc + c;
                    if (ga.C) ga.C[off] = v;
                    if (ga.So_h) {
                        __nv_bfloat16 hh = __float2bfloat16(v);
                        ga.So_h[off] = hh;
                        ga.So_l[off] = __float2bfloat16(v - __bfloat162float(hh));
                    }
                }
            }
        }
    }
}

// ===== embed GEMM: mixed fp16/bf16 split-2, drained every 4 chunks =====
// hh product in fp16 (exact operands); hl/lh residuals in bf16 (full rate).
// Dtype branch hoisted to CHUNK level: two straight-line ks-loop bodies,
// each structurally identical to the R9-proven inner loop.
struct SegH { const __half* A; const __half* B; int shift; float scale; int bf; };
struct HArgs { SegH segs[9]; const float* bias; float* C; };

__device__ __forceinline__ void tg_load_h(const HArgs& ha, uint32_t smb, int ci, int p,
                                          int bm, int bn, int tid) {
    const SegH s = ha.segs[ci >> 5];
    const int k0 = (ci & 31) * 64;
    const uint32_t abase = smb + p * 32768;
    const uint32_t bbase = abase + 16384;
#pragma unroll
    for (int g = 0; g < 2; ++g) {
        int id = tid + g * 512;
        int row = id >> 3, c = id & 7;
        uint32_t soff = row * 128 + ((c ^ (row & 7)) * 16);
        {
            int m = bm + row;
            const void* src = s.A;
            int sz = 0;
            if (m < M_EMB) {
                int t = m % Tn;
                int ts = t + s.shift;
                if (ts >= 0 && ts < Tn) { src = s.A + (size_t)(m + s.shift) * 2048 + k0 + c * 8; sz = 16; }
            }
            cp_async16(abase + soff, src, sz);
        }
        {
            int n = bn + row;    // N = 2048, always in range
            cp_async16(bbase + soff, s.B + (size_t)n * 2048 + k0 + c * 8, 16);
        }
    }
    asm volatile("cp.async.commit_group;" ::: "memory");
}

__global__ void __launch_bounds__(512) tgemm_emb(HArgs ha) {
    extern __shared__ char gsm[];
    const uint32_t smb = smem_to_u32(gsm);
    const int tid = threadIdx.x;
    const int wid = tid >> 5, lane = tid & 31;
    const int bm = blockIdx.y * 128;
    const int bn = blockIdx.x * 128;
    const int mw = (wid & 3) * 32;
    const int nw = (wid >> 2) * 32;
    const int nchunk = 9 * 32;

    float sum[2][4][4];
    float acc[2][4][4];
#pragma unroll
    for (int i = 0; i < 2; ++i)
#pragma unroll
        for (int j = 0; j < 4; ++j)
#pragma unroll
            for (int q = 0; q < 4; ++q) sum[i][j][q] = 0.f;

    tg_load_h(ha, smb, 0, 0, bm, bn, tid);

    const int quad = lane >> 3, ri = lane & 7;

    for (int ci = 0; ci < nchunk; ++ci) {
        if (ci + 1 < nchunk) {
            tg_load_h(ha, smb, ci + 1, (ci + 1) & 1, bm, bn, tid);
            asm volatile("cp.async.wait_group 1;" ::: "memory");
        } else {
            asm volatile("cp.async.wait_group 0;" ::: "memory");
        }
        __syncthreads();

        const uint32_t abase = smb + (ci & 1) * 32768;
        const uint32_t bbase = abase + 16384;
        const bool fresh = ((ci & 3) == 0);

        if (ha.segs[ci >> 5].bf) {
            // ---- bf16 body (hl / lh residual products) ----
#pragma unroll
            for (int ks = 0; ks < 4; ++ks) {
                const int kc = ks * 2;
                uint32_t afr[2][4];
#pragma unroll
                for (int mt = 0; mt < 2; ++mt) {
                    int row = mw + mt * 16 + ri + (quad & 1) * 8;
                    int ch = (kc + (quad >> 1)) ^ (row & 7);
                    ldmatrix_x4(afr[mt], abase + row * 128 + ch * 16);
                }
#pragma unroll
                for (int bt = 0; bt < 2; ++bt) {
                    uint32_t bfr[4];
                    int nrow = nw + bt * 16 + ri + (quad >> 1) * 8;
                    int ch = (kc + (quad & 1)) ^ (nrow & 7);
                    ldmatrix_x4(bfr, bbase + nrow * 128 + ch * 16);
#pragma unroll
                    for (int mt = 0; mt < 2; ++mt) {
                        if (fresh && ks == 0) {
                            mma_bf16_z(acc[mt][bt * 2],     afr[mt], bfr[0], bfr[1]);
                            mma_bf16_z(acc[mt][bt * 2 + 1], afr[mt], bfr[2], bfr[3]);
                        } else {
                            mma_bf16(acc[mt][bt * 2],     afr[mt], bfr[0], bfr[1]);
                            mma_bf16(acc[mt][bt * 2 + 1], afr[mt], bfr[2], bfr[3]);
                        }
                    }
                }
            }
        } else {
            // ---- fp16 body (hh product) ----
#pragma unroll
            for (int ks = 0; ks < 4; ++ks) {
                const int kc = ks * 2;
                uint32_t afr[2][4];
#pragma unroll
                for (int mt = 0; mt < 2; ++mt) {
                    int row = mw + mt * 16 + ri + (quad & 1) * 8;
                    int ch = (kc + (quad >> 1)) ^ (row & 7);
                    ldmatrix_x4(afr[mt], abase + row * 128 + ch * 16);
                }
#pragma unroll
                for (int bt = 0; bt < 2; ++bt) {
                    uint32_t bfr[4];
                    int nrow = nw + bt * 16 + ri + (quad >> 1) * 8;
                    int ch = (kc + (quad & 1)) ^ (nrow & 7);
                    ldmatrix_x4(bfr, bbase + nrow * 128 + ch * 16);
#pragma unroll
                    for (int mt = 0; mt < 2; ++mt) {
                        if (fresh && ks == 0) {
                            mma_f16_z(acc[mt][bt * 2],     afr[mt], bfr[0], bfr[1]);
                            mma_f16_z(acc[mt][bt * 2 + 1], afr[mt], bfr[2], bfr[3]);
                        } else {
                            mma_f16(acc[mt][bt * 2],     afr[mt], bfr[0], bfr[1]);
                            mma_f16(acc[mt][bt * 2 + 1], afr[mt], bfr[2], bfr[3]);
                        }
                    }
                }
            }
        }
        // drain every 4 chunks (chain-16; R9-proven numerics)
        if ((ci & 3) == 3) {
            const float scl = ha.segs[ci >> 5].scale;
#pragma unroll
            for (int i = 0; i < 2; ++i)
#pragma unroll
                for (int j = 0; j < 4; ++j)
#pragma unroll
                    for (int q = 0; q < 4; ++q) sum[i][j][q] += acc[i][j][q] * scl;
        }
        __syncthreads();
    }

#pragma unroll
    for (int mt = 0; mt < 2; ++mt) {
#pragma unroll
        for (int nt = 0; nt < 4; ++nt) {
            int col = bn + nw + nt * 8 + (lane & 3) * 2;
#pragma unroll
            for (int h = 0; h < 2; ++h) {
                int row = bm + mw + mt * 16 + (lane >> 2) + h * 8;
                if (row >= M_EMB) continue;
#pragma unroll
                for (int q = 0; q < 2; ++q) {
                    int c = col + q;
                    float v = sum[mt][nt][h * 2 + q] + ha.bias[c];
                    ha.C[(size_t)row * Fd + c] = fmaxf(v, 0.f);
                }
            }
        }
    }
}

// ================= split kernels =================
#define RSCALE 2048.f
__global__ void split2h_x(const float* __restrict__ s, __half* h, __half* l,
                          __nv_bfloat16* bh, __nv_bfloat16* bl, long n) {
    for (long i = blockIdx.x * (long)blockDim.x + threadIdx.x; i < n;
         i += (long)gridDim.x * blockDim.x) {
        float x = s[i];
        __half a = __float2half(x);
        float xh = __half2float(a);
        float r = (x - xh) * RSCALE;
        __half lr = __float2half(r);
        h[i] = a; l[i] = lr;
        bh[i] = __float2bfloat16(xh);
        bl[i] = __float2bfloat16(__half2float(lr));
    }
}
__global__ void split2h_wk(const float* __restrict__ w, __half* h, __half* l,
                           __nv_bfloat16* bh, __nv_bfloat16* bl) {
    const long n = 3L * Fd * Fd;
    for (long i = blockIdx.x * (long)blockDim.x + threadIdx.x; i < n;
         i += (long)gridDim.x * blockDim.x) {
        long sh = i / ((long)Fd * Fd);
        long rem = i - sh * (long)Fd * Fd;
        float x = w[rem * 3 + sh];
        __half a = __float2half(x);
        float xh = __half2float(a);
        float r = (x - xh) * RSCALE;
        __half lr = __float2half(r);
        h[i] = a; l[i] = lr;
        bh[i] = __float2bfloat16(xh);
        bl[i] = __float2bfloat16(__half2float(lr));
    }
}
__global__ void split2_kernel(const float* __restrict__ s, __nv_bfloat16* h,
                              __nv_bfloat16* l, long n) {
    for (long i = blockIdx.x * (long)blockDim.x + threadIdx.x; i < n;
         i += (long)gridDim.x * blockDim.x) {
        float x = s[i];
        __nv_bfloat16 a = __float2bfloat16(x);
        h[i] = a; l[i] = __float2bfloat16(x - __bfloat162float(a));
    }
}
__global__ void split2_c1w_kernel(const float* __restrict__ w, __nv_bfloat16* h,
                                  __nv_bfloat16* l) {
    const long n = 3L * 128 * Fd;
    for (long i = blockIdx.x * (long)blockDim.x + threadIdx.x; i < n;
         i += (long)gridDim.x * blockDim.x) {
        long sh = i / (128L * Fd);
        long rem = i - sh * 128L * Fd;
        float x = w[rem * 3 + sh];
        __nv_bfloat16 a = __float2bfloat16(x);
        h[i] = a; l[i] = __float2bfloat16(x - __bfloat162float(a));
    }
}

// ================= CAS + actionness =================
__global__ void __launch_bounds__(320) cas_kernel(const float* __restrict__ wcls,
                                                  float* __restrict__ dout)
{
    __shared__ float embs[5 * Fd];
    __shared__ float cres[5 * NC];
    const int b  = blockIdx.x / 150;
    const int t0 = (blockIdx.x % 150) * 5;
    const float* src = g_emb + ((size_t)b * Tn + t0) * Fd;
    for (int i = threadIdx.x; i < 5 * Fd; i += 320) embs[i] = src[i];
    __syncthreads();

    const int w = threadIdx.x >> 5, lane = threadIdx.x & 31;
    const int tl = w >> 1, cg = (w & 1) * 10;
    for (int c = cg; c < cg + 10; ++c) {
        float acc = 0.f;
        const float* wr = wcls + (size_t)c * Fd;
        const float* er = embs + tl * Fd;
        for (int e = lane; e < Fd; e += 32) acc += er[e] * wr[e];
#pragma unroll
        for (int off = 16; off; off >>= 1) acc += __shfl_down_sync(0xffffffffu, acc, off);
        if (lane == 0) cres[tl * NC + c] = fmaxf(acc, 0.f);
    }
    __syncthreads();

    if (threadIdx.x < 100) {
        int tl2 = threadIdx.x / NC, c2 = threadIdx.x % NC;
        dout[OUT_CAS + ((size_t)(b * Tn + t0 + tl2)) * NC + c2] = cres[tl2 * NC + c2];
    }
    if (threadIdx.x < 5) {
        float s = 0.f;
        for (int c = 0; c < NC; ++c) s += cres[threadIdx.x * NC + c];
        dout[OUT_ACT + b * Tn + t0 + threadIdx.x] = s;
    }
}

// ================= a2 =================
__global__ void a2_kernel(const float* __restrict__ tf1w, const float* __restrict__ tf1b,
                          const float* __restrict__ tf2w, const float* __restrict__ tf2b,
                          float* __restrict__ dout)
{
    __shared__ float a[Tn], a1[Tn];
    const int b = blockIdx.x;
    for (int t = threadIdx.x; t < Tn; t += blockDim.x) a[t] = dout[OUT_ACT + b*Tn + t];
    __syncthreads();
    for (int t = threadIdx.x; t < Tn; t += blockDim.x) {
        float v = tf1b[0];
#pragma unroll
        for (int k = 0; k < 3; ++k) { int tt = t+k-1; if (tt>=0 && tt<Tn) v += tf1w[k]*a[tt]; }
        a1[t] = fmaxf(v, 0.f);
    }
    __syncthreads();
    for (int t = threadIdx.x; t < Tn; t += blockDim.x) {
        float v = tf2b[0];
#pragma unroll
        for (int k = 0; k < 3; ++k) { int tt = t+k-1; if (tt>=0 && tt<Tn) v += tf2w[k]*a1[tt]; }
        dout[OUT_A2 + b*Tn + t] = fmaxf(v, 0.f);
    }
}

// ================= sorting =================
__device__ __forceinline__ unsigned int fkey(float v) {
    unsigned int b = __float_as_uint(v);
    return (b & 0x80000000u) ? ~b : (b | 0x80000000u);
}
__device__ __forceinline__ float fdec(unsigned int u) {
    unsigned int b = (u & 0x80000000u) ? (u ^ 0x80000000u) : ~u;
    return __uint_as_float(b);
}
__device__ void bitonic1024_u64(unsigned long long* key, int tid) {
    for (int k = 2; k <= 1024; k <<= 1)
        for (int j = k >> 1; j > 0; j >>= 1) {
            __syncthreads();
            for (int i = tid; i < 1024; i += 512) {
                int ixj = i ^ j;
                if (ixj > i) {
                    bool up = ((i & k) == 0);
                    unsigned long long a = key[i], b2 = key[ixj];
                    bool sw = up ? (a > b2) : (a < b2);
                    if (sw) { key[i] = b2; key[ixj] = a; }
                }
            }
        }
    __syncthreads();
}
__device__ void bitonic1024_u32(unsigned int* key, int tid) {
    for (int k = 2; k <= 1024; k <<= 1)
        for (int j = k >> 1; j > 0; j >>= 1) {
            __syncthreads();
            for (int i = tid; i < 1024; i += 512) {
                int ixj = i ^ j;
                if (ixj > i) {
                    bool up = ((i & k) == 0);
                    unsigned int a = key[i], b2 = key[ixj];
                    bool sw = up ? (a > b2) : (a < b2);
                    if (sw) { key[i] = b2; key[ixj] = a; }
                }
            }
        }
    __syncthreads();
}

__global__ void __launch_bounds__(512) sort_act_kernel(const float* __restrict__ dout) {
    __shared__ unsigned long long key[1024];
    const int b = blockIdx.x, tid = threadIdx.x;
    for (int i = tid; i < 1024; i += 512) {
        if (i < Tn) {
            unsigned int nu = ~fkey(dout[OUT_ACT + b*Tn + i]);
            key[i] = ((unsigned long long)nu << 32) | (unsigned int)i;
        } else key[i] = 0xFFFFFFFFFFFFFFFFull;
    }
    bitonic1024_u64(key, tid);
    for (int i = tid; i < 150; i += 512) g_idx[b*150 + i] = (int)(key[i] & 0xffffffffu);
    if (tid == 0) {
        float v0 = fdec(~(unsigned int)(key[374] >> 32));
        float v1 = fdec(~(unsigned int)(key[375] >> 32));
        g_med[b] = 0.5f * (v0 + v1);
    }
}

__global__ void morph_kernel(const float* __restrict__ dout) {
    __shared__ float a[Tn];
    __shared__ float bin[Tn];
    __shared__ float red[256];
    const int b = blockIdx.x, tid = threadIdx.x;
    float lmax = -FLT_MAX;
    for (int t = tid; t < Tn; t += 256) { float v = dout[OUT_ACT + b*Tn + t]; a[t] = v; lmax = fmaxf(lmax, v); }
    red[tid] = lmax; __syncthreads();
    for (int s = 128; s > 0; s >>= 1) { if (tid < s) red[tid] = fmaxf(red[tid], red[tid+s]); __syncthreads(); }
    float amax = red[0];
    float med = g_med[b];
    for (int t = tid; t < Tn; t += 256) bin[t] = (a[t] > med) ? 1.f : 0.f;
    __syncthreads();
    for (int t = tid; t < Tn; t += 256) {
        float e3 = 1.f, e6 = 1.f, d6 = 0.f, d3 = 0.f;
#pragma unroll
        for (int o = -1; o <= 1; ++o) { int u = t+o; float v = (u>=0&&u<Tn)?bin[u]:0.f; e3 = fminf(e3,v); d3 = fmaxf(d3,v); }
#pragma unroll
        for (int o = -3; o <= 2; ++o) { int u = t+o; float v = (u>=0&&u<Tn)?bin[u]:0.f; e6 = fminf(e6,v); }
#pragma unroll
        for (int o = -2; o <= 3; ++o) { int u = t+o; float v = (u>=0&&u<Tn)?bin[u]:0.f; d6 = fmaxf(d6,v); }
        g_sel[1*Bn*Tn + b*Tn + t] = amax - a[t];
        g_sel[2*Bn*Tn + b*Tn + t] = a[t] * (e3 - e6);
        g_sel[3*Bn*Tn + b*Tn + t] = a[t] * (d6 - d3);
    }
}

__global__ void __launch_bounds__(512) sort_gen_kernel() {
    __shared__ unsigned long long key[1024];
    const int aid = blockIdx.x / 16 + 1;
    const int b = blockIdx.x % 16;
    const int tid = threadIdx.x;
    const float* sc = g_sel + aid*Bn*Tn + b*Tn;
    const unsigned int msk = (aid == 1) ? 0xFFFFFFF8u : 0xFFFFFFFFu;
    for (int i = tid; i < 1024; i += 512) {
        if (i < Tn) {
            unsigned int nu = ~(fkey(sc[i]) & msk);
            key[i] = ((unsigned long long)nu << 32) | (unsigned int)i;
        } else key[i] = 0xFFFFFFFFFFFFFFFFull;
    }
    bitonic1024_u64(key, tid);
    if (aid == 1) { for (int i = tid; i < 150; i += 512) g_idx[2400 + b*150 + i] = (int)(key[i] & 0xffffffffu); }
    else if (aid == 2) { if (tid < 37) g_idx[4800 + b*37 + tid] = (int)(key[tid] & 0xffffffffu); }
    else { if (tid < 37) g_idx[5392 + b*37 + tid] = (int)(key[tid] & 0xffffffffu); }
}

__global__ void __launch_bounds__(256) gather_kernel(float* __restrict__ dout) {
    const int r = blockIdx.x; // 0..5983
    int b, j, srcidx, set = -1;
    float* dst;
    if (r < 2400) {
        b = r/150; j = r%150; srcidx = g_idx[b*150 + j];
        dst = dout + OUT_EA + (size_t)r * Fd;
        if (j < 148) set = j / 37;
    } else if (r < 4800) {
        int rr = r - 2400; b = rr/150; j = rr%150; srcidx = g_idx[2400 + b*150 + j];
        dst = dout + OUT_EB + (size_t)rr * Fd;
        if (j < 148) set = 4 + j / 37;
    } else if (r < 5392) {
        int rr = r - 4800; b = rr/37; j = rr%37; srcidx = g_idx[4800 + rr];
        dst = dout + OUT_HA + (size_t)rr * Fd; set = 8;
    } else {
        int rr = r - 5392; b = rr/37; j = rr%37; srcidx = g_idx[5392 + rr];
        dst = dout + OUT_HB + (size_t)rr * Fd; set = 9;
    }
    const float4* src = reinterpret_cast<const float4*>(g_emb + ((size_t)b*Tn + srcidx)*Fd);
    float4* d4 = reinterpret_cast<float4*>(dst);
    __nv_bfloat16* th = nullptr; __nv_bfloat16* tl = nullptr;
    if (set >= 0) {
        size_t tb = ((size_t)set*SROWS + b*37 + (j % 37))*Fd;
        th = g_tok2 + tb;
        tl = g_tok2 + (size_t)TOKROWS*Fd + tb;
    }
    for (int i = threadIdx.x; i < Fd/4; i += 256) {
        float4 v = src[i];
        d4[i] = v;
        if (th) {
            float vv[4] = {v.x, v.y, v.z, v.w};
#pragma unroll
            for (int q = 0; q < 4; ++q) {
                __nv_bfloat16 h = __float2bfloat16(vv[q]);
                th[i*4 + q] = h;
                tl[i*4 + q] = __float2bfloat16(vv[q] - __bfloat162float(h));
            }
        }
    }
}

// ================= attention (writes aopre split-2 planes) =================
__global__ void __launch_bounds__(256) attn_kernel() {
    __shared__ float qt[37*64];
    __shared__ float kt[37*64];
    __shared__ float s[37*37];
    const int id = blockIdx.x;
    const int h = id & 3, b = (id >> 2) & 15, m = id >> 6;
    const int rh = m >> 1, role = m & 1;
    const int as = d_aset[rh], bs = d_bset[rh];
    const int qset = role ? as : bs;
    const int kvset = role ? bs : as;
    const int trowbase = role ? 37 : 0;
    const int tid = threadIdx.x;
    const float scale = 0.044194173824159216f; // 1/sqrt(512)

    const float* Qb = g_qkv + ((size_t)(qset*SROWS + b*37)) * K6 + h*512;
    const float* Kb = g_qkv + ((size_t)(kvset*SROWS + b*37)) * K6 + 2048 + h*512;
    const float* Vb = g_qkv + ((size_t)(kvset*SROWS + b*37)) * K6 + 4096 + h*512;

    for (int i = tid; i < 1369; i += 256) s[i] = 0.f;
    for (int dt = 0; dt < 8; ++dt) {
        __syncthreads();
        for (int i = tid; i < 2368; i += 256) {
            int q = i >> 6, d = i & 63;
            qt[i] = Qb[(size_t)q*K6 + dt*64 + d];
            kt[i] = Kb[(size_t)q*K6 + dt*64 + d];
        }
        __syncthreads();
        for (int p = tid; p < 1369; p += 256) {
            int q = p / 37, k = p % 37;
            const float* qr = qt + q*64;
            const float* kr = kt + k*64;
            float acc = 0.f;
#pragma unroll
            for (int d = 0; d < 64; ++d) acc += qr[d] * kr[d];
            s[p] += acc;
        }
    }
    __syncthreads();
    {
        const int w = tid >> 5, lane = tid & 31;
        for (int r = w; r < 37; r += 8) {
            float sv0 = s[r*37 + lane] * scale;
            float sv1 = (lane < 5) ? s[r*37 + 32 + lane] * scale : -FLT_MAX;
            float mx = fmaxf(sv0, sv1);
#pragma unroll
            for (int off = 16; off; off >>= 1) mx = fmaxf(mx, __shfl_xor_sync(0xffffffffu, mx, off));
            float e0 = expf(sv0 - mx);
            float e1 = (lane < 5) ? expf(sv1 - mx) : 0.f;
            float sum = e0 + e1;
#pragma unroll
            for (int off = 16; off; off >>= 1) sum += __shfl_xor_sync(0xffffffffu, sum, off);
            float inv = 1.f / sum;
            s[r*37 + lane] = e0 * inv;
            if (lane < 5) s[r*37 + 32 + lane] = e1 * inv;
        }
    }
    const size_t rowbase = (size_t)(rh*1184 + b*74 + trowbase);
    for (int dt = 0; dt < 8; ++dt) {
        __syncthreads();
        for (int i = tid; i < 2368; i += 256) {
            int k = i >> 6, d = i & 63;
            kt[i] = Vb[(size_t)k*K6 + dt*64 + d];
        }
        __syncthreads();
        for (int p = tid; p < 2368; p += 256) {
            int q = p >> 6, d = p & 63;
            const float* sr = s + q*37;
            float acc = 0.f;
#pragma unroll
            for (int k = 0; k < 37; ++k) acc += sr[k] * kt[k*64 + d];
            size_t off = (rowbase + q)*Fd + h*512 + dt*64 + d;
            __nv_bfloat16 hh = __float2bfloat16(acc);
            g_aop2[off] = hh;
            g_aop2[(size_t)AOROWS*Fd + off] = __float2bfloat16(acc - __bfloat162float(hh));
        }
    }
}

// ================= c2 + l1 + l2 fused =================
__global__ void __launch_bounds__(256) tail_kernel(
    const float* __restrict__ c2w, const float* __restrict__ c2b,
    const float* __restrict__ l1w, const float* __restrict__ l1b,
    const float* __restrict__ l2w, const float* __restrict__ l2b,
    float* __restrict__ dout)
{
    __shared__ float sm[74*128];
    const int rb = blockIdx.x;
    const int tid = threadIdx.x;
    for (int i = tid; i < 74*128; i += 256)
        sm[i] = g_c1o[(size_t)rb*74*128 + i];
    __syncthreads();

    const int o = tid & 31;
    const int tbase = tid >> 5;
    float r[10];
    int nt = 0;
    for (int t = tbase; t < 74; t += 8) {
        float v = c2b[o];
#pragma unroll
        for (int k = 0; k < 3; ++k) {
            int tt = t + k - 1;
            if (tt >= 0 && tt < 74) {
                const float* row = sm + tt*128;
                const float* w = c2w + o*384 + k;
#pragma unroll 16
                for (int c = 0; c < 128; ++c) v += row[c] * w[c*3];
            }
        }
        r[nt++] = (v >= 0.f) ? v : 0.2f * v;
    }
    __syncthreads();
    { int i = 0; for (int t = tbase; t < 74; t += 8) sm[o*74 + t] = r[i++]; }
    __syncthreads();

    for (int p = tid; p < 320; p += 256) {
        int c = p / 10, j = p % 10;
        float v = l1b[j];
        const float* y = sm + c*74;
        const float* w = l1w + j*74;
        for (int t = 0; t < 74; ++t) v += y[t] * w[t];
        sm[2368 + p] = (v >= 0.f) ? v : 0.2f * v;
    }
    __syncthreads();
    float ps = 0.f;
    for (int p = tid; p < 320; p += 256) ps += sm[2368 + p] * l2w[p];
    sm[3000 + tid] = ps;
    __syncthreads();
    for (int s = 128; s > 0; s >>= 1) { if (tid < s) sm[3000+tid] += sm[3000+tid+s]; __syncthreads(); }
    if (tid == 0) {
        float x = sm[3000] + l2b[0];
        dout[OUT_RH + rb] = 1.f / (1.f + expf(-x));
    }
}

// ================= video scores =================
__global__ void __launch_bounds__(512) vsort_kernel(const float* __restrict__ dout) {
    __shared__ unsigned int key[1024];
    const int bc = blockIdx.x;
    const int b = bc / NC, c = bc % NC;
    const int tid = threadIdx.x;
    for (int i = tid; i < 1024; i += 512)
        key[i] = (i < Tn) ? ~fkey(dout[OUT_CAS + (size_t)(b*Tn + i)*NC + c]) : 0xFFFFFFFFu;
    bitonic1024_u32(key, tid);
    if (tid == 0) {
        float s = 0.f;
        for (int i = 0; i < 150; ++i) s += fdec(~key[i]);
        g_vmean[bc] = s / 150.f;
    }
}
__global__ void vsoftmax_kernel(float* __restrict__ dout) {
    const int b = blockIdx.x, t = threadIdx.x;
    float v = (t < NC) ? g_vmean[b*NC + t] : -FLT_MAX;
    float mx = v;
#pragma unroll
    for (int off = 16; off; off >>= 1) mx = fmaxf(mx, __shfl_xor_sync(0xffffffffu, mx, off));
    float e = (t < NC) ? expf(v - mx) : 0.f;
    float sum = e;
#pragma unroll
    for (int off = 16; off; off >>= 1) sum += __shfl_xor_sync(0xffffffffu, sum, off);
    if (t < NC) dout[OUT_VS + b*NC + t] = e / sum;
}

// ================= launch =================
extern "C" void kernel_launch(void* const* d_in, const int* in_sizes, int n_in,
                              void* d_out, int out_size) {
    const float* x    = (const float*)d_in[0];
    const float* wemb = (const float*)d_in[1];
    const float* bemb = (const float*)d_in[2];
    const float* wcls = (const float*)d_in[3];
    const float* tf1w = (const float*)d_in[4];
    const float* tf1b = (const float*)d_in[5];
    const float* tf2w = (const float*)d_in[6];
    const float* tf2b = (const float*)d_in[7];
    const float* inw  = (const float*)d_in[8];
    const float* inb  = (const float*)d_in[9];
    const float* outw = (const float*)d_in[10];
    const float* outb = (const float*)d_in[11];
    const float* c1w  = (const float*)d_in[12];
    const float* c1b  = (const float*)d_in[13];
    const float* c2w  = (const float*)d_in[14];
    const float* c2b  = (const float*)d_in[15];
    const float* l1w  = (const float*)d_in[16];
    const float* l1b  = (const float*)d_in[17];
    const float* l2w  = (const float*)d_in[18];
    const float* l2b  = (const float*)d_in[19];
    float* dout = (float*)d_out;

    float *p_emb, *p_qkv, *p_c1o;
    __half *p_xh, *p_wkh;
    __nv_bfloat16 *p_xb, *p_wkb;
    __nv_bfloat16 *p_tok2, *p_inw2, *p_aop2, *p_outw2, *p_ao2, *p_c1w2;
    cudaGetSymbolAddress((void**)&p_emb,  g_emb);
    cudaGetSymbolAddress((void**)&p_qkv,  g_qkv);
    cudaGetSymbolAddress((void**)&p_c1o,  g_c1o);
    cudaGetSymbolAddress((void**)&p_xh,   g_xh);
    cudaGetSymbolAddress((void**)&p_wkh,  g_wkh);
    cudaGetSymbolAddress((void**)&p_xb,   g_xb);
    cudaGetSymbolAddress((void**)&p_wkb,  g_wkb);
    cudaGetSymbolAddress((void**)&p_tok2, g_tok2);
    cudaGetSymbolAddress((void**)&p_inw2, g_inw2);
    cudaGetSymbolAddress((void**)&p_aop2, g_aop2);
    cudaGetSymbolAddress((void**)&p_outw2,g_outw2);
    cudaGetSymbolAddress((void**)&p_c1w2, g_c1w2);
    cudaGetSymbolAddress((void**)&p_ao2,  g_ao2);

    cudaFuncSetAttribute(tgemm, cudaFuncAttributeMaxDynamicSharedMemorySize, TG_SMEM);
    cudaFuncSetAttribute(tgemm_emb, cudaFuncAttributeMaxDynamicSharedMemorySize, TG_SMEM);

    const size_t XP   = (size_t)M_EMB * Fd;
    const size_t WKP  = (size_t)3 * Fd * Fd;
    const size_t TOKP = (size_t)TOKROWS * Fd;
    const size_t INWP = (size_t)K6 * Fd;
    const size_t AOP  = (size_t)AOROWS * Fd;
    const size_t OWP  = (size_t)Fd * Fd;
    const size_t C1P  = (size_t)3 * 128 * Fd;

    // splits (fp16 planes + bf16 copies for residual products)
    split2h_x<<<2048, 256>>>(x, p_xh, p_xh + XP, p_xb, p_xb + XP, (long)XP);
    split2h_wk<<<2048, 256>>>(wemb, p_wkh, p_wkh + WKP, p_wkb, p_wkb + WKP);
    split2_kernel<<<2048, 256>>>(inw, p_inw2, p_inw2 + INWP, (long)INWP);
    split2_kernel<<<1024, 256>>>(outw, p_outw2, p_outw2 + OWP, (long)OWP);
    split2_c1w_kernel<<<256, 256>>>(c1w, p_c1w2, p_c1w2 + C1P);

    // embed conv GEMM: mixed precision — hh fp16, hl/lh bf16 (chunk-level dispatch)
    {
        HArgs ha = {};
        const float S = 1.f / RSCALE;
        int q = 0;
        // hh (fp16)
        for (int sh = 0; sh < 3; ++sh) {
            ha.segs[q].A = p_xh;
            ha.segs[q].B = p_wkh + (size_t)sh * Fd * Fd;
            ha.segs[q].shift = sh - 1; ha.segs[q].scale = 1.f; ha.segs[q].bf = 0; ++q;
        }
        // hl (bf16): bf16(x_h) * bf16(w_l*2048)
        for (int sh = 0; sh < 3; ++sh) {
            ha.segs[q].A = (const __half*)p_xb;
            ha.segs[q].B = (const __half*)(p_wkb + WKP + (size_t)sh * Fd * Fd);
            ha.segs[q].shift = sh - 1; ha.segs[q].scale = S; ha.segs[q].bf = 1; ++q;
        }
        // lh (bf16): bf16(x_l*2048) * bf16(w_h)
        for (int sh = 0; sh < 3; ++sh) {
            ha.segs[q].A = (const __half*)(p_xb + XP);
            ha.segs[q].B = (const __half*)(p_wkb + (size_t)sh * Fd * Fd);
            ha.segs[q].shift = sh - 1; ha.segs[q].scale = S; ha.segs[q].bf = 1; ++q;
        }
        ha.bias = bemb; ha.C = p_emb;
        tgemm_emb<<<dim3(Fd/128, (M_EMB + 127)/128), 512, TG_SMEM>>>(ha);
    }

    cas_kernel<<<Bn*150, 320>>>(wcls, dout);
    a2_kernel<<<Bn, 256>>>(tf1w, tf1b, tf2w, tf2b, dout);
    sort_act_kernel<<<Bn, 512>>>(dout);
    morph_kernel<<<Bn, 256>>>(dout);
    sort_gen_kernel<<<48, 512>>>();
    gather_kernel<<<5984, 256>>>(dout);

    // QKV GEMM: bf16 split-2 x 3 products (undrained, proven fast)
    {
        GArgs ga = {};
        const int pa[3] = {0,0,1}, pb[3] = {0,1,0};
        for (int pr = 0; pr < 3; ++pr) {
            ga.segs[pr].A = p_tok2 + (size_t)pa[pr]*TOKP;
            ga.segs[pr].B = p_inw2 + (size_t)pb[pr]*INWP;
            ga.segs[pr].shift = 0;
        }
        ga.nseg = 3; ga.M = TOKROWS; ga.N = K6; ga.Tper = 0;
        ga.C = p_qkv; ga.bias = inb; ga.act = 0; ga.ldc = K6;
        tgemm<<<dim3(K6/128, (TOKROWS+127)/128), 256, TG_SMEM>>>(ga);
    }

    attn_kernel<<<1536, 256>>>();

    // out-proj GEMM: bf16 split-2, epilogue writes split-2 planes
    {
        GArgs ga = {};
        const int pa[3] = {0,0,1}, pb[3] = {0,1,0};
        for (int pr = 0; pr < 3; ++pr) {
            ga.segs[pr].A = p_aop2 + (size_t)pa[pr]*AOP;
            ga.segs[pr].B = p_outw2 + (size_t)pb[pr]*OWP;
            ga.segs[pr].shift = 0;
        }
        ga.nseg = 3; ga.M = AOROWS; ga.N = Fd; ga.Tper = 0;
        ga.C = nullptr; ga.bias = outb; ga.act = 0; ga.ldc = Fd;
        ga.So_h = p_ao2; ga.So_l = p_ao2 + AOP;
        tgemm<<<dim3(Fd/128, AOROWS/128), 256, TG_SMEM>>>(ga);
    }

    // c1 conv GEMM: bf16 split-2 x 3 products x 3 shifts, N=128
    {
        GArgs ga = {};
        const int pa[3] = {0,0,1}, pb[3] = {0,1,0};
        int q = 0;
        for (int sh = 0; sh < 3; ++sh)
            for (int pr = 0; pr < 3; ++pr) {
                ga.segs[q].A = p_ao2 + (size_t)pa[pr]*AOP;
                ga.segs[q].B = p_c1w2 + (size_t)pb[pr]*C1P + (size_t)sh*128*Fd;
                ga.segs[q].shift = sh - 1;
                ++q;
            }
        ga.nseg = 9; ga.M = AOROWS; ga.N = 128; ga.Tper = 74;
        ga.C = p_c1o; ga.bias = c1b; ga.act = 2; ga.ldc = 128;
        tgemm<<<dim3(1, AOROWS/128), 256, TG_SMEM>>>(ga);
    }

    tail_kernel<<<192, 256>>>(c2w, c2b, l1w, l1b, l2w, l2b, dout);
    vsort_kernel<<<Bn*NC, 512>>>(dout);
    vsoftmax_kernel<<<Bn, 32>>>(dout);
}

// round 15
// speedup vs baseline: 1.8034x; 1.0425x over previous
#include <cuda_runtime.h>
#include <cuda_bf16.h>
#include <cuda_fp16.h>
#include <math.h>
#include <float.h>
#include <stdint.h>

#define Bn 16
#define Tn 750
#define Fd 2048
#define NC 20
#define K6 6144
#define M_EMB 12000
#define SROWS 592
#define TOKROWS 5920
#define AOROWS 14208

#define OUT_VS   0
#define OUT_ACT  320
#define OUT_A2   12320
#define OUT_CAS  24320
#define OUT_RH   264320
#define OUT_EA   264512
#define OUT_EB   5179712
#define OUT_HA   10094912
#define OUT_HB   11307328

// ---------------- scratch (device globals) ----------------
__device__ float g_emb [(size_t)M_EMB * Fd];
__device__ float g_qkv [(size_t)TOKROWS * K6];
__device__ float g_c1o [(size_t)AOROWS * 128];
__device__ float g_sel [4 * Bn * Tn];
__device__ float g_med [Bn];
__device__ int   g_idx [5984];
__device__ float g_vmean[Bn * NC];

// fp16 split-2 planes for embed GEMM
__device__ __half g_xh  [2 * (size_t)M_EMB * Fd];          // x: h, l(*2048)
__device__ __half g_wkh [2 * (size_t)3 * Fd * Fd];         // w_embed: [split][sh][o][e]

// bf16 split-2 planes for trio GEMMs
__device__ __nv_bfloat16 g_tok2 [2 * (size_t)TOKROWS * Fd];
__device__ __nv_bfloat16 g_inw2 [2 * (size_t)K6 * Fd];
__device__ __nv_bfloat16 g_aop2 [2 * (size_t)AOROWS * Fd];
__device__ __nv_bfloat16 g_outw2[2 * (size_t)Fd * Fd];
__device__ __nv_bfloat16 g_ao2  [2 * (size_t)AOROWS * Fd];
__device__ __nv_bfloat16 g_c1w2 [2 * (size_t)3 * 128 * Fd];

__device__ __constant__ int d_aset[12] = {1,3,0,5,7,4,9,3,8,3,6,2};
__device__ __constant__ int d_bset[12] = {8,2,3,9,6,7,8,9,7,7,3,7};

// ================= MMA helpers (sm_80+ base features) =================
__device__ __forceinline__ uint32_t smem_to_u32(const void* p) {
    uint32_t a;
    asm("{ .reg .u64 t; cvta.to.shared.u64 t, %1; cvt.u32.u64 %0, t; }" : "=r"(a) : "l"(p));
    return a;
}
__device__ __forceinline__ void ldmatrix_x4(uint32_t* r, uint32_t addr) {
    asm volatile("ldmatrix.sync.aligned.m8n8.x4.shared.b16 {%0,%1,%2,%3}, [%4];"
        : "=r"(r[0]), "=r"(r[1]), "=r"(r[2]), "=r"(r[3]) : "r"(addr));
}
__device__ __forceinline__ void mma_bf16(float* d, const uint32_t* a, uint32_t b0, uint32_t b1) {
    asm volatile("mma.sync.aligned.m16n8k16.row.col.f32.bf16.bf16.f32 "
        "{%0,%1,%2,%3}, {%4,%5,%6,%7}, {%8,%9}, {%0,%1,%2,%3};"
        : "+f"(d[0]), "+f"(d[1]), "+f"(d[2]), "+f"(d[3])
        : "r"(a[0]), "r"(a[1]), "r"(a[2]), "r"(a[3]), "r"(b0), "r"(b1));
}
__device__ __forceinline__ void mma_f16(float* d, const uint32_t* a, uint32_t b0, uint32_t b1) {
    asm volatile("mma.sync.aligned.m16n8k16.row.col.f32.f16.f16.f32 "
        "{%0,%1,%2,%3}, {%4,%5,%6,%7}, {%8,%9}, {%0,%1,%2,%3};"
        : "+f"(d[0]), "+f"(d[1]), "+f"(d[2]), "+f"(d[3])
        : "r"(a[0]), "r"(a[1]), "r"(a[2]), "r"(a[3]), "r"(b0), "r"(b1));
}
__device__ __forceinline__ void mma_f16_z(float* d, const uint32_t* a, uint32_t b0, uint32_t b1) {
    asm volatile("mma.sync.aligned.m16n8k16.row.col.f32.f16.f16.f32 "
        "{%0,%1,%2,%3}, {%4,%5,%6,%7}, {%8,%9}, {%10,%11,%12,%13};"
        : "=f"(d[0]), "=f"(d[1]), "=f"(d[2]), "=f"(d[3])
        : "r"(a[0]), "r"(a[1]), "r"(a[2]), "r"(a[3]), "r"(b0), "r"(b1),
          "f"(0.f), "f"(0.f), "f"(0.f), "f"(0.f));
}
__device__ __forceinline__ void cp_async16(uint32_t dst, const void* src, int srcsize) {
    asm volatile("cp.async.ca.shared.global [%0], [%1], 16, %2;"
        :: "r"(dst), "l"(src), "r"(srcsize));
}

// ================= trio GEMM: bf16, undrained (R6/R9-proven) =================
struct Seg { const __nv_bfloat16* A; const __nv_bfloat16* B; int shift; };
struct GArgs {
    Seg segs[9];
    int nseg, M, N, Tper, act, ldc;
    float* C; const float* bias;
    __nv_bfloat16* So_h; __nv_bfloat16* So_l;
};

#define TG_SMEM 65536

__device__ __forceinline__ void tg_load(const GArgs& ga, uint32_t smb, int ci, int p,
                                        int bm, int bn, int tid) {
    const Seg s = ga.segs[ci >> 5];
    const int k0 = (ci & 31) * 64;
    const uint32_t abase = smb + p * 32768;
    const uint32_t bbase = abase + 16384;
#pragma unroll
    for (int g = 0; g < 4; ++g) {
        int id = tid + g * 256;
        int row = id >> 3, c = id & 7;
        uint32_t soff = row * 128 + ((c ^ (row & 7)) * 16);
        {
            int m = bm + row;
            const void* src = s.A;
            int sz = 0;
            if (m < ga.M) {
                int srow = m;
                bool ok = true;
                if (ga.Tper) {
                    int t = m % ga.Tper; int ts = t + s.shift;
                    ok = (ts >= 0 && ts < ga.Tper);
                    srow = m + s.shift;
                }
                if (ok) { src = s.A + (size_t)srow * 2048 + k0 + c * 8; sz = 16; }
            }
            cp_async16(abase + soff, src, sz);
        }
        {
            int n = bn + row;
            const void* src = s.B;
            int sz = 0;
            if (n < ga.N) { src = s.B + (size_t)n * 2048 + k0 + c * 8; sz = 16; }
            cp_async16(bbase + soff, src, sz);
        }
    }
    asm volatile("cp.async.commit_group;" ::: "memory");
}

__global__ void __launch_bounds__(256) tgemm(GArgs ga) {
    extern __shared__ char gsm[];
    const uint32_t smb = smem_to_u32(gsm);
    const int tid = threadIdx.x;
    const int wid = tid >> 5, lane = tid & 31;
    const int bm = blockIdx.y * 128;
    const int bn = blockIdx.x * 128;
    const int mw = (wid & 3) * 32;
    const int nw = (wid >> 2) * 64;
    const int nchunk = ga.nseg * 32;

    float acc[2][8][4];
#pragma unroll
    for (int i = 0; i < 2; ++i)
#pragma unroll
        for (int j = 0; j < 8; ++j)
#pragma unroll
            for (int q = 0; q < 4; ++q) acc[i][j][q] = 0.f;

    tg_load(ga, smb, 0, 0, bm, bn, tid);

    const int quad = lane >> 3, ri = lane & 7;

    for (int ci = 0; ci < nchunk; ++ci) {
        if (ci + 1 < nchunk) {
            tg_load(ga, smb, ci + 1, (ci + 1) & 1, bm, bn, tid);
            asm volatile("cp.async.wait_group 1;" ::: "memory");
        } else {
            asm volatile("cp.async.wait_group 0;" ::: "memory");
        }
        __syncthreads();

        const uint32_t abase = smb + (ci & 1) * 32768;
        const uint32_t bbase = abase + 16384;
#pragma unroll
        for (int ks = 0; ks < 4; ++ks) {
            const int kc = ks * 2;
            uint32_t afr[2][4];
#pragma unroll
            for (int mt = 0; mt < 2; ++mt) {
                int row = mw + mt * 16 + ri + (quad & 1) * 8;
                int ch = (kc + (quad >> 1)) ^ (row & 7);
                ldmatrix_x4(afr[mt], abase + row * 128 + ch * 16);
            }
#pragma unroll
            for (int np = 0; np < 4; ++np) {
                uint32_t bfr[4];
                int nrow = nw + np * 16 + ri + (quad >> 1) * 8;
                int ch = (kc + (quad & 1)) ^ (nrow & 7);
                ldmatrix_x4(bfr, bbase + nrow * 128 + ch * 16);
#pragma unroll
                for (int mt = 0; mt < 2; ++mt) {
                    mma_bf16(acc[mt][np * 2],     afr[mt], bfr[0], bfr[1]);
                    mma_bf16(acc[mt][np * 2 + 1], afr[mt], bfr[2], bfr[3]);
                }
            }
        }
        __syncthreads();
    }

#pragma unroll
    for (int mt = 0; mt < 2; ++mt) {
#pragma unroll
        for (int nt = 0; nt < 8; ++nt) {
            int col = bn + nw + nt * 8 + (lane & 3) * 2;
            if (col >= ga.N) continue;
#pragma unroll
            for (int h = 0; h < 2; ++h) {
                int row = bm + mw + mt * 16 + (lane >> 2) + h * 8;
                if (row >= ga.M) continue;
#pragma unroll
                for (int q = 0; q < 2; ++q) {
                    int c = col + q;
                    float v = acc[mt][nt][h * 2 + q];
                    if (ga.bias) v += ga.bias[c];
                    if (ga.act == 1) v = fmaxf(v, 0.f);
                    else if (ga.act == 2) v = (v >= 0.f) ? v : 0.2f * v;
                    size_t off = (size_t)row * ga.ldc + c;
                    if (ga.C) ga.C[off] = v;
                    if (ga.So_h) {
                        __nv_bfloat16 hh = __float2bfloat16(v);
                        ga.So_h[off] = hh;
                        ga.So_l[off] = __float2bfloat16(v - __bfloat162float(hh));
                    }
                }
            }
        }
    }
}

// ================= embed GEMM: fp16 split-2, drained every 4 chunks =================
struct SegH { const __half* A; const __half* B; int shift; float scale; };
struct HArgs { SegH segs[9]; const float* bias; float* C; };

__device__ __forceinline__ void tg_load_h(const HArgs& ha, uint32_t smb, int ci, int p,
                                          int bm, int bn, int tid) {
    const SegH s = ha.segs[ci >> 5];
    const int k0 = (ci & 31) * 64;
    const uint32_t abase = smb + p * 32768;
    const uint32_t bbase = abase + 16384;
#pragma unroll
    for (int g = 0; g < 2; ++g) {
        int id = tid + g * 512;
        int row = id >> 3, c = id & 7;
        uint32_t soff = row * 128 + ((c ^ (row & 7)) * 16);
        {
            int m = bm + row;
            const void* src = s.A;
            int sz = 0;
            if (m < M_EMB) {
                int t = m % Tn;
                int ts = t + s.shift;
                if (ts >= 0 && ts < Tn) { src = s.A + (size_t)(m + s.shift) * 2048 + k0 + c * 8; sz = 16; }
            }
            cp_async16(abase + soff, src, sz);
        }
        {
            int n = bn + row;    // N = 2048, always in range
            cp_async16(bbase + soff, s.B + (size_t)n * 2048 + k0 + c * 8, 16);
        }
    }
    asm volatile("cp.async.commit_group;" ::: "memory");
}

__global__ void __launch_bounds__(512) tgemm_emb(HArgs ha) {
    extern __shared__ char gsm[];
    const uint32_t smb = smem_to_u32(gsm);
    const int tid = threadIdx.x;
    const int wid = tid >> 5, lane = tid & 31;
    const int bm = blockIdx.y * 128;
    const int bn = blockIdx.x * 128;
    const int mw = (wid & 3) * 32;
    const int nw = (wid >> 2) * 32;
    const int nchunk = 9 * 32;

    float sum[2][4][4];
    float acc[2][4][4];
#pragma unroll
    for (int i = 0; i < 2; ++i)
#pragma unroll
        for (int j = 0; j < 4; ++j)
#pragma unroll
            for (int q = 0; q < 4; ++q) sum[i][j][q] = 0.f;

    tg_load_h(ha, smb, 0, 0, bm, bn, tid);

    const int quad = lane >> 3, ri = lane & 7;

    for (int ci = 0; ci < nchunk; ++ci) {
        if (ci + 1 < nchunk) {
            tg_load_h(ha, smb, ci + 1, (ci + 1) & 1, bm, bn, tid);
            asm volatile("cp.async.wait_group 1;" ::: "memory");
        } else {
            asm volatile("cp.async.wait_group 0;" ::: "memory");
        }
        __syncthreads();

        const uint32_t abase = smb + (ci & 1) * 32768;
        const uint32_t bbase = abase + 16384;
        const bool fresh = ((ci & 3) == 0);
#pragma unroll
        for (int ks = 0; ks < 4; ++ks) {
            const int kc = ks * 2;
            uint32_t afr[2][4];
#pragma unroll
            for (int mt = 0; mt < 2; ++mt) {
                int row = mw + mt * 16 + ri + (quad & 1) * 8;
                int ch = (kc + (quad >> 1)) ^ (row & 7);
                ldmatrix_x4(afr[mt], abase + row * 128 + ch * 16);
            }
#pragma unroll
            for (int bt = 0; bt < 2; ++bt) {
                uint32_t bfr[4];
                int nrow = nw + bt * 16 + ri + (quad >> 1) * 8;
                int ch = (kc + (quad & 1)) ^ (nrow & 7);
                ldmatrix_x4(bfr, bbase + nrow * 128 + ch * 16);
#pragma unroll
                for (int mt = 0; mt < 2; ++mt) {
                    if (fresh && ks == 0) {
                        mma_f16_z(acc[mt][bt * 2],     afr[mt], bfr[0], bfr[1]);
                        mma_f16_z(acc[mt][bt * 2 + 1], afr[mt], bfr[2], bfr[3]);
                    } else {
                        mma_f16(acc[mt][bt * 2],     afr[mt], bfr[0], bfr[1]);
                        mma_f16(acc[mt][bt * 2 + 1], afr[mt], bfr[2], bfr[3]);
                    }
                }
            }
        }
        // drain every 4 chunks (chain-16): RN adds bound RZ-chain bias at ~2e-6
        // while keeping drain FFMA issue cost low. Segment (32-chunk) boundaries
        // are multiples of 4, so each drain group has one scale.
        if ((ci & 3) == 3) {
            const float scl = ha.segs[ci >> 5].scale;
#pragma unroll
            for (int i = 0; i < 2; ++i)
#pragma unroll
                for (int j = 0; j < 4; ++j)
#pragma unroll
                    for (int q = 0; q < 4; ++q) sum[i][j][q] += acc[i][j][q] * scl;
        }
        __syncthreads();
    }

#pragma unroll
    for (int mt = 0; mt < 2; ++mt) {
#pragma unroll
        for (int nt = 0; nt < 4; ++nt) {
            int col = bn + nw + nt * 8 + (lane & 3) * 2;
#pragma unroll
            for (int h = 0; h < 2; ++h) {
                int row = bm + mw + mt * 16 + (lane >> 2) + h * 8;
                if (row >= M_EMB) continue;
#pragma unroll
                for (int q = 0; q < 2; ++q) {
                    int c = col + q;
                    float v = sum[mt][nt][h * 2 + q] + ha.bias[c];
                    ha.C[(size_t)row * Fd + c] = fmaxf(v, 0.f);
                }
            }
        }
    }
}

// ================= split kernels =================
#define RSCALE 2048.f
__global__ void split2h_x(const float* __restrict__ s, __half* h, __half* l, long n) {
    for (long i = blockIdx.x * (long)blockDim.x + threadIdx.x; i < n;
         i += (long)gridDim.x * blockDim.x) {
        float x = s[i];
        __half a = __float2half(x);
        h[i] = a; l[i] = __float2half((x - __half2float(a)) * RSCALE);
    }
}
__global__ void split2h_wk(const float* __restrict__ w, __half* h, __half* l) {
    const long n = 3L * Fd * Fd;
    for (long i = blockIdx.x * (long)blockDim.x + threadIdx.x; i < n;
         i += (long)gridDim.x * blockDim.x) {
        long sh = i / ((long)Fd * Fd);
        long rem = i - sh * (long)Fd * Fd;
        float x = w[rem * 3 + sh];
        __half a = __float2half(x);
        h[i] = a; l[i] = __float2half((x - __half2float(a)) * RSCALE);
    }
}
__global__ void split2_kernel(const float* __restrict__ s, __nv_bfloat16* h,
                              __nv_bfloat16* l, long n) {
    for (long i = blockIdx.x * (long)blockDim.x + threadIdx.x; i < n;
         i += (long)gridDim.x * blockDim.x) {
        float x = s[i];
        __nv_bfloat16 a = __float2bfloat16(x);
        h[i] = a; l[i] = __float2bfloat16(x - __bfloat162float(a));
    }
}
__global__ void split2_c1w_kernel(const float* __restrict__ w, __nv_bfloat16* h,
                                  __nv_bfloat16* l) {
    const long n = 3L * 128 * Fd;
    for (long i = blockIdx.x * (long)blockDim.x + threadIdx.x; i < n;
         i += (long)gridDim.x * blockDim.x) {
        long sh = i / (128L * Fd);
        long rem = i - sh * 128L * Fd;
        float x = w[rem * 3 + sh];
        __nv_bfloat16 a = __float2bfloat16(x);
        h[i] = a; l[i] = __float2bfloat16(x - __bfloat162float(a));
    }
}

// ================= CAS + actionness =================
__global__ void __launch_bounds__(320) cas_kernel(const float* __restrict__ wcls,
                                                  float* __restrict__ dout)
{
    __shared__ float embs[5 * Fd];
    __shared__ float cres[5 * NC];
    const int b  = blockIdx.x / 150;
    const int t0 = (blockIdx.x % 150) * 5;
    const float* src = g_emb + ((size_t)b * Tn + t0) * Fd;
    for (int i = threadIdx.x; i < 5 * Fd; i += 320) embs[i] = src[i];
    __syncthreads();

    const int w = threadIdx.x >> 5, lane = threadIdx.x & 31;
    const int tl = w >> 1, cg = (w & 1) * 10;
    for (int c = cg; c < cg + 10; ++c) {
        float acc = 0.f;
        const float* wr = wcls + (size_t)c * Fd;
        const float* er = embs + tl * Fd;
        for (int e = lane; e < Fd; e += 32) acc += er[e] * wr[e];
#pragma unroll
        for (int off = 16; off; off >>= 1) acc += __shfl_down_sync(0xffffffffu, acc, off);
        if (lane == 0) cres[tl * NC + c] = fmaxf(acc, 0.f);
    }
    __syncthreads();

    if (threadIdx.x < 100) {
        int tl2 = threadIdx.x / NC, c2 = threadIdx.x % NC;
        dout[OUT_CAS + ((size_t)(b * Tn + t0 + tl2)) * NC + c2] = cres[tl2 * NC + c2];
    }
    if (threadIdx.x < 5) {
        float s = 0.f;
        for (int c = 0; c < NC; ++c) s += cres[threadIdx.x * NC + c];
        dout[OUT_ACT + b * Tn + t0 + threadIdx.x] = s;
    }
}

// ================= a2 =================
__global__ void a2_kernel(const float* __restrict__ tf1w, const float* __restrict__ tf1b,
                          const float* __restrict__ tf2w, const float* __restrict__ tf2b,
                          float* __restrict__ dout)
{
    __shared__ float a[Tn], a1[Tn];
    const int b = blockIdx.x;
    for (int t = threadIdx.x; t < Tn; t += blockDim.x) a[t] = dout[OUT_ACT + b*Tn + t];
    __syncthreads();
    for (int t = threadIdx.x; t < Tn; t += blockDim.x) {
        float v = tf1b[0];
#pragma unroll
        for (int k = 0; k < 3; ++k) { int tt = t+k-1; if (tt>=0 && tt<Tn) v += tf1w[k]*a[tt]; }
        a1[t] = fmaxf(v, 0.f);
    }
    __syncthreads();
    for (int t = threadIdx.x; t < Tn; t += blockDim.x) {
        float v = tf2b[0];
#pragma unroll
        for (int k = 0; k < 3; ++k) { int tt = t+k-1; if (tt>=0 && tt<Tn) v += tf2w[k]*a1[tt]; }
        dout[OUT_A2 + b*Tn + t] = fmaxf(v, 0.f);
    }
}

// ================= sorting =================
__device__ __forceinline__ unsigned int fkey(float v) {
    unsigned int b = __float_as_uint(v);
    return (b & 0x80000000u) ? ~b : (b | 0x80000000u);
}
__device__ __forceinline__ float fdec(unsigned int u) {
    unsigned int b = (u & 0x80000000u) ? (u ^ 0x80000000u) : ~u;
    return __uint_as_float(b);
}
__device__ void bitonic1024_u64(unsigned long long* key, int tid) {
    for (int k = 2; k <= 1024; k <<= 1)
        for (int j = k >> 1; j > 0; j >>= 1) {
            __syncthreads();
            for (int i = tid; i < 1024; i += 512) {
                int ixj = i ^ j;
                if (ixj > i) {
                    bool up = ((i & k) == 0);
                    unsigned long long a = key[i], b2 = key[ixj];
                    bool sw = up ? (a > b2) : (a < b2);
                    if (sw) { key[i] = b2; key[ixj] = a; }
                }
            }
        }
    __syncthreads();
}
__device__ void bitonic1024_u32(unsigned int* key, int tid) {
    for (int k = 2; k <= 1024; k <<= 1)
        for (int j = k >> 1; j > 0; j >>= 1) {
            __syncthreads();
            for (int i = tid; i < 1024; i += 512) {
                int ixj = i ^ j;
                if (ixj > i) {
                    bool up = ((i & k) == 0);
                    unsigned int a = key[i], b2 = key[ixj];
                    bool sw = up ? (a > b2) : (a < b2);
                    if (sw) { key[i] = b2; key[ixj] = a; }
                }
            }
        }
    __syncthreads();
}

__global__ void __launch_bounds__(512) sort_act_kernel(const float* __restrict__ dout) {
    __shared__ unsigned long long key[1024];
    const int b = blockIdx.x, tid = threadIdx.x;
    for (int i = tid; i < 1024; i += 512) {
        if (i < Tn) {
            unsigned int nu = ~fkey(dout[OUT_ACT + b*Tn + i]);
            key[i] = ((unsigned long long)nu << 32) | (unsigned int)i;
        } else key[i] = 0xFFFFFFFFFFFFFFFFull;
    }
    bitonic1024_u64(key, tid);
    for (int i = tid; i < 150; i += 512) g_idx[b*150 + i] = (int)(key[i] & 0xffffffffu);
    if (tid == 0) {
        float v0 = fdec(~(unsigned int)(key[374] >> 32));
        float v1 = fdec(~(unsigned int)(key[375] >> 32));
        g_med[b] = 0.5f * (v0 + v1);
    }
}

__global__ void morph_kernel(const float* __restrict__ dout) {
    __shared__ float a[Tn];
    __shared__ float bin[Tn];
    __shared__ float red[256];
    const int b = blockIdx.x, tid = threadIdx.x;
    float lmax = -FLT_MAX;
    for (int t = tid; t < Tn; t += 256) { float v = dout[OUT_ACT + b*Tn + t]; a[t] = v; lmax = fmaxf(lmax, v); }
    red[tid] = lmax; __syncthreads();
    for (int s = 128; s > 0; s >>= 1) { if (tid < s) red[tid] = fmaxf(red[tid], red[tid+s]); __syncthreads(); }
    float amax = red[0];
    float med = g_med[b];
    for (int t = tid; t < Tn; t += 256) bin[t] = (a[t] > med) ? 1.f : 0.f;
    __syncthreads();
    for (int t = tid; t < Tn; t += 256) {
        float e3 = 1.f, e6 = 1.f, d6 = 0.f, d3 = 0.f;
#pragma unroll
        for (int o = -1; o <= 1; ++o) { int u = t+o; float v = (u>=0&&u<Tn)?bin[u]:0.f; e3 = fminf(e3,v); d3 = fmaxf(d3,v); }
#pragma unroll
        for (int o = -3; o <= 2; ++o) { int u = t+o; float v = (u>=0&&u<Tn)?bin[u]:0.f; e6 = fminf(e6,v); }
#pragma unroll
        for (int o = -2; o <= 3; ++o) { int u = t+o; float v = (u>=0&&u<Tn)?bin[u]:0.f; d6 = fmaxf(d6,v); }
        g_sel[1*Bn*Tn + b*Tn + t] = amax - a[t];
        g_sel[2*Bn*Tn + b*Tn + t] = a[t] * (e3 - e6);
        g_sel[3*Bn*Tn + b*Tn + t] = a[t] * (d6 - d3);
    }
}

__global__ void __launch_bounds__(512) sort_gen_kernel() {
    __shared__ unsigned long long key[1024];
    const int aid = blockIdx.x / 16 + 1;
    const int b = blockIdx.x % 16;
    const int tid = threadIdx.x;
    const float* sc = g_sel + aid*Bn*Tn + b*Tn;
    const unsigned int msk = (aid == 1) ? 0xFFFFFFF8u : 0xFFFFFFFFu;
    for (int i = tid; i < 1024; i += 512) {
        if (i < Tn) {
            unsigned int nu = ~(fkey(sc[i]) & msk);
            key[i] = ((unsigned long long)nu << 32) | (unsigned int)i;
        } else key[i] = 0xFFFFFFFFFFFFFFFFull;
    }
    bitonic1024_u64(key, tid);
    if (aid == 1) { for (int i = tid; i < 150; i += 512) g_idx[2400 + b*150 + i] = (int)(key[i] & 0xffffffffu); }
    else if (aid == 2) { if (tid < 37) g_idx[4800 + b*37 + tid] = (int)(key[tid] & 0xffffffffu); }
    else { if (tid < 37) g_idx[5392 + b*37 + tid] = (int)(key[tid] & 0xffffffffu); }
}

__global__ void __launch_bounds__(256) gather_kernel(float* __restrict__ dout) {
    const int r = blockIdx.x; // 0..5983
    int b, j, srcidx, set = -1;
    float* dst;
    if (r < 2400) {
        b = r/150; j = r%150; srcidx = g_idx[b*150 + j];
        dst = dout + OUT_EA + (size_t)r * Fd;
        if (j < 148) set = j / 37;
    } else if (r < 4800) {
        int rr = r - 2400; b = rr/150; j = rr%150; srcidx = g_idx[2400 + b*150 + j];
        dst = dout + OUT_EB + (size_t)rr * Fd;
        if (j < 148) set = 4 + j / 37;
    } else if (r < 5392) {
        int rr = r - 4800; b = rr/37; j = rr%37; srcidx = g_idx[4800 + rr];
        dst = dout + OUT_HA + (size_t)rr * Fd; set = 8;
    } else {
        int rr = r - 5392; b = rr/37; j = rr%37; srcidx = g_idx[5392 + rr];
        dst = dout + OUT_HB + (size_t)rr * Fd; set = 9;
    }
    const float4* src = reinterpret_cast<const float4*>(g_emb + ((size_t)b*Tn + srcidx)*Fd);
    float4* d4 = reinterpret_cast<float4*>(dst);
    __nv_bfloat16* th = nullptr; __nv_bfloat16* tl = nullptr;
    if (set >= 0) {
        size_t tb = ((size_t)set*SROWS + b*37 + (j % 37))*Fd;
        th = g_tok2 + tb;
        tl = g_tok2 + (size_t)TOKROWS*Fd + tb;
    }
    for (int i = threadIdx.x; i < Fd/4; i += 256) {
        float4 v = src[i];
        d4[i] = v;
        if (th) {
            float vv[4] = {v.x, v.y, v.z, v.w};
#pragma unroll
            for (int q = 0; q < 4; ++q) {
                __nv_bfloat16 h = __float2bfloat16(vv[q]);
                th[i*4 + q] = h;
                tl[i*4 + q] = __float2bfloat16(vv[q] - __bfloat162float(h));
            }
        }
    }
}

// ================= attention (writes aopre split-2 planes) =================
__global__ void __launch_bounds__(256) attn_kernel() {
    __shared__ float qt[37*64];
    __shared__ float kt[37*64];
    __shared__ float s[37*37];
    const int id = blockIdx.x;
    const int h = id & 3, b = (id >> 2) & 15, m = id >> 6;
    const int rh = m >> 1, role = m & 1;
    const int as = d_aset[rh], bs = d_bset[rh];
    const int qset = role ? as : bs;
    const int kvset = role ? bs : as;
    const int trowbase = role ? 37 : 0;
    const int tid = threadIdx.x;
    const float scale = 0.044194173824159216f; // 1/sqrt(512)

    const float* Qb = g_qkv + ((size_t)(qset*SROWS + b*37)) * K6 + h*512;
    const float* Kb = g_qkv + ((size_t)(kvset*SROWS + b*37)) * K6 + 2048 + h*512;
    const float* Vb = g_qkv + ((size_t)(kvset*SROWS + b*37)) * K6 + 4096 + h*512;

    for (int i = tid; i < 1369; i += 256) s[i] = 0.f;
    for (int dt = 0; dt < 8; ++dt) {
        __syncthreads();
        for (int i = tid; i < 2368; i += 256) {
            int q = i >> 6, d = i & 63;
            qt[i] = Qb[(size_t)q*K6 + dt*64 + d];
            kt[i] = Kb[(size_t)q*K6 + dt*64 + d];
        }
        __syncthreads();
        for (int p = tid; p < 1369; p += 256) {
            int q = p / 37, k = p % 37;
            const float* qr = qt + q*64;
            const float* kr = kt + k*64;
            float acc = 0.f;
#pragma unroll
            for (int d = 0; d < 64; ++d) acc += qr[d] * kr[d];
            s[p] += acc;
        }
    }
    __syncthreads();
    {
        const int w = tid >> 5, lane = tid & 31;
        for (int r = w; r < 37; r += 8) {
            float sv0 = s[r*37 + lane] * scale;
            float sv1 = (lane < 5) ? s[r*37 + 32 + lane] * scale : -FLT_MAX;
            float mx = fmaxf(sv0, sv1);
#pragma unroll
            for (int off = 16; off; off >>= 1) mx = fmaxf(mx, __shfl_xor_sync(0xffffffffu, mx, off));
            float e0 = expf(sv0 - mx);
            float e1 = (lane < 5) ? expf(sv1 - mx) : 0.f;
            float sum = e0 + e1;
#pragma unroll
            for (int off = 16; off; off >>= 1) sum += __shfl_xor_sync(0xffffffffu, sum, off);
            float inv = 1.f / sum;
            s[r*37 + lane] = e0 * inv;
            if (lane < 5) s[r*37 + 32 + lane] = e1 * inv;
        }
    }
    const size_t rowbase = (size_t)(rh*1184 + b*74 + trowbase);
    for (int dt = 0; dt < 8; ++dt) {
        __syncthreads();
        for (int i = tid; i < 2368; i += 256) {
            int k = i >> 6, d = i & 63;
            kt[i] = Vb[(size_t)k*K6 + dt*64 + d];
        }
        __syncthreads();
        for (int p = tid; p < 2368; p += 256) {
            int q = p >> 6, d = p & 63;
            const float* sr = s + q*37;
            float acc = 0.f;
#pragma unroll
            for (int k = 0; k < 37; ++k) acc += sr[k] * kt[k*64 + d];
            size_t off = (rowbase + q)*Fd + h*512 + dt*64 + d;
            __nv_bfloat16 hh = __float2bfloat16(acc);
            g_aop2[off] = hh;
            g_aop2[(size_t)AOROWS*Fd + off] = __float2bfloat16(acc - __bfloat162float(hh));
        }
    }
}

// ================= c2 + l1 + l2 fused =================
__global__ void __launch_bounds__(256) tail_kernel(
    const float* __restrict__ c2w, const float* __restrict__ c2b,
    const float* __restrict__ l1w, const float* __restrict__ l1b,
    const float* __restrict__ l2w, const float* __restrict__ l2b,
    float* __restrict__ dout)
{
    __shared__ float sm[74*128];
    const int rb = blockIdx.x;
    const int tid = threadIdx.x;
    for (int i = tid; i < 74*128; i += 256)
        sm[i] = g_c1o[(size_t)rb*74*128 + i];
    __syncthreads();

    const int o = tid & 31;
    const int tbase = tid >> 5;
    float r[10];
    int nt = 0;
    for (int t = tbase; t < 74; t += 8) {
        float v = c2b[o];
#pragma unroll
        for (int k = 0; k < 3; ++k) {
            int tt = t + k - 1;
            if (tt >= 0 && tt < 74) {
                const float* row = sm + tt*128;
                const float* w = c2w + o*384 + k;
#pragma unroll 16
                for (int c = 0; c < 128; ++c) v += row[c] * w[c*3];
            }
        }
        r[nt++] = (v >= 0.f) ? v : 0.2f * v;
    }
    __syncthreads();
    { int i = 0; for (int t = tbase; t < 74; t += 8) sm[o*74 + t] = r[i++]; }
    __syncthreads();

    for (int p = tid; p < 320; p += 256) {
        int c = p / 10, j = p % 10;
        float v = l1b[j];
        const float* y = sm + c*74;
        const float* w = l1w + j*74;
        for (int t = 0; t < 74; ++t) v += y[t] * w[t];
        sm[2368 + p] = (v >= 0.f) ? v : 0.2f * v;
    }
    __syncthreads();
    float ps = 0.f;
    for (int p = tid; p < 320; p += 256) ps += sm[2368 + p] * l2w[p];
    sm[3000 + tid] = ps;
    __syncthreads();
    for (int s = 128; s > 0; s >>= 1) { if (tid < s) sm[3000+tid] += sm[3000+tid+s]; __syncthreads(); }
    if (tid == 0) {
        float x = sm[3000] + l2b[0];
        dout[OUT_RH + rb] = 1.f / (1.f + expf(-x));
    }
}

// ================= video scores =================
__global__ void __launch_bounds__(512) vsort_kernel(const float* __restrict__ dout) {
    __shared__ unsigned int key[1024];
    const int bc = blockIdx.x;
    const int b = bc / NC, c = bc % NC;
    const int tid = threadIdx.x;
    for (int i = tid; i < 1024; i += 512)
        key[i] = (i < Tn) ? ~fkey(dout[OUT_CAS + (size_t)(b*Tn + i)*NC + c]) : 0xFFFFFFFFu;
    bitonic1024_u32(key, tid);
    if (tid == 0) {
        float s = 0.f;
        for (int i = 0; i < 150; ++i) s += fdec(~key[i]);
        g_vmean[bc] = s / 150.f;
    }
}
__global__ void vsoftmax_kernel(float* __restrict__ dout) {
    const int b = blockIdx.x, t = threadIdx.x;
    float v = (t < NC) ? g_vmean[b*NC + t] : -FLT_MAX;
    float mx = v;
#pragma unroll
    for (int off = 16; off; off >>= 1) mx = fmaxf(mx, __shfl_xor_sync(0xffffffffu, mx, off));
    float e = (t < NC) ? expf(v - mx) : 0.f;
    float sum = e;
#pragma unroll
    for (int off = 16; off; off >>= 1) sum += __shfl_xor_sync(0xffffffffu, sum, off);
    if (t < NC) dout[OUT_VS + b*NC + t] = e / sum;
}

// ================= launch =================
extern "C" void kernel_launch(void* const* d_in, const int* in_sizes, int n_in,
                              void* d_out, int out_size) {
    const float* x    = (const float*)d_in[0];
    const float* wemb = (const float*)d_in[1];
    const float* bemb = (const float*)d_in[2];
    const float* wcls = (const float*)d_in[3];
    const float* tf1w = (const float*)d_in[4];
    const float* tf1b = (const float*)d_in[5];
    const float* tf2w = (const float*)d_in[6];
    const float* tf2b = (const float*)d_in[7];
    const float* inw  = (const float*)d_in[8];
    const float* inb  = (const float*)d_in[9];
    const float* outw = (const float*)d_in[10];
    const float* outb = (const float*)d_in[11];
    const float* c1w  = (const float*)d_in[12];
    const float* c1b  = (const float*)d_in[13];
    const float* c2w  = (const float*)d_in[14];
    const float* c2b  = (const float*)d_in[15];
    const float* l1w  = (const float*)d_in[16];
    const float* l1b  = (const float*)d_in[17];
    const float* l2w  = (const float*)d_in[18];
    const float* l2b  = (const float*)d_in[19];
    float* dout = (float*)d_out;

    float *p_emb, *p_qkv, *p_c1o;
    __half *p_xh, *p_wkh;
    __nv_bfloat16 *p_tok2, *p_inw2, *p_aop2, *p_outw2, *p_ao2, *p_c1w2;
    cudaGetSymbolAddress((void**)&p_emb,  g_emb);
    cudaGetSymbolAddress((void**)&p_qkv,  g_qkv);
    cudaGetSymbolAddress((void**)&p_c1o,  g_c1o);
    cudaGetSymbolAddress((void**)&p_xh,   g_xh);
    cudaGetSymbolAddress((void**)&p_wkh,  g_wkh);
    cudaGetSymbolAddress((void**)&p_tok2, g_tok2);
    cudaGetSymbolAddress((void**)&p_inw2, g_inw2);
    cudaGetSymbolAddress((void**)&p_aop2, g_aop2);
    cudaGetSymbolAddress((void**)&p_outw2,g_outw2);
    cudaGetSymbolAddress((void**)&p_c1w2, g_c1w2);
    cudaGetSymbolAddress((void**)&p_ao2,  g_ao2);

    cudaFuncSetAttribute(tgemm, cudaFuncAttributeMaxDynamicSharedMemorySize, TG_SMEM);
    cudaFuncSetAttribute(tgemm_emb, cudaFuncAttributeMaxDynamicSharedMemorySize, TG_SMEM);

    const size_t XP   = (size_t)M_EMB * Fd;
    const size_t WKP  = (size_t)3 * Fd * Fd;
    const size_t TOKP = (size_t)TOKROWS * Fd;
    const size_t INWP = (size_t)K6 * Fd;
    const size_t AOP  = (size_t)AOROWS * Fd;
    const size_t OWP  = (size_t)Fd * Fd;
    const size_t C1P  = (size_t)3 * 128 * Fd;

    // splits
    split2h_x<<<2048, 256>>>(x, p_xh, p_xh + XP, (long)XP);
    split2h_wk<<<2048, 256>>>(wemb, p_wkh, p_wkh + WKP);
    split2_kernel<<<2048, 256>>>(inw, p_inw2, p_inw2 + INWP, (long)INWP);
    split2_kernel<<<1024, 256>>>(outw, p_outw2, p_outw2 + OWP, (long)OWP);
    split2_c1w_kernel<<<256, 256>>>(c1w, p_c1w2, p_c1w2 + C1P);

    // embed conv GEMM: fp16 split-2 {hh, hl, lh} x 3 shifts, drained every 4 chunks
    {
        HArgs ha = {};
        const float S = 1.f / RSCALE;
        const int pa[3] = {0, 0, 1};
        const int pb[3] = {0, 1, 0};
        const float ps[3] = {1.f, S, S};
        int q = 0;
        for (int sh = 0; sh < 3; ++sh)
            for (int pr = 0; pr < 3; ++pr) {
                ha.segs[q].A = p_xh + (size_t)pa[pr] * XP;
                ha.segs[q].B = p_wkh + (size_t)pb[pr] * WKP + (size_t)sh * Fd * Fd;
                ha.segs[q].shift = sh - 1;
                ha.segs[q].scale = ps[pr];
                ++q;
            }
        ha.bias = bemb; ha.C = p_emb;
        tgemm_emb<<<dim3(Fd/128, (M_EMB + 127)/128), 512, TG_SMEM>>>(ha);
    }

    cas_kernel<<<Bn*150, 320>>>(wcls, dout);
    a2_kernel<<<Bn, 256>>>(tf1w, tf1b, tf2w, tf2b, dout);
    sort_act_kernel<<<Bn, 512>>>(dout);
    morph_kernel<<<Bn, 256>>>(dout);
    sort_gen_kernel<<<48, 512>>>();
    gather_kernel<<<5984, 256>>>(dout);

    // QKV GEMM: bf16 split-2 x 3 products (undrained, proven fast)
    {
        GArgs ga = {};
        const int pa[3] = {0,0,1}, pb[3] = {0,1,0};
        for (int pr = 0; pr < 3; ++pr) {
            ga.segs[pr].A = p_tok2 + (size_t)pa[pr]*TOKP;
            ga.segs[pr].B = p_inw2 + (size_t)pb[pr]*INWP;
            ga.segs[pr].shift = 0;
        }
        ga.nseg = 3; ga.M = TOKROWS; ga.N = K6; ga.Tper = 0;
        ga.C = p_qkv; ga.bias = inb; ga.act = 0; ga.ldc = K6;
        tgemm<<<dim3(K6/128, (TOKROWS+127)/128), 256, TG_SMEM>>>(ga);
    }

    attn_kernel<<<1536, 256>>>();

    // out-proj GEMM: bf16 split-2, epilogue writes split-2 planes
    {
        GArgs ga = {};
        const int pa[3] = {0,0,1}, pb[3] = {0,1,0};
        for (int pr = 0; pr < 3; ++pr) {
            ga.segs[pr].A = p_aop2 + (size_t)pa[pr]*AOP;
            ga.segs[pr].B = p_outw2 + (size_t)pb[pr]*OWP;
            ga.segs[pr].shift = 0;
        }
        ga.nseg = 3; ga.M = AOROWS; ga.N = Fd; ga.Tper = 0;
        ga.C = nullptr; ga.bias = outb; ga.act = 0; ga.ldc = Fd;
        ga.So_h = p_ao2; ga.So_l = p_ao2 + AOP;
        tgemm<<<dim3(Fd/128, AOROWS/128), 256, TG_SMEM>>>(ga);
    }

    // c1 conv GEMM: bf16 split-2 x 3 products x 3 shifts, N=128
    {
        GArgs ga = {};
        const int pa[3] = {0,0,1}, pb[3] = {0,1,0};
        int q = 0;
        for (int sh = 0; sh < 3; ++sh)
            for (int pr = 0; pr < 3; ++pr) {
                ga.segs[q].A = p_ao2 + (size_t)pa[pr]*AOP;
                ga.segs[q].B = p_c1w2 + (size_t)pb[pr]*C1P + (size_t)sh*128*Fd;
                ga.segs[q].shift = sh - 1;
                ++q;
            }
        ga.nseg = 9; ga.M = AOROWS; ga.N = 128; ga.Tper = 74;
        ga.C = p_c1o; ga.bias = c1b; ga.act = 2; ga.ldc = 128;
        tgemm<<<dim3(1, AOROWS/128), 256, TG_SMEM>>>(ga);
    }

    tail_kernel<<<192, 256>>>(c2w, c2b, l1w, l1b, l2w, l2b, dout);
    vsort_kernel<<<Bn*NC, 512>>>(dout);
    vsoftmax_kernel<<<Bn, 32>>>(dout);
}

// round 16
// speedup vs baseline: 1.8068x; 1.0019x over previous
#include <cuda_runtime.h>
#include <cuda_bf16.h>
#include <cuda_fp16.h>
#include <math.h>
#include <float.h>
#include <stdint.h>

#define Bn 16
#define Tn 750
#define Fd 2048
#define NC 20
#define K6 6144
#define M_EMB 12000
#define SROWS 592
#define TOKROWS 5920
#define AOROWS 14208

#define OUT_VS   0
#define OUT_ACT  320
#define OUT_A2   12320
#define OUT_CAS  24320
#define OUT_RH   264320
#define OUT_EA   264512
#define OUT_EB   5179712
#define OUT_HA   10094912
#define OUT_HB   11307328

// ---------------- scratch (device globals) ----------------
__device__ float g_emb [(size_t)M_EMB * Fd];
__device__ float g_qkv [(size_t)TOKROWS * K6];
__device__ float g_c1o [(size_t)AOROWS * 128];
__device__ float g_c1p [2 * (size_t)AOROWS * 128];   // split-K partials
__device__ float g_sel [4 * Bn * Tn];
__device__ float g_med [Bn];
__device__ int   g_idx [5984];
__device__ float g_vmean[Bn * NC];

// fp16 split-2 planes for embed GEMM
__device__ __half g_xh  [2 * (size_t)M_EMB * Fd];          // x: h, l(*2048)
__device__ __half g_wkh [2 * (size_t)3 * Fd * Fd];         // w_embed: [split][sh][o][e]

// bf16 split-2 planes for trio GEMMs
__device__ __nv_bfloat16 g_tok2 [2 * (size_t)TOKROWS * Fd];
__device__ __nv_bfloat16 g_inw2 [2 * (size_t)K6 * Fd];
__device__ __nv_bfloat16 g_aop2 [2 * (size_t)AOROWS * Fd];
__device__ __nv_bfloat16 g_outw2[2 * (size_t)Fd * Fd];
__device__ __nv_bfloat16 g_ao2  [2 * (size_t)AOROWS * Fd];
__device__ __nv_bfloat16 g_c1w2 [2 * (size_t)3 * 128 * Fd];

__device__ __constant__ int d_aset[12] = {1,3,0,5,7,4,9,3,8,3,6,2};
__device__ __constant__ int d_bset[12] = {8,2,3,9,6,7,8,9,7,7,3,7};

// ================= MMA helpers (sm_80+ base features) =================
__device__ __forceinline__ uint32_t smem_to_u32(const void* p) {
    uint32_t a;
    asm("{ .reg .u64 t; cvta.to.shared.u64 t, %1; cvt.u32.u64 %0, t; }" : "=r"(a) : "l"(p));
    return a;
}
__device__ __forceinline__ void ldmatrix_x4(uint32_t* r, uint32_t addr) {
    asm volatile("ldmatrix.sync.aligned.m8n8.x4.shared.b16 {%0,%1,%2,%3}, [%4];"
        : "=r"(r[0]), "=r"(r[1]), "=r"(r[2]), "=r"(r[3]) : "r"(addr));
}
__device__ __forceinline__ void mma_bf16(float* d, const uint32_t* a, uint32_t b0, uint32_t b1) {
    asm volatile("mma.sync.aligned.m16n8k16.row.col.f32.bf16.bf16.f32 "
        "{%0,%1,%2,%3}, {%4,%5,%6,%7}, {%8,%9}, {%0,%1,%2,%3};"
        : "+f"(d[0]), "+f"(d[1]), "+f"(d[2]), "+f"(d[3])
        : "r"(a[0]), "r"(a[1]), "r"(a[2]), "r"(a[3]), "r"(b0), "r"(b1));
}
__device__ __forceinline__ void mma_f16(float* d, const uint32_t* a, uint32_t b0, uint32_t b1) {
    asm volatile("mma.sync.aligned.m16n8k16.row.col.f32.f16.f16.f32 "
        "{%0,%1,%2,%3}, {%4,%5,%6,%7}, {%8,%9}, {%0,%1,%2,%3};"
        : "+f"(d[0]), "+f"(d[1]), "+f"(d[2]), "+f"(d[3])
        : "r"(a[0]), "r"(a[1]), "r"(a[2]), "r"(a[3]), "r"(b0), "r"(b1));
}
__device__ __forceinline__ void mma_f16_z(float* d, const uint32_t* a, uint32_t b0, uint32_t b1) {
    asm volatile("mma.sync.aligned.m16n8k16.row.col.f32.f16.f16.f32 "
        "{%0,%1,%2,%3}, {%4,%5,%6,%7}, {%8,%9}, {%10,%11,%12,%13};"
        : "=f"(d[0]), "=f"(d[1]), "=f"(d[2]), "=f"(d[3])
        : "r"(a[0]), "r"(a[1]), "r"(a[2]), "r"(a[3]), "r"(b0), "r"(b1),
          "f"(0.f), "f"(0.f), "f"(0.f), "f"(0.f));
}
__device__ __forceinline__ void cp_async16(uint32_t dst, const void* src, int srcsize) {
    asm volatile("cp.async.ca.shared.global [%0], [%1], 16, %2;"
        :: "r"(dst), "l"(src), "r"(srcsize));
}

// ================= trio GEMM: bf16, undrained (R6/R9-proven) =================
struct Seg { const __nv_bfloat16* A; const __nv_bfloat16* B; int shift; };
struct GArgs {
    Seg segs[9];
    int nseg, M, N, Tper, act, ldc;
    float* C; const float* bias;
    __nv_bfloat16* So_h; __nv_bfloat16* So_l;
};

#define TG_SMEM 65536

__device__ __forceinline__ void tg_load(const GArgs& ga, uint32_t smb, int ci, int p,
                                        int bm, int bn, int tid, int segbase) {
    const Seg s = ga.segs[segbase + (ci >> 5)];
    const int k0 = (ci & 31) * 64;
    const uint32_t abase = smb + p * 32768;
    const uint32_t bbase = abase + 16384;
#pragma unroll
    for (int g = 0; g < 4; ++g) {
        int id = tid + g * 256;
        int row = id >> 3, c = id & 7;
        uint32_t soff = row * 128 + ((c ^ (row & 7)) * 16);
        {
            int m = bm + row;
            const void* src = s.A;
            int sz = 0;
            if (m < ga.M) {
                int srow = m;
                bool ok = true;
                if (ga.Tper) {
                    int t = m % ga.Tper; int ts = t + s.shift;
                    ok = (ts >= 0 && ts < ga.Tper);
                    srow = m + s.shift;
                }
                if (ok) { src = s.A + (size_t)srow * 2048 + k0 + c * 8; sz = 16; }
            }
            cp_async16(abase + soff, src, sz);
        }
        {
            int n = bn + row;
            const void* src = s.B;
            int sz = 0;
            if (n < ga.N) { src = s.B + (size_t)n * 2048 + k0 + c * 8; sz = 16; }
            cp_async16(bbase + soff, src, sz);
        }
    }
    asm volatile("cp.async.commit_group;" ::: "memory");
}

__global__ void __launch_bounds__(256) tgemm(GArgs ga) {
    extern __shared__ char gsm[];
    const uint32_t smb = smem_to_u32(gsm);
    const int tid = threadIdx.x;
    const int wid = tid >> 5, lane = tid & 31;
    const int bm = blockIdx.y * 128;
    const int bn = blockIdx.x * 128;
    const int mw = (wid & 3) * 32;
    const int nw = (wid >> 2) * 64;
    const int nchunk = ga.nseg * 32;

    float acc[2][8][4];
#pragma unroll
    for (int i = 0; i < 2; ++i)
#pragma unroll
        for (int j = 0; j < 8; ++j)
#pragma unroll
            for (int q = 0; q < 4; ++q) acc[i][j][q] = 0.f;

    tg_load(ga, smb, 0, 0, bm, bn, tid, 0);

    const int quad = lane >> 3, ri = lane & 7;

    for (int ci = 0; ci < nchunk; ++ci) {
        if (ci + 1 < nchunk) {
            tg_load(ga, smb, ci + 1, (ci + 1) & 1, bm, bn, tid, 0);
            asm volatile("cp.async.wait_group 1;" ::: "memory");
        } else {
            asm volatile("cp.async.wait_group 0;" ::: "memory");
        }
        __syncthreads();

        const uint32_t abase = smb + (ci & 1) * 32768;
        const uint32_t bbase = abase + 16384;
#pragma unroll
        for (int ks = 0; ks < 4; ++ks) {
            const int kc = ks * 2;
            uint32_t afr[2][4];
#pragma unroll
            for (int mt = 0; mt < 2; ++mt) {
                int row = mw + mt * 16 + ri + (quad & 1) * 8;
                int ch = (kc + (quad >> 1)) ^ (row & 7);
                ldmatrix_x4(afr[mt], abase + row * 128 + ch * 16);
            }
#pragma unroll
            for (int np = 0; np < 4; ++np) {
                uint32_t bfr[4];
                int nrow = nw + np * 16 + ri + (quad >> 1) * 8;
                int ch = (kc + (quad & 1)) ^ (nrow & 7);
                ldmatrix_x4(bfr, bbase + nrow * 128 + ch * 16);
#pragma unroll
                for (int mt = 0; mt < 2; ++mt) {
                    mma_bf16(acc[mt][np * 2],     afr[mt], bfr[0], bfr[1]);
                    mma_bf16(acc[mt][np * 2 + 1], afr[mt], bfr[2], bfr[3]);
                }
            }
        }
        __syncthreads();
    }

#pragma unroll
    for (int mt = 0; mt < 2; ++mt) {
#pragma unroll
        for (int nt = 0; nt < 8; ++nt) {
            int col = bn + nw + nt * 8 + (lane & 3) * 2;
            if (col >= ga.N) continue;
#pragma unroll
            for (int h = 0; h < 2; ++h) {
                int row = bm + mw + mt * 16 + (lane >> 2) + h * 8;
                if (row >= ga.M) continue;
#pragma unroll
                for (int q = 0; q < 2; ++q) {
                    int c = col + q;
                    float v = acc[mt][nt][h * 2 + q];
                    if (ga.bias) v += ga.bias[c];
                    if (ga.act == 1) v = fmaxf(v, 0.f);
                    else if (ga.act == 2) v = (v >= 0.f) ? v : 0.2f * v;
                    size_t off = (size_t)row * ga.ldc + c;
                    if (ga.C) ga.C[off] = v;
                    if (ga.So_h) {
                        __nv_bfloat16 hh = __float2bfloat16(v);
                        ga.So_h[off] = hh;
                        ga.So_l[off] = __float2bfloat16(v - __bfloat162float(hh));
                    }
                }
            }
        }
    }
}

// ===== c1 split-K variant: grid (2, 111); part 0 = segs 0-4, part 1 = segs 5-8.
// Writes raw fp32 partials to g_c1p; c1red_kernel combines + bias + leaky. =====
__global__ void __launch_bounds__(256) tgemm_c1(GArgs ga) {
    extern __shared__ char gsm[];
    const uint32_t smb = smem_to_u32(gsm);
    const int tid = threadIdx.x;
    const int wid = tid >> 5, lane = tid & 31;
    const int part = blockIdx.x;                 // 0 or 1
    const int bm = blockIdx.y * 128;
    const int bn = 0;
    const int mw = (wid & 3) * 32;
    const int nw = (wid >> 2) * 64;
    const int segbase = part ? 5 : 0;
    const int nchunk = (part ? 4 : 5) * 32;
    float* Cp = ga.C + (size_t)part * AOROWS * 128;

    float acc[2][8][4];
#pragma unroll
    for (int i = 0; i < 2; ++i)
#pragma unroll
        for (int j = 0; j < 8; ++j)
#pragma unroll
            for (int q = 0; q < 4; ++q) acc[i][j][q] = 0.f;

    tg_load(ga, smb, 0, 0, bm, bn, tid, segbase);

    const int quad = lane >> 3, ri = lane & 7;

    for (int ci = 0; ci < nchunk; ++ci) {
        if (ci + 1 < nchunk) {
            tg_load(ga, smb, ci + 1, (ci + 1) & 1, bm, bn, tid, segbase);
            asm volatile("cp.async.wait_group 1;" ::: "memory");
        } else {
            asm volatile("cp.async.wait_group 0;" ::: "memory");
        }
        __syncthreads();

        const uint32_t abase = smb + (ci & 1) * 32768;
        const uint32_t bbase = abase + 16384;
#pragma unroll
        for (int ks = 0; ks < 4; ++ks) {
            const int kc = ks * 2;
            uint32_t afr[2][4];
#pragma unroll
            for (int mt = 0; mt < 2; ++mt) {
                int row = mw + mt * 16 + ri + (quad & 1) * 8;
                int ch = (kc + (quad >> 1)) ^ (row & 7);
                ldmatrix_x4(afr[mt], abase + row * 128 + ch * 16);
            }
#pragma unroll
            for (int np = 0; np < 4; ++np) {
                uint32_t bfr[4];
                int nrow = nw + np * 16 + ri + (quad >> 1) * 8;
                int ch = (kc + (quad & 1)) ^ (nrow & 7);
                ldmatrix_x4(bfr, bbase + nrow * 128 + ch * 16);
#pragma unroll
                for (int mt = 0; mt < 2; ++mt) {
                    mma_bf16(acc[mt][np * 2],     afr[mt], bfr[0], bfr[1]);
                    mma_bf16(acc[mt][np * 2 + 1], afr[mt], bfr[2], bfr[3]);
                }
            }
        }
        __syncthreads();
    }

    // raw partial store (no bias/act)
#pragma unroll
    for (int mt = 0; mt < 2; ++mt) {
#pragma unroll
        for (int nt = 0; nt < 8; ++nt) {
            int col = bn + nw + nt * 8 + (lane & 3) * 2;
            if (col >= ga.N) continue;
#pragma unroll
            for (int h = 0; h < 2; ++h) {
                int row = bm + mw + mt * 16 + (lane >> 2) + h * 8;
                if (row >= ga.M) continue;
#pragma unroll
                for (int q = 0; q < 2; ++q) {
                    int c = col + q;
                    Cp[(size_t)row * 128 + c] = acc[mt][nt][h * 2 + q];
                }
            }
        }
    }
}

__global__ void c1red_kernel(const float* __restrict__ c1b) {
    const long n = (long)AOROWS * 128;
    for (long i = blockIdx.x * (long)blockDim.x + threadIdx.x; i < n;
         i += (long)gridDim.x * blockDim.x) {
        float v = g_c1p[i] + g_c1p[n + i] + c1b[(int)(i & 127)];
        g_c1o[i] = (v >= 0.f) ? v : 0.2f * v;
    }
}

// ================= embed GEMM: fp16 split-2, drained every 4 chunks =================
struct SegH { const __half* A; const __half* B; int shift; float scale; };
struct HArgs { SegH segs[9]; const float* bias; float* C; };

__device__ __forceinline__ void tg_load_h(const HArgs& ha, uint32_t smb, int ci, int p,
                                          int bm, int bn, int tid) {
    const SegH s = ha.segs[ci >> 5];
    const int k0 = (ci & 31) * 64;
    const uint32_t abase = smb + p * 32768;
    const uint32_t bbase = abase + 16384;
#pragma unroll
    for (int g = 0; g < 2; ++g) {
        int id = tid + g * 512;
        int row = id >> 3, c = id & 7;
        uint32_t soff = row * 128 + ((c ^ (row & 7)) * 16);
        {
            int m = bm + row;
            const void* src = s.A;
            int sz = 0;
            if (m < M_EMB) {
                int t = m % Tn;
                int ts = t + s.shift;
                if (ts >= 0 && ts < Tn) { src = s.A + (size_t)(m + s.shift) * 2048 + k0 + c * 8; sz = 16; }
            }
            cp_async16(abase + soff, src, sz);
        }
        {
            int n = bn + row;    // N = 2048, always in range
            cp_async16(bbase + soff, s.B + (size_t)n * 2048 + k0 + c * 8, 16);
        }
    }
    asm volatile("cp.async.commit_group;" ::: "memory");
}

__global__ void __launch_bounds__(512) tgemm_emb(HArgs ha) {
    extern __shared__ char gsm[];
    const uint32_t smb = smem_to_u32(gsm);
    const int tid = threadIdx.x;
    const int wid = tid >> 5, lane = tid & 31;
    const int bm = blockIdx.y * 128;
    const int bn = blockIdx.x * 128;
    const int mw = (wid & 3) * 32;
    const int nw = (wid >> 2) * 32;
    const int nchunk = 9 * 32;

    float sum[2][4][4];
    float acc[2][4][4];
#pragma unroll
    for (int i = 0; i < 2; ++i)
#pragma unroll
        for (int j = 0; j < 4; ++j)
#pragma unroll
            for (int q = 0; q < 4; ++q) sum[i][j][q] = 0.f;

    tg_load_h(ha, smb, 0, 0, bm, bn, tid);

    const int quad = lane >> 3, ri = lane & 7;

    for (int ci = 0; ci < nchunk; ++ci) {
        if (ci + 1 < nchunk) {
            tg_load_h(ha, smb, ci + 1, (ci + 1) & 1, bm, bn, tid);
            asm volatile("cp.async.wait_group 1;" ::: "memory");
        } else {
            asm volatile("cp.async.wait_group 0;" ::: "memory");
        }
        __syncthreads();

        const uint32_t abase = smb + (ci & 1) * 32768;
        const uint32_t bbase = abase + 16384;
        const bool fresh = ((ci & 3) == 0);
#pragma unroll
        for (int ks = 0; ks < 4; ++ks) {
            const int kc = ks * 2;
            uint32_t afr[2][4];
#pragma unroll
            for (int mt = 0; mt < 2; ++mt) {
                int row = mw + mt * 16 + ri + (quad & 1) * 8;
                int ch = (kc + (quad >> 1)) ^ (row & 7);
                ldmatrix_x4(afr[mt], abase + row * 128 + ch * 16);
            }
#pragma unroll
            for (int bt = 0; bt < 2; ++bt) {
                uint32_t bfr[4];
                int nrow = nw + bt * 16 + ri + (quad >> 1) * 8;
                int ch = (kc + (quad & 1)) ^ (nrow & 7);
                ldmatrix_x4(bfr, bbase + nrow * 128 + ch * 16);
#pragma unroll
                for (int mt = 0; mt < 2; ++mt) {
                    if (fresh && ks == 0) {
                        mma_f16_z(acc[mt][bt * 2],     afr[mt], bfr[0], bfr[1]);
                        mma_f16_z(acc[mt][bt * 2 + 1], afr[mt], bfr[2], bfr[3]);
                    } else {
                        mma_f16(acc[mt][bt * 2],     afr[mt], bfr[0], bfr[1]);
                        mma_f16(acc[mt][bt * 2 + 1], afr[mt], bfr[2], bfr[3]);
                    }
                }
            }
        }
        // drain every 4 chunks (chain-16): RN adds bound RZ-chain bias at ~2e-6
        // while keeping drain FFMA issue cost low. Segment (32-chunk) boundaries
        // are multiples of 4, so each drain group has one scale.
        if ((ci & 3) == 3) {
            const float scl = ha.segs[ci >> 5].scale;
#pragma unroll
            for (int i = 0; i < 2; ++i)
#pragma unroll
                for (int j = 0; j < 4; ++j)
#pragma unroll
                    for (int q = 0; q < 4; ++q) sum[i][j][q] += acc[i][j][q] * scl;
        }
        __syncthreads();
    }

#pragma unroll
    for (int mt = 0; mt < 2; ++mt) {
#pragma unroll
        for (int nt = 0; nt < 4; ++nt) {
            int col = bn + nw + nt * 8 + (lane & 3) * 2;
#pragma unroll
            for (int h = 0; h < 2; ++h) {
                int row = bm + mw + mt * 16 + (lane >> 2) + h * 8;
                if (row >= M_EMB) continue;
#pragma unroll
                for (int q = 0; q < 2; ++q) {
                    int c = col + q;
                    float v = sum[mt][nt][h * 2 + q] + ha.bias[c];
                    ha.C[(size_t)row * Fd + c] = fmaxf(v, 0.f);
                }
            }
        }
    }
}

// ================= split kernels =================
#define RSCALE 2048.f
__global__ void split2h_x(const float* __restrict__ s, __half* h, __half* l, long n) {
    for (long i = blockIdx.x * (long)blockDim.x + threadIdx.x; i < n;
         i += (long)gridDim.x * blockDim.x) {
        float x = s[i];
        __half a = __float2half(x);
        h[i] = a; l[i] = __float2half((x - __half2float(a)) * RSCALE);
    }
}
__global__ void split2h_wk(const float* __restrict__ w, __half* h, __half* l) {
    const long n = 3L * Fd * Fd;
    for (long i = blockIdx.x * (long)blockDim.x + threadIdx.x; i < n;
         i += (long)gridDim.x * blockDim.x) {
        long sh = i / ((long)Fd * Fd);
        long rem = i - sh * (long)Fd * Fd;
        float x = w[rem * 3 + sh];
        __half a = __float2half(x);
        h[i] = a; l[i] = __float2half((x - __half2float(a)) * RSCALE);
    }
}
__global__ void split2_kernel(const float* __restrict__ s, __nv_bfloat16* h,
                              __nv_bfloat16* l, long n) {
    for (long i = blockIdx.x * (long)blockDim.x + threadIdx.x; i < n;
         i += (long)gridDim.x * blockDim.x) {
        float x = s[i];
        __nv_bfloat16 a = __float2bfloat16(x);
        h[i] = a; l[i] = __float2bfloat16(x - __bfloat162float(a));
    }
}
__global__ void split2_c1w_kernel(const float* __restrict__ w, __nv_bfloat16* h,
                                  __nv_bfloat16* l) {
    const long n = 3L * 128 * Fd;
    for (long i = blockIdx.x * (long)blockDim.x + threadIdx.x; i < n;
         i += (long)gridDim.x * blockDim.x) {
        long sh = i / (128L * Fd);
        long rem = i - sh * 128L * Fd;
        float x = w[rem * 3 + sh];
        __nv_bfloat16 a = __float2bfloat16(x);
        h[i] = a; l[i] = __float2bfloat16(x - __bfloat162float(a));
    }
}

// ================= CAS + actionness =================
__global__ void __launch_bounds__(320) cas_kernel(const float* __restrict__ wcls,
                                                  float* __restrict__ dout)
{
    __shared__ float embs[5 * Fd];
    __shared__ float cres[5 * NC];
    const int b  = blockIdx.x / 150;
    const int t0 = (blockIdx.x % 150) * 5;
    const float* src = g_emb + ((size_t)b * Tn + t0) * Fd;
    for (int i = threadIdx.x; i < 5 * Fd; i += 320) embs[i] = src[i];
    __syncthreads();

    const int w = threadIdx.x >> 5, lane = threadIdx.x & 31;
    const int tl = w >> 1, cg = (w & 1) * 10;
    for (int c = cg; c < cg + 10; ++c) {
        float acc = 0.f;
        const float* wr = wcls + (size_t)c * Fd;
        const float* er = embs + tl * Fd;
        for (int e = lane; e < Fd; e += 32) acc += er[e] * wr[e];
#pragma unroll
        for (int off = 16; off; off >>= 1) acc += __shfl_down_sync(0xffffffffu, acc, off);
        if (lane == 0) cres[tl * NC + c] = fmaxf(acc, 0.f);
    }
    __syncthreads();

    if (threadIdx.x < 100) {
        int tl2 = threadIdx.x / NC, c2 = threadIdx.x % NC;
        dout[OUT_CAS + ((size_t)(b * Tn + t0 + tl2)) * NC + c2] = cres[tl2 * NC + c2];
    }
    if (threadIdx.x < 5) {
        float s = 0.f;
        for (int c = 0; c < NC; ++c) s += cres[threadIdx.x * NC + c];
        dout[OUT_ACT + b * Tn + t0 + threadIdx.x] = s;
    }
}

// ================= a2 =================
__global__ void a2_kernel(const float* __restrict__ tf1w, const float* __restrict__ tf1b,
                          const float* __restrict__ tf2w, const float* __restrict__ tf2b,
                          float* __restrict__ dout)
{
    __shared__ float a[Tn], a1[Tn];
    const int b = blockIdx.x;
    for (int t = threadIdx.x; t < Tn; t += blockDim.x) a[t] = dout[OUT_ACT + b*Tn + t];
    __syncthreads();
    for (int t = threadIdx.x; t < Tn; t += blockDim.x) {
        float v = tf1b[0];
#pragma unroll
        for (int k = 0; k < 3; ++k) { int tt = t+k-1; if (tt>=0 && tt<Tn) v += tf1w[k]*a[tt]; }
        a1[t] = fmaxf(v, 0.f);
    }
    __syncthreads();
    for (int t = threadIdx.x; t < Tn; t += blockDim.x) {
        float v = tf2b[0];
#pragma unroll
        for (int k = 0; k < 3; ++k) { int tt = t+k-1; if (tt>=0 && tt<Tn) v += tf2w[k]*a1[tt]; }
        dout[OUT_A2 + b*Tn + t] = fmaxf(v, 0.f);
    }
}

// ================= sorting =================
__device__ __forceinline__ unsigned int fkey(float v) {
    unsigned int b = __float_as_uint(v);
    return (b & 0x80000000u) ? ~b : (b | 0x80000000u);
}
__device__ __forceinline__ float fdec(unsigned int u) {
    unsigned int b = (u & 0x80000000u) ? (u ^ 0x80000000u) : ~u;
    return __uint_as_float(b);
}
__device__ void bitonic1024_u64(unsigned long long* key, int tid) {
    for (int k = 2; k <= 1024; k <<= 1)
        for (int j = k >> 1; j > 0; j >>= 1) {
            __syncthreads();
            for (int i = tid; i < 1024; i += 512) {
                int ixj = i ^ j;
                if (ixj > i) {
                    bool up = ((i & k) == 0);
                    unsigned long long a = key[i], b2 = key[ixj];
                    bool sw = up ? (a > b2) : (a < b2);
                    if (sw) { key[i] = b2; key[ixj] = a; }
                }
            }
        }
    __syncthreads();
}
__device__ void bitonic1024_u32(unsigned int* key, int tid) {
    for (int k = 2; k <= 1024; k <<= 1)
        for (int j = k >> 1; j > 0; j >>= 1) {
            __syncthreads();
            for (int i = tid; i < 1024; i += 512) {
                int ixj = i ^ j;
                if (ixj > i) {
                    bool up = ((i & k) == 0);
                    unsigned int a = key[i], b2 = key[ixj];
                    bool sw = up ? (a > b2) : (a < b2);
                    if (sw) { key[i] = b2; key[ixj] = a; }
                }
            }
        }
    __syncthreads();
}

__global__ void __launch_bounds__(512) sort_act_kernel(const float* __restrict__ dout) {
    __shared__ unsigned long long key[1024];
    const int b = blockIdx.x, tid = threadIdx.x;
    for (int i = tid; i < 1024; i += 512) {
        if (i < Tn) {
            unsigned int nu = ~fkey(dout[OUT_ACT + b*Tn + i]);
            key[i] = ((unsigned long long)nu << 32) | (unsigned int)i;
        } else key[i] = 0xFFFFFFFFFFFFFFFFull;
    }
    bitonic1024_u64(key, tid);
    for (int i = tid; i < 150; i += 512) g_idx[b*150 + i] = (int)(key[i] & 0xffffffffu);
    if (tid == 0) {
        float v0 = fdec(~(unsigned int)(key[374] >> 32));
        float v1 = fdec(~(unsigned int)(key[375] >> 32));
        g_med[b] = 0.5f * (v0 + v1);
    }
}

__global__ void morph_kernel(const float* __restrict__ dout) {
    __shared__ float a[Tn];
    __shared__ float bin[Tn];
    __shared__ float red[256];
    const int b = blockIdx.x, tid = threadIdx.x;
    float lmax = -FLT_MAX;
    for (int t = tid; t < Tn; t += 256) { float v = dout[OUT_ACT + b*Tn + t]; a[t] = v; lmax = fmaxf(lmax, v); }
    red[tid] = lmax; __syncthreads();
    for (int s = 128; s > 0; s >>= 1) { if (tid < s) red[tid] = fmaxf(red[tid], red[tid+s]); __syncthreads(); }
    float amax = red[0];
    float med = g_med[b];
    for (int t = tid; t < Tn; t += 256) bin[t] = (a[t] > med) ? 1.f : 0.f;
    __syncthreads();
    for (int t = tid; t < Tn; t += 256) {
        float e3 = 1.f, e6 = 1.f, d6 = 0.f, d3 = 0.f;
#pragma unroll
        for (int o = -1; o <= 1; ++o) { int u = t+o; float v = (u>=0&&u<Tn)?bin[u]:0.f; e3 = fminf(e3,v); d3 = fmaxf(d3,v); }
#pragma unroll
        for (int o = -3; o <= 2; ++o) { int u = t+o; float v = (u>=0&&u<Tn)?bin[u]:0.f; e6 = fminf(e6,v); }
#pragma unroll
        for (int o = -2; o <= 3; ++o) { int u = t+o; float v = (u>=0&&u<Tn)?bin[u]:0.f; d6 = fmaxf(d6,v); }
        g_sel[1*Bn*Tn + b*Tn + t] = amax - a[t];
        g_sel[2*Bn*Tn + b*Tn + t] = a[t] * (e3 - e6);
        g_sel[3*Bn*Tn + b*Tn + t] = a[t] * (d6 - d3);
    }
}

__global__ void __launch_bounds__(512) sort_gen_kernel() {
    __shared__ unsigned long long key[1024];
    const int aid = blockIdx.x / 16 + 1;
    const int b = blockIdx.x % 16;
    const int tid = threadIdx.x;
    const float* sc = g_sel + aid*Bn*Tn + b*Tn;
    const unsigned int msk = (aid == 1) ? 0xFFFFFFF8u : 0xFFFFFFFFu;
    for (int i = tid; i < 1024; i += 512) {
        if (i < Tn) {
            unsigned int nu = ~(fkey(sc[i]) & msk);
            key[i] = ((unsigned long long)nu << 32) | (unsigned int)i;
        } else key[i] = 0xFFFFFFFFFFFFFFFFull;
    }
    bitonic1024_u64(key, tid);
    if (aid == 1) { for (int i = tid; i < 150; i += 512) g_idx[2400 + b*150 + i] = (int)(key[i] & 0xffffffffu); }
    else if (aid == 2) { if (tid < 37) g_idx[4800 + b*37 + tid] = (int)(key[tid] & 0xffffffffu); }
    else { if (tid < 37) g_idx[5392 + b*37 + tid] = (int)(key[tid] & 0xffffffffu); }
}

__global__ void __launch_bounds__(256) gather_kernel(float* __restrict__ dout) {
    const int r = blockIdx.x; // 0..5983
    int b, j, srcidx, set = -1;
    float* dst;
    if (r < 2400) {
        b = r/150; j = r%150; srcidx = g_idx[b*150 + j];
        dst = dout + OUT_EA + (size_t)r * Fd;
        if (j < 148) set = j / 37;
    } else if (r < 4800) {
        int rr = r - 2400; b = rr/150; j = rr%150; srcidx = g_idx[2400 + b*150 + j];
        dst = dout + OUT_EB + (size_t)rr * Fd;
        if (j < 148) set = 4 + j / 37;
    } else if (r < 5392) {
        int rr = r - 4800; b = rr/37; j = rr%37; srcidx = g_idx[4800 + rr];
        dst = dout + OUT_HA + (size_t)rr * Fd; set = 8;
    } else {
        int rr = r - 5392; b = rr/37; j = rr%37; srcidx = g_idx[5392 + rr];
        dst = dout + OUT_HB + (size_t)rr * Fd; set = 9;
    }
    const float4* src = reinterpret_cast<const float4*>(g_emb + ((size_t)b*Tn + srcidx)*Fd);
    float4* d4 = reinterpret_cast<float4*>(dst);
    __nv_bfloat16* th = nullptr; __nv_bfloat16* tl = nullptr;
    if (set >= 0) {
        size_t tb = ((size_t)set*SROWS + b*37 + (j % 37))*Fd;
        th = g_tok2 + tb;
        tl = g_tok2 + (size_t)TOKROWS*Fd + tb;
    }
    for (int i = threadIdx.x; i < Fd/4; i += 256) {
        float4 v = src[i];
        d4[i] = v;
        if (th) {
            float vv[4] = {v.x, v.y, v.z, v.w};
#pragma unroll
            for (int q = 0; q < 4; ++q) {
                __nv_bfloat16 h = __float2bfloat16(vv[q]);
                th[i*4 + q] = h;
                tl[i*4 + q] = __float2bfloat16(vv[q] - __bfloat162float(h));
            }
        }
    }
}

// ================= attention (writes aopre split-2 planes) =================
__global__ void __launch_bounds__(256) attn_kernel() {
    __shared__ float qt[37*64];
    __shared__ float kt[37*64];
    __shared__ float s[37*37];
    const int id = blockIdx.x;
    const int h = id & 3, b = (id >> 2) & 15, m = id >> 6;
    const int rh = m >> 1, role = m & 1;
    const int as = d_aset[rh], bs = d_bset[rh];
    const int qset = role ? as : bs;
    const int kvset = role ? bs : as;
    const int trowbase = role ? 37 : 0;
    const int tid = threadIdx.x;
    const float scale = 0.044194173824159216f; // 1/sqrt(512)

    const float* Qb = g_qkv + ((size_t)(qset*SROWS + b*37)) * K6 + h*512;
    const float* Kb = g_qkv + ((size_t)(kvset*SROWS + b*37)) * K6 + 2048 + h*512;
    const float* Vb = g_qkv + ((size_t)(kvset*SROWS + b*37)) * K6 + 4096 + h*512;

    for (int i = tid; i < 1369; i += 256) s[i] = 0.f;
    for (int dt = 0; dt < 8; ++dt) {
        __syncthreads();
        for (int i = tid; i < 2368; i += 256) {
            int q = i >> 6, d = i & 63;
            qt[i] = Qb[(size_t)q*K6 + dt*64 + d];
            kt[i] = Kb[(size_t)q*K6 + dt*64 + d];
        }
        __syncthreads();
        for (int p = tid; p < 1369; p += 256) {
            int q = p / 37, k = p % 37;
            const float* qr = qt + q*64;
            const float* kr = kt + k*64;
            float acc = 0.f;
#pragma unroll
            for (int d = 0; d < 64; ++d) acc += qr[d] * kr[d];
            s[p] += acc;
        }
    }
    __syncthreads();
    {
        const int w = tid >> 5, lane = tid & 31;
        for (int r = w; r < 37; r += 8) {
            float sv0 = s[r*37 + lane] * scale;
            float sv1 = (lane < 5) ? s[r*37 + 32 + lane] * scale : -FLT_MAX;
            float mx = fmaxf(sv0, sv1);
#pragma unroll
            for (int off = 16; off; off >>= 1) mx = fmaxf(mx, __shfl_xor_sync(0xffffffffu, mx, off));
            float e0 = expf(sv0 - mx);
            float e1 = (lane < 5) ? expf(sv1 - mx) : 0.f;
            float sum = e0 + e1;
#pragma unroll
            for (int off = 16; off; off >>= 1) sum += __shfl_xor_sync(0xffffffffu, sum, off);
            float inv = 1.f / sum;
            s[r*37 + lane] = e0 * inv;
            if (lane < 5) s[r*37 + 32 + lane] = e1 * inv;
        }
    }
    const size_t rowbase = (size_t)(rh*1184 + b*74 + trowbase);
    for (int dt = 0; dt < 8; ++dt) {
        __syncthreads();
        for (int i = tid; i < 2368; i += 256) {
            int k = i >> 6, d = i & 63;
            kt[i] = Vb[(size_t)k*K6 + dt*64 + d];
        }
        __syncthreads();
        for (int p = tid; p < 2368; p += 256) {
            int q = p >> 6, d = p & 63;
            const float* sr = s + q*37;
            float acc = 0.f;
#pragma unroll
            for (int k = 0; k < 37; ++k) acc += sr[k] * kt[k*64 + d];
            size_t off = (rowbase + q)*Fd + h*512 + dt*64 + d;
            __nv_bfloat16 hh = __float2bfloat16(acc);
            g_aop2[off] = hh;
            g_aop2[(size_t)AOROWS*Fd + off] = __float2bfloat16(acc - __bfloat162float(hh));
        }
    }
}

// ================= c2 + l1 + l2 fused =================
__global__ void __launch_bounds__(256) tail_kernel(
    const float* __restrict__ c2w, const float* __restrict__ c2b,
    const float* __restrict__ l1w, const float* __restrict__ l1b,
    const float* __restrict__ l2w, const float* __restrict__ l2b,
    float* __restrict__ dout)
{
    __shared__ float sm[74*128];
    const int rb = blockIdx.x;
    const int tid = threadIdx.x;
    for (int i = tid; i < 74*128; i += 256)
        sm[i] = g_c1o[(size_t)rb*74*128 + i];
    __syncthreads();

    const int o = tid & 31;
    const int tbase = tid >> 5;
    float r[10];
    int nt = 0;
    for (int t = tbase; t < 74; t += 8) {
        float v = c2b[o];
#pragma unroll
        for (int k = 0; k < 3; ++k) {
            int tt = t + k - 1;
            if (tt >= 0 && tt < 74) {
                const float* row = sm + tt*128;
                const float* w = c2w + o*384 + k;
#pragma unroll 16
                for (int c = 0; c < 128; ++c) v += row[c] * w[c*3];
            }
        }
        r[nt++] = (v >= 0.f) ? v : 0.2f * v;
    }
    __syncthreads();
    { int i = 0; for (int t = tbase; t < 74; t += 8) sm[o*74 + t] = r[i++]; }
    __syncthreads();

    for (int p = tid; p < 320; p += 256) {
        int c = p / 10, j = p % 10;
        float v = l1b[j];
        const float* y = sm + c*74;
        const float* w = l1w + j*74;
        for (int t = 0; t < 74; ++t) v += y[t] * w[t];
        sm[2368 + p] = (v >= 0.f) ? v : 0.2f * v;
    }
    __syncthreads();
    float ps = 0.f;
    for (int p = tid; p < 320; p += 256) ps += sm[2368 + p] * l2w[p];
    sm[3000 + tid] = ps;
    __syncthreads();
    for (int s = 128; s > 0; s >>= 1) { if (tid < s) sm[3000+tid] += sm[3000+tid+s]; __syncthreads(); }
    if (tid == 0) {
        float x = sm[3000] + l2b[0];
        dout[OUT_RH + rb] = 1.f / (1.f + expf(-x));
    }
}

// ================= video scores =================
__global__ void __launch_bounds__(512) vsort_kernel(const float* __restrict__ dout) {
    __shared__ unsigned int key[1024];
    const int bc = blockIdx.x;
    const int b = bc / NC, c = bc % NC;
    const int tid = threadIdx.x;
    for (int i = tid; i < 1024; i += 512)
        key[i] = (i < Tn) ? ~fkey(dout[OUT_CAS + (size_t)(b*Tn + i)*NC + c]) : 0xFFFFFFFFu;
    bitonic1024_u32(key, tid);
    if (tid == 0) {
        float s = 0.f;
        for (int i = 0; i < 150; ++i) s += fdec(~key[i]);
        g_vmean[bc] = s / 150.f;
    }
}
__global__ void vsoftmax_kernel(float* __restrict__ dout) {
    const int b = blockIdx.x, t = threadIdx.x;
    float v = (t < NC) ? g_vmean[b*NC + t] : -FLT_MAX;
    float mx = v;
#pragma unroll
    for (int off = 16; off; off >>= 1) mx = fmaxf(mx, __shfl_xor_sync(0xffffffffu, mx, off));
    float e = (t < NC) ? expf(v - mx) : 0.f;
    float sum = e;
#pragma unroll
    for (int off = 16; off; off >>= 1) sum += __shfl_xor_sync(0xffffffffu, sum, off);
    if (t < NC) dout[OUT_VS + b*NC + t] = e / sum;
}

// ================= launch =================
extern "C" void kernel_launch(void* const* d_in, const int* in_sizes, int n_in,
                              void* d_out, int out_size) {
    const float* x    = (const float*)d_in[0];
    const float* wemb = (const float*)d_in[1];
    const float* bemb = (const float*)d_in[2];
    const float* wcls = (const float*)d_in[3];
    const float* tf1w = (const float*)d_in[4];
    const float* tf1b = (const float*)d_in[5];
    const float* tf2w = (const float*)d_in[6];
    const float* tf2b = (const float*)d_in[7];
    const float* inw  = (const float*)d_in[8];
    const float* inb  = (const float*)d_in[9];
    const float* outw = (const float*)d_in[10];
    const float* outb = (const float*)d_in[11];
    const float* c1w  = (const float*)d_in[12];
    const float* c1b  = (const float*)d_in[13];
    const float* c2w  = (const float*)d_in[14];
    const float* c2b  = (const float*)d_in[15];
    const float* l1w  = (const float*)d_in[16];
    const float* l1b  = (const float*)d_in[17];
    const float* l2w  = (const float*)d_in[18];
    const float* l2b  = (const float*)d_in[19];
    float* dout = (float*)d_out;

    float *p_emb, *p_qkv, *p_c1o, *p_c1p;
    __half *p_xh, *p_wkh;
    __nv_bfloat16 *p_tok2, *p_inw2, *p_aop2, *p_outw2, *p_ao2, *p_c1w2;
    cudaGetSymbolAddress((void**)&p_emb,  g_emb);
    cudaGetSymbolAddress((void**)&p_qkv,  g_qkv);
    cudaGetSymbolAddress((void**)&p_c1o,  g_c1o);
    cudaGetSymbolAddress((void**)&p_c1p,  g_c1p);
    cudaGetSymbolAddress((void**)&p_xh,   g_xh);
    cudaGetSymbolAddress((void**)&p_wkh,  g_wkh);
    cudaGetSymbolAddress((void**)&p_tok2, g_tok2);
    cudaGetSymbolAddress((void**)&p_inw2, g_inw2);
    cudaGetSymbolAddress((void**)&p_aop2, g_aop2);
    cudaGetSymbolAddress((void**)&p_outw2,g_outw2);
    cudaGetSymbolAddress((void**)&p_c1w2, g_c1w2);
    cudaGetSymbolAddress((void**)&p_ao2,  g_ao2);

    cudaFuncSetAttribute(tgemm, cudaFuncAttributeMaxDynamicSharedMemorySize, TG_SMEM);
    cudaFuncSetAttribute(tgemm_c1, cudaFuncAttributeMaxDynamicSharedMemorySize, TG_SMEM);
    cudaFuncSetAttribute(tgemm_emb, cudaFuncAttributeMaxDynamicSharedMemorySize, TG_SMEM);

    const size_t XP   = (size_t)M_EMB * Fd;
    const size_t WKP  = (size_t)3 * Fd * Fd;
    const size_t TOKP = (size_t)TOKROWS * Fd;
    const size_t INWP = (size_t)K6 * Fd;
    const size_t AOP  = (size_t)AOROWS * Fd;
    const size_t OWP  = (size_t)Fd * Fd;
    const size_t C1P  = (size_t)3 * 128 * Fd;

    // splits
    split2h_x<<<2048, 256>>>(x, p_xh, p_xh + XP, (long)XP);
    split2h_wk<<<2048, 256>>>(wemb, p_wkh, p_wkh + WKP);
    split2_kernel<<<2048, 256>>>(inw, p_inw2, p_inw2 + INWP, (long)INWP);
    split2_kernel<<<1024, 256>>>(outw, p_outw2, p_outw2 + OWP, (long)OWP);
    split2_c1w_kernel<<<256, 256>>>(c1w, p_c1w2, p_c1w2 + C1P);

    // embed conv GEMM: fp16 split-2 {hh, hl, lh} x 3 shifts, drained every 4 chunks
    {
        HArgs ha = {};
        const float S = 1.f / RSCALE;
        const int pa[3] = {0, 0, 1};
        const int pb[3] = {0, 1, 0};
        const float ps[3] = {1.f, S, S};
        int q = 0;
        for (int sh = 0; sh < 3; ++sh)
            for (int pr = 0; pr < 3; ++pr) {
                ha.segs[q].A = p_xh + (size_t)pa[pr] * XP;
                ha.segs[q].B = p_wkh + (size_t)pb[pr] * WKP + (size_t)sh * Fd * Fd;
                ha.segs[q].shift = sh - 1;
                ha.segs[q].scale = ps[pr];
                ++q;
            }
        ha.bias = bemb; ha.C = p_emb;
        tgemm_emb<<<dim3(Fd/128, (M_EMB + 127)/128), 512, TG_SMEM>>>(ha);
    }

    cas_kernel<<<Bn*150, 320>>>(wcls, dout);
    a2_kernel<<<Bn, 256>>>(tf1w, tf1b, tf2w, tf2b, dout);
    sort_act_kernel<<<Bn, 512>>>(dout);
    morph_kernel<<<Bn, 256>>>(dout);
    sort_gen_kernel<<<48, 512>>>();
    gather_kernel<<<5984, 256>>>(dout);

    // QKV GEMM: bf16 split-2 x 3 products (undrained, proven fast)
    {
        GArgs ga = {};
        const int pa[3] = {0,0,1}, pb[3] = {0,1,0};
        for (int pr = 0; pr < 3; ++pr) {
            ga.segs[pr].A = p_tok2 + (size_t)pa[pr]*TOKP;
            ga.segs[pr].B = p_inw2 + (size_t)pb[pr]*INWP;
            ga.segs[pr].shift = 0;
        }
        ga.nseg = 3; ga.M = TOKROWS; ga.N = K6; ga.Tper = 0;
        ga.C = p_qkv; ga.bias = inb; ga.act = 0; ga.ldc = K6;
        tgemm<<<dim3(K6/128, (TOKROWS+127)/128), 256, TG_SMEM>>>(ga);
    }

    attn_kernel<<<1536, 256>>>();

    // out-proj GEMM: bf16 split-2, epilogue writes split-2 planes
    {
        GArgs ga = {};
        const int pa[3] = {0,0,1}, pb[3] = {0,1,0};
        for (int pr = 0; pr < 3; ++pr) {
            ga.segs[pr].A = p_aop2 + (size_t)pa[pr]*AOP;
            ga.segs[pr].B = p_outw2 + (size_t)pb[pr]*OWP;
            ga.segs[pr].shift = 0;
        }
        ga.nseg = 3; ga.M = AOROWS; ga.N = Fd; ga.Tper = 0;
        ga.C = nullptr; ga.bias = outb; ga.act = 0; ga.ldc = Fd;
        ga.So_h = p_ao2; ga.So_l = p_ao2 + AOP;
        tgemm<<<dim3(Fd/128, AOROWS/128), 256, TG_SMEM>>>(ga);
    }

    // c1 conv GEMM: bf16 split-2 x 3 products x 3 shifts, N=128 — split-K across
    // 2 grid-x parts (segs 0-4 / 5-8) into raw partials, then combine.
    {
        GArgs ga = {};
        const int pa[3] = {0,0,1}, pb[3] = {0,1,0};
        int q = 0;
        for (int sh = 0; sh < 3; ++sh)
            for (int pr = 0; pr < 3; ++pr) {
                ga.segs[q].A = p_ao2 + (size_t)pa[pr]*AOP;
                ga.segs[q].B = p_c1w2 + (size_t)pb[pr]*C1P + (size_t)sh*128*Fd;
                ga.segs[q].shift = sh - 1;
                ++q;
            }
        ga.nseg = 9; ga.M = AOROWS; ga.N = 128; ga.Tper = 74;
        ga.C = p_c1p; ga.bias = nullptr; ga.act = 0; ga.ldc = 128;
        tgemm_c1<<<dim3(2, AOROWS/128), 256, TG_SMEM>>>(ga);
        c1red_kernel<<<2048, 256>>>(c1b);
    }

    tail_kernel<<<192, 256>>>(c2w, c2b, l1w, l1b, l2w, l2b, dout);
    vsort_kernel<<<Bn*NC, 512>>>(dout);
    vsoftmax_kernel<<<Bn, 32>>>(dout);
}

// round 17
// speedup vs baseline: 1.8082x; 1.0008x over previous
#include <cuda_runtime.h>
#include <cuda_bf16.h>
#include <cuda_fp16.h>
#include <math.h>
#include <float.h>
#include <stdint.h>

#define Bn 16
#define Tn 750
#define Fd 2048
#define NC 20
#define K6 6144
#define M_EMB 12000
#define SROWS 592
#define TOKROWS 5920
#define AOROWS 14208

#define OUT_VS   0
#define OUT_ACT  320
#define OUT_A2   12320
#define OUT_CAS  24320
#define OUT_RH   264320
#define OUT_EA   264512
#define OUT_EB   5179712
#define OUT_HA   10094912
#define OUT_HB   11307328

// ---------------- scratch (device globals) ----------------
__device__ float g_emb [(size_t)M_EMB * Fd];
__device__ float g_qkv [(size_t)TOKROWS * K6];
__device__ float g_c1o [(size_t)AOROWS * 128];
__device__ float g_c1p [2 * (size_t)AOROWS * 128];   // split-K partials
__device__ float g_sel [4 * Bn * Tn];
__device__ int   g_idx [5984];
__device__ float g_vmean[Bn * NC];

// fp16 split-2 planes for embed GEMM
__device__ __half g_xh  [2 * (size_t)M_EMB * Fd];          // x: h, l(*2048)
__device__ __half g_wkh [2 * (size_t)3 * Fd * Fd];         // w_embed: [split][sh][o][e]

// bf16 split-2 planes for trio GEMMs
__device__ __nv_bfloat16 g_tok2 [2 * (size_t)TOKROWS * Fd];
__device__ __nv_bfloat16 g_inw2 [2 * (size_t)K6 * Fd];
__device__ __nv_bfloat16 g_aop2 [2 * (size_t)AOROWS * Fd];
__device__ __nv_bfloat16 g_outw2[2 * (size_t)Fd * Fd];
__device__ __nv_bfloat16 g_ao2  [2 * (size_t)AOROWS * Fd];
__device__ __nv_bfloat16 g_c1w2 [2 * (size_t)3 * 128 * Fd];

__device__ __constant__ int d_aset[12] = {1,3,0,5,7,4,9,3,8,3,6,2};
__device__ __constant__ int d_bset[12] = {8,2,3,9,6,7,8,9,7,7,3,7};

// ================= MMA helpers (sm_80+ base features) =================
__device__ __forceinline__ uint32_t smem_to_u32(const void* p) {
    uint32_t a;
    asm("{ .reg .u64 t; cvta.to.shared.u64 t, %1; cvt.u32.u64 %0, t; }" : "=r"(a) : "l"(p));
    return a;
}
__device__ __forceinline__ void ldmatrix_x4(uint32_t* r, uint32_t addr) {
    asm volatile("ldmatrix.sync.aligned.m8n8.x4.shared.b16 {%0,%1,%2,%3}, [%4];"
        : "=r"(r[0]), "=r"(r[1]), "=r"(r[2]), "=r"(r[3]) : "r"(addr));
}
__device__ __forceinline__ void mma_bf16(float* d, const uint32_t* a, uint32_t b0, uint32_t b1) {
    asm volatile("mma.sync.aligned.m16n8k16.row.col.f32.bf16.bf16.f32 "
        "{%0,%1,%2,%3}, {%4,%5,%6,%7}, {%8,%9}, {%0,%1,%2,%3};"
        : "+f"(d[0]), "+f"(d[1]), "+f"(d[2]), "+f"(d[3])
        : "r"(a[0]), "r"(a[1]), "r"(a[2]), "r"(a[3]), "r"(b0), "r"(b1));
}
__device__ __forceinline__ void mma_f16(float* d, const uint32_t* a, uint32_t b0, uint32_t b1) {
    asm volatile("mma.sync.aligned.m16n8k16.row.col.f32.f16.f16.f32 "
        "{%0,%1,%2,%3}, {%4,%5,%6,%7}, {%8,%9}, {%0,%1,%2,%3};"
        : "+f"(d[0]), "+f"(d[1]), "+f"(d[2]), "+f"(d[3])
        : "r"(a[0]), "r"(a[1]), "r"(a[2]), "r"(a[3]), "r"(b0), "r"(b1));
}
__device__ __forceinline__ void mma_f16_z(float* d, const uint32_t* a, uint32_t b0, uint32_t b1) {
    asm volatile("mma.sync.aligned.m16n8k16.row.col.f32.f16.f16.f32 "
        "{%0,%1,%2,%3}, {%4,%5,%6,%7}, {%8,%9}, {%10,%11,%12,%13};"
        : "=f"(d[0]), "=f"(d[1]), "=f"(d[2]), "=f"(d[3])
        : "r"(a[0]), "r"(a[1]), "r"(a[2]), "r"(a[3]), "r"(b0), "r"(b1),
          "f"(0.f), "f"(0.f), "f"(0.f), "f"(0.f));
}
__device__ __forceinline__ void cp_async16(uint32_t dst, const void* src, int srcsize) {
    asm volatile("cp.async.ca.shared.global [%0], [%1], 16, %2;"
        :: "r"(dst), "l"(src), "r"(srcsize));
}

// ================= trio GEMM: bf16, undrained (R6/R9-proven) =================
struct Seg { const __nv_bfloat16* A; const __nv_bfloat16* B; int shift; };
struct GArgs {
    Seg segs[9];
    int nseg, M, N, Tper, act, ldc;
    float* C; const float* bias;
    __nv_bfloat16* So_h; __nv_bfloat16* So_l;
};

#define TG_SMEM 65536

__device__ __forceinline__ void tg_load(const GArgs& ga, uint32_t smb, int ci, int p,
                                        int bm, int bn, int tid, int segbase) {
    const Seg s = ga.segs[segbase + (ci >> 5)];
    const int k0 = (ci & 31) * 64;
    const uint32_t abase = smb + p * 32768;
    const uint32_t bbase = abase + 16384;
#pragma unroll
    for (int g = 0; g < 4; ++g) {
        int id = tid + g * 256;
        int row = id >> 3, c = id & 7;
        uint32_t soff = row * 128 + ((c ^ (row & 7)) * 16);
        {
            int m = bm + row;
            const void* src = s.A;
            int sz = 0;
            if (m < ga.M) {
                int srow = m;
                bool ok = true;
                if (ga.Tper) {
                    int t = m % ga.Tper; int ts = t + s.shift;
                    ok = (ts >= 0 && ts < ga.Tper);
                    srow = m + s.shift;
                }
                if (ok) { src = s.A + (size_t)srow * 2048 + k0 + c * 8; sz = 16; }
            }
            cp_async16(abase + soff, src, sz);
        }
        {
            int n = bn + row;
            const void* src = s.B;
            int sz = 0;
            if (n < ga.N) { src = s.B + (size_t)n * 2048 + k0 + c * 8; sz = 16; }
            cp_async16(bbase + soff, src, sz);
        }
    }
    asm volatile("cp.async.commit_group;" ::: "memory");
}

__global__ void __launch_bounds__(256) tgemm(GArgs ga) {
    extern __shared__ char gsm[];
    const uint32_t smb = smem_to_u32(gsm);
    const int tid = threadIdx.x;
    const int wid = tid >> 5, lane = tid & 31;
    const int bm = blockIdx.y * 128;
    const int bn = blockIdx.x * 128;
    const int mw = (wid & 3) * 32;
    const int nw = (wid >> 2) * 64;
    const int nchunk = ga.nseg * 32;

    float acc[2][8][4];
#pragma unroll
    for (int i = 0; i < 2; ++i)
#pragma unroll
        for (int j = 0; j < 8; ++j)
#pragma unroll
            for (int q = 0; q < 4; ++q) acc[i][j][q] = 0.f;

    tg_load(ga, smb, 0, 0, bm, bn, tid, 0);

    const int quad = lane >> 3, ri = lane & 7;

    for (int ci = 0; ci < nchunk; ++ci) {
        if (ci + 1 < nchunk) {
            tg_load(ga, smb, ci + 1, (ci + 1) & 1, bm, bn, tid, 0);
            asm volatile("cp.async.wait_group 1;" ::: "memory");
        } else {
            asm volatile("cp.async.wait_group 0;" ::: "memory");
        }
        __syncthreads();

        const uint32_t abase = smb + (ci & 1) * 32768;
        const uint32_t bbase = abase + 16384;
#pragma unroll
        for (int ks = 0; ks < 4; ++ks) {
            const int kc = ks * 2;
            uint32_t afr[2][4];
#pragma unroll
            for (int mt = 0; mt < 2; ++mt) {
                int row = mw + mt * 16 + ri + (quad & 1) * 8;
                int ch = (kc + (quad >> 1)) ^ (row & 7);
                ldmatrix_x4(afr[mt], abase + row * 128 + ch * 16);
            }
#pragma unroll
            for (int np = 0; np < 4; ++np) {
                uint32_t bfr[4];
                int nrow = nw + np * 16 + ri + (quad >> 1) * 8;
                int ch = (kc + (quad & 1)) ^ (nrow & 7);
                ldmatrix_x4(bfr, bbase + nrow * 128 + ch * 16);
#pragma unroll
                for (int mt = 0; mt < 2; ++mt) {
                    mma_bf16(acc[mt][np * 2],     afr[mt], bfr[0], bfr[1]);
                    mma_bf16(acc[mt][np * 2 + 1], afr[mt], bfr[2], bfr[3]);
                }
            }
        }
        __syncthreads();
    }

#pragma unroll
    for (int mt = 0; mt < 2; ++mt) {
#pragma unroll
        for (int nt = 0; nt < 8; ++nt) {
            int col = bn + nw + nt * 8 + (lane & 3) * 2;
            if (col >= ga.N) continue;
#pragma unroll
            for (int h = 0; h < 2; ++h) {
                int row = bm + mw + mt * 16 + (lane >> 2) + h * 8;
                if (row >= ga.M) continue;
#pragma unroll
                for (int q = 0; q < 2; ++q) {
                    int c = col + q;
                    float v = acc[mt][nt][h * 2 + q];
                    if (ga.bias) v += ga.bias[c];
                    if (ga.act == 1) v = fmaxf(v, 0.f);
                    else if (ga.act == 2) v = (v >= 0.f) ? v : 0.2f * v;
                    size_t off = (size_t)row * ga.ldc + c;
                    if (ga.C) ga.C[off] = v;
                    if (ga.So_h) {
                        __nv_bfloat16 hh = __float2bfloat16(v);
                        ga.So_h[off] = hh;
                        ga.So_l[off] = __float2bfloat16(v - __bfloat162float(hh));
                    }
                }
            }
        }
    }
}

// ===== c1 split-K variant: grid (2, 111); part 0 = segs 0-4, part 1 = segs 5-8.
// Writes raw fp32 partials to g_c1p; c1red_kernel combines + bias + leaky. =====
__global__ void __launch_bounds__(256) tgemm_c1(GArgs ga) {
    extern __shared__ char gsm[];
    const uint32_t smb = smem_to_u32(gsm);
    const int tid = threadIdx.x;
    const int wid = tid >> 5, lane = tid & 31;
    const int part = blockIdx.x;                 // 0 or 1
    const int bm = blockIdx.y * 128;
    const int bn = 0;
    const int mw = (wid & 3) * 32;
    const int nw = (wid >> 2) * 64;
    const int segbase = part ? 5 : 0;
    const int nchunk = (part ? 4 : 5) * 32;
    float* Cp = ga.C + (size_t)part * AOROWS * 128;

    float acc[2][8][4];
#pragma unroll
    for (int i = 0; i < 2; ++i)
#pragma unroll
        for (int j = 0; j < 8; ++j)
#pragma unroll
            for (int q = 0; q < 4; ++q) acc[i][j][q] = 0.f;

    tg_load(ga, smb, 0, 0, bm, bn, tid, segbase);

    const int quad = lane >> 3, ri = lane & 7;

    for (int ci = 0; ci < nchunk; ++ci) {
        if (ci + 1 < nchunk) {
            tg_load(ga, smb, ci + 1, (ci + 1) & 1, bm, bn, tid, segbase);
            asm volatile("cp.async.wait_group 1;" ::: "memory");
        } else {
            asm volatile("cp.async.wait_group 0;" ::: "memory");
        }
        __syncthreads();

        const uint32_t abase = smb + (ci & 1) * 32768;
        const uint32_t bbase = abase + 16384;
#pragma unroll
        for (int ks = 0; ks < 4; ++ks) {
            const int kc = ks * 2;
            uint32_t afr[2][4];
#pragma unroll
            for (int mt = 0; mt < 2; ++mt) {
                int row = mw + mt * 16 + ri + (quad & 1) * 8;
                int ch = (kc + (quad >> 1)) ^ (row & 7);
                ldmatrix_x4(afr[mt], abase + row * 128 + ch * 16);
            }
#pragma unroll
            for (int np = 0; np < 4; ++np) {
                uint32_t bfr[4];
                int nrow = nw + np * 16 + ri + (quad >> 1) * 8;
                int ch = (kc + (quad & 1)) ^ (nrow & 7);
                ldmatrix_x4(bfr, bbase + nrow * 128 + ch * 16);
#pragma unroll
                for (int mt = 0; mt < 2; ++mt) {
                    mma_bf16(acc[mt][np * 2],     afr[mt], bfr[0], bfr[1]);
                    mma_bf16(acc[mt][np * 2 + 1], afr[mt], bfr[2], bfr[3]);
                }
            }
        }
        __syncthreads();
    }

    // raw partial store (no bias/act)
#pragma unroll
    for (int mt = 0; mt < 2; ++mt) {
#pragma unroll
        for (int nt = 0; nt < 8; ++nt) {
            int col = bn + nw + nt * 8 + (lane & 3) * 2;
            if (col >= ga.N) continue;
#pragma unroll
            for (int h = 0; h < 2; ++h) {
                int row = bm + mw + mt * 16 + (lane >> 2) + h * 8;
                if (row >= ga.M) continue;
#pragma unroll
                for (int q = 0; q < 2; ++q) {
                    int c = col + q;
                    Cp[(size_t)row * 128 + c] = acc[mt][nt][h * 2 + q];
                }
            }
        }
    }
}

__global__ void c1red_kernel(const float* __restrict__ c1b) {
    const long n = (long)AOROWS * 128;
    for (long i = blockIdx.x * (long)blockDim.x + threadIdx.x; i < n;
         i += (long)gridDim.x * blockDim.x) {
        float v = g_c1p[i] + g_c1p[n + i] + c1b[(int)(i & 127)];
        g_c1o[i] = (v >= 0.f) ? v : 0.2f * v;
    }
}

// ================= embed GEMM: fp16 split-2, drained every 4 chunks =================
struct SegH { const __half* A; const __half* B; int shift; float scale; };
struct HArgs { SegH segs[9]; const float* bias; float* C; };

__device__ __forceinline__ void tg_load_h(const HArgs& ha, uint32_t smb, int ci, int p,
                                          int bm, int bn, int tid) {
    const SegH s = ha.segs[ci >> 5];
    const int k0 = (ci & 31) * 64;
    const uint32_t abase = smb + p * 32768;
    const uint32_t bbase = abase + 16384;
#pragma unroll
    for (int g = 0; g < 2; ++g) {
        int id = tid + g * 512;
        int row = id >> 3, c = id & 7;
        uint32_t soff = row * 128 + ((c ^ (row & 7)) * 16);
        {
            int m = bm + row;
            const void* src = s.A;
            int sz = 0;
            if (m < M_EMB) {
                int t = m % Tn;
                int ts = t + s.shift;
                if (ts >= 0 && ts < Tn) { src = s.A + (size_t)(m + s.shift) * 2048 + k0 + c * 8; sz = 16; }
            }
            cp_async16(abase + soff, src, sz);
        }
        {
            int n = bn + row;    // N = 2048, always in range
            cp_async16(bbase + soff, s.B + (size_t)n * 2048 + k0 + c * 8, 16);
        }
    }
    asm volatile("cp.async.commit_group;" ::: "memory");
}

__global__ void __launch_bounds__(512) tgemm_emb(HArgs ha) {
    extern __shared__ char gsm[];
    const uint32_t smb = smem_to_u32(gsm);
    const int tid = threadIdx.x;
    const int wid = tid >> 5, lane = tid & 31;
    const int bm = blockIdx.y * 128;
    const int bn = blockIdx.x * 128;
    const int mw = (wid & 3) * 32;
    const int nw = (wid >> 2) * 32;
    const int nchunk = 9 * 32;

    float sum[2][4][4];
    float acc[2][4][4];
#pragma unroll
    for (int i = 0; i < 2; ++i)
#pragma unroll
        for (int j = 0; j < 4; ++j)
#pragma unroll
            for (int q = 0; q < 4; ++q) sum[i][j][q] = 0.f;

    tg_load_h(ha, smb, 0, 0, bm, bn, tid);

    const int quad = lane >> 3, ri = lane & 7;

    for (int ci = 0; ci < nchunk; ++ci) {
        if (ci + 1 < nchunk) {
            tg_load_h(ha, smb, ci + 1, (ci + 1) & 1, bm, bn, tid);
            asm volatile("cp.async.wait_group 1;" ::: "memory");
        } else {
            asm volatile("cp.async.wait_group 0;" ::: "memory");
        }
        __syncthreads();

        const uint32_t abase = smb + (ci & 1) * 32768;
        const uint32_t bbase = abase + 16384;
        const bool fresh = ((ci & 3) == 0);
#pragma unroll
        for (int ks = 0; ks < 4; ++ks) {
            const int kc = ks * 2;
            uint32_t afr[2][4];
#pragma unroll
            for (int mt = 0; mt < 2; ++mt) {
                int row = mw + mt * 16 + ri + (quad & 1) * 8;
                int ch = (kc + (quad >> 1)) ^ (row & 7);
                ldmatrix_x4(afr[mt], abase + row * 128 + ch * 16);
            }
#pragma unroll
            for (int bt = 0; bt < 2; ++bt) {
                uint32_t bfr[4];
                int nrow = nw + bt * 16 + ri + (quad >> 1) * 8;
                int ch = (kc + (quad & 1)) ^ (nrow & 7);
                ldmatrix_x4(bfr, bbase + nrow * 128 + ch * 16);
#pragma unroll
                for (int mt = 0; mt < 2; ++mt) {
                    if (fresh && ks == 0) {
                        mma_f16_z(acc[mt][bt * 2],     afr[mt], bfr[0], bfr[1]);
                        mma_f16_z(acc[mt][bt * 2 + 1], afr[mt], bfr[2], bfr[3]);
                    } else {
                        mma_f16(acc[mt][bt * 2],     afr[mt], bfr[0], bfr[1]);
                        mma_f16(acc[mt][bt * 2 + 1], afr[mt], bfr[2], bfr[3]);
                    }
                }
            }
        }
        // drain every 4 chunks (chain-16): RN adds bound RZ-chain bias at ~2e-6
        // while keeping drain FFMA issue cost low. Segment (32-chunk) boundaries
        // are multiples of 4, so each drain group has one scale.
        if ((ci & 3) == 3) {
            const float scl = ha.segs[ci >> 5].scale;
#pragma unroll
            for (int i = 0; i < 2; ++i)
#pragma unroll
                for (int j = 0; j < 4; ++j)
#pragma unroll
                    for (int q = 0; q < 4; ++q) sum[i][j][q] += acc[i][j][q] * scl;
        }
        __syncthreads();
    }

#pragma unroll
    for (int mt = 0; mt < 2; ++mt) {
#pragma unroll
        for (int nt = 0; nt < 4; ++nt) {
            int col = bn + nw + nt * 8 + (lane & 3) * 2;
#pragma unroll
            for (int h = 0; h < 2; ++h) {
                int row = bm + mw + mt * 16 + (lane >> 2) + h * 8;
                if (row >= M_EMB) continue;
#pragma unroll
                for (int q = 0; q < 2; ++q) {
                    int c = col + q;
                    float v = sum[mt][nt][h * 2 + q] + ha.bias[c];
                    ha.C[(size_t)row * Fd + c] = fmaxf(v, 0.f);
                }
            }
        }
    }
}

// ================= split kernels =================
#define RSCALE 2048.f
__global__ void split2h_x(const float* __restrict__ s, __half* h, __half* l, long n) {
    for (long i = blockIdx.x * (long)blockDim.x + threadIdx.x; i < n;
         i += (long)gridDim.x * blockDim.x) {
        float x = s[i];
        __half a = __float2half(x);
        h[i] = a; l[i] = __float2half((x - __half2float(a)) * RSCALE);
    }
}
__global__ void split2h_wk(const float* __restrict__ w, __half* h, __half* l) {
    const long n = 3L * Fd * Fd;
    for (long i = blockIdx.x * (long)blockDim.x + threadIdx.x; i < n;
         i += (long)gridDim.x * blockDim.x) {
        long sh = i / ((long)Fd * Fd);
        long rem = i - sh * (long)Fd * Fd;
        float x = w[rem * 3 + sh];
        __half a = __float2half(x);
        h[i] = a; l[i] = __float2half((x - __half2float(a)) * RSCALE);
    }
}
__global__ void split2_kernel(const float* __restrict__ s, __nv_bfloat16* h,
                              __nv_bfloat16* l, long n) {
    for (long i = blockIdx.x * (long)blockDim.x + threadIdx.x; i < n;
         i += (long)gridDim.x * blockDim.x) {
        float x = s[i];
        __nv_bfloat16 a = __float2bfloat16(x);
        h[i] = a; l[i] = __float2bfloat16(x - __bfloat162float(a));
    }
}
__global__ void split2_c1w_kernel(const float* __restrict__ w, __nv_bfloat16* h,
                                  __nv_bfloat16* l) {
    const long n = 3L * 128 * Fd;
    for (long i = blockIdx.x * (long)blockDim.x + threadIdx.x; i < n;
         i += (long)gridDim.x * blockDim.x) {
        long sh = i / (128L * Fd);
        long rem = i - sh * 128L * Fd;
        float x = w[rem * 3 + sh];
        __nv_bfloat16 a = __float2bfloat16(x);
        h[i] = a; l[i] = __float2bfloat16(x - __bfloat162float(a));
    }
}

// ================= CAS + actionness =================
__global__ void __launch_bounds__(320) cas_kernel(const float* __restrict__ wcls,
                                                  float* __restrict__ dout)
{
    __shared__ float embs[5 * Fd];
    __shared__ float cres[5 * NC];
    const int b  = blockIdx.x / 150;
    const int t0 = (blockIdx.x % 150) * 5;
    const float* src = g_emb + ((size_t)b * Tn + t0) * Fd;
    for (int i = threadIdx.x; i < 5 * Fd; i += 320) embs[i] = src[i];
    __syncthreads();

    const int w = threadIdx.x >> 5, lane = threadIdx.x & 31;
    const int tl = w >> 1, cg = (w & 1) * 10;
    for (int c = cg; c < cg + 10; ++c) {
        float acc = 0.f;
        const float* wr = wcls + (size_t)c * Fd;
        const float* er = embs + tl * Fd;
        for (int e = lane; e < Fd; e += 32) acc += er[e] * wr[e];
#pragma unroll
        for (int off = 16; off; off >>= 1) acc += __shfl_down_sync(0xffffffffu, acc, off);
        if (lane == 0) cres[tl * NC + c] = fmaxf(acc, 0.f);
    }
    __syncthreads();

    if (threadIdx.x < 100) {
        int tl2 = threadIdx.x / NC, c2 = threadIdx.x % NC;
        dout[OUT_CAS + ((size_t)(b * Tn + t0 + tl2)) * NC + c2] = cres[tl2 * NC + c2];
    }
    if (threadIdx.x < 5) {
        float s = 0.f;
        for (int c = 0; c < NC; ++c) s += cres[threadIdx.x * NC + c];
        dout[OUT_ACT + b * Tn + t0 + threadIdx.x] = s;
    }
}

// ================= a2 =================
__global__ void a2_kernel(const float* __restrict__ tf1w, const float* __restrict__ tf1b,
                          const float* __restrict__ tf2w, const float* __restrict__ tf2b,
                          float* __restrict__ dout)
{
    __shared__ float a[Tn], a1[Tn];
    const int b = blockIdx.x;
    for (int t = threadIdx.x; t < Tn; t += blockDim.x) a[t] = dout[OUT_ACT + b*Tn + t];
    __syncthreads();
    for (int t = threadIdx.x; t < Tn; t += blockDim.x) {
        float v = tf1b[0];
#pragma unroll
        for (int k = 0; k < 3; ++k) { int tt = t+k-1; if (tt>=0 && tt<Tn) v += tf1w[k]*a[tt]; }
        a1[t] = fmaxf(v, 0.f);
    }
    __syncthreads();
    for (int t = threadIdx.x; t < Tn; t += blockDim.x) {
        float v = tf2b[0];
#pragma unroll
        for (int k = 0; k < 3; ++k) { int tt = t+k-1; if (tt>=0 && tt<Tn) v += tf2w[k]*a1[tt]; }
        dout[OUT_A2 + b*Tn + t] = fmaxf(v, 0.f);
    }
}

// ================= sorting =================
__device__ __forceinline__ unsigned int fkey(float v) {
    unsigned int b = __float_as_uint(v);
    return (b & 0x80000000u) ? ~b : (b | 0x80000000u);
}
__device__ __forceinline__ float fdec(unsigned int u) {
    unsigned int b = (u & 0x80000000u) ? (u ^ 0x80000000u) : ~u;
    return __uint_as_float(b);
}
__device__ void bitonic1024_u64(unsigned long long* key, int tid) {
    for (int k = 2; k <= 1024; k <<= 1)
        for (int j = k >> 1; j > 0; j >>= 1) {
            __syncthreads();
            for (int i = tid; i < 1024; i += 512) {
                int ixj = i ^ j;
                if (ixj > i) {
                    bool up = ((i & k) == 0);
                    unsigned long long a = key[i], b2 = key[ixj];
                    bool sw = up ? (a > b2) : (a < b2);
                    if (sw) { key[i] = b2; key[ixj] = a; }
                }
            }
        }
    __syncthreads();
}
__device__ void bitonic1024_u32(unsigned int* key, int tid) {
    for (int k = 2; k <= 1024; k <<= 1)
        for (int j = k >> 1; j > 0; j >>= 1) {
            __syncthreads();
            for (int i = tid; i < 1024; i += 512) {
                int ixj = i ^ j;
                if (ixj > i) {
                    bool up = ((i & k) == 0);
                    unsigned int a = key[i], b2 = key[ixj];
                    bool sw = up ? (a > b2) : (a < b2);
                    if (sw) { key[i] = b2; key[ixj] = a; }
                }
            }
        }
    __syncthreads();
}

// fused: easy_act top-150 sort + median + amax + morphology + hard scores.
// amax = sorted key[0] (exact max, bit-identical to an fmaxf reduction);
// median = mean of sorted ranks 374/375; morph windows identical to reference.
__global__ void __launch_bounds__(512) sortmorph_kernel(const float* __restrict__ dout) {
    __shared__ unsigned long long key[1024];
    __shared__ float a[Tn];
    __shared__ float bin[Tn];
    const int b = blockIdx.x, tid = threadIdx.x;
    for (int i = tid; i < 1024; i += 512) {
        if (i < Tn) {
            float v = dout[OUT_ACT + b*Tn + i];
            a[i] = v;
            unsigned int nu = ~fkey(v);
            key[i] = ((unsigned long long)nu << 32) | (unsigned int)i;
        } else key[i] = 0xFFFFFFFFFFFFFFFFull;
    }
    bitonic1024_u64(key, tid);     // trailing __syncthreads inside
    for (int i = tid; i < 150; i += 512) g_idx[b*150 + i] = (int)(key[i] & 0xffffffffu);

    const float v0 = fdec(~(unsigned int)(key[374] >> 32));
    const float v1 = fdec(~(unsigned int)(key[375] >> 32));
    const float med = 0.5f * (v0 + v1);
    const float amax = fdec(~(unsigned int)(key[0] >> 32));

    for (int t = tid; t < Tn; t += 512) bin[t] = (a[t] > med) ? 1.f : 0.f;
    __syncthreads();
    for (int t = tid; t < Tn; t += 512) {
        float e3 = 1.f, e6 = 1.f, d6 = 0.f, d3 = 0.f;
#pragma unroll
        for (int o = -1; o <= 1; ++o) { int u = t+o; float v = (u>=0&&u<Tn)?bin[u]:0.f; e3 = fminf(e3,v); d3 = fmaxf(d3,v); }
#pragma unroll
        for (int o = -3; o <= 2; ++o) { int u = t+o; float v = (u>=0&&u<Tn)?bin[u]:0.f; e6 = fminf(e6,v); }
#pragma unroll
        for (int o = -2; o <= 3; ++o) { int u = t+o; float v = (u>=0&&u<Tn)?bin[u]:0.f; d6 = fmaxf(d6,v); }
        g_sel[1*Bn*Tn + b*Tn + t] = amax - a[t];
        g_sel[2*Bn*Tn + b*Tn + t] = a[t] * (e3 - e6);
        g_sel[3*Bn*Tn + b*Tn + t] = a[t] * (d6 - d3);
    }
}

__global__ void __launch_bounds__(512) sort_gen_kernel() {
    __shared__ unsigned long long key[1024];
    const int aid = blockIdx.x / 16 + 1;
    const int b = blockIdx.x % 16;
    const int tid = threadIdx.x;
    const float* sc = g_sel + aid*Bn*Tn + b*Tn;
    const unsigned int msk = (aid == 1) ? 0xFFFFFFF8u : 0xFFFFFFFFu;
    for (int i = tid; i < 1024; i += 512) {
        if (i < Tn) {
            unsigned int nu = ~(fkey(sc[i]) & msk);
            key[i] = ((unsigned long long)nu << 32) | (unsigned int)i;
        } else key[i] = 0xFFFFFFFFFFFFFFFFull;
    }
    bitonic1024_u64(key, tid);
    if (aid == 1) { for (int i = tid; i < 150; i += 512) g_idx[2400 + b*150 + i] = (int)(key[i] & 0xffffffffu); }
    else if (aid == 2) { if (tid < 37) g_idx[4800 + b*37 + tid] = (int)(key[tid] & 0xffffffffu); }
    else { if (tid < 37) g_idx[5392 + b*37 + tid] = (int)(key[tid] & 0xffffffffu); }
}

__global__ void __launch_bounds__(256) gather_kernel(float* __restrict__ dout) {
    const int r = blockIdx.x; // 0..5983
    int b, j, srcidx, set = -1;
    float* dst;
    if (r < 2400) {
        b = r/150; j = r%150; srcidx = g_idx[b*150 + j];
        dst = dout + OUT_EA + (size_t)r * Fd;
        if (j < 148) set = j / 37;
    } else if (r < 4800) {
        int rr = r - 2400; b = rr/150; j = rr%150; srcidx = g_idx[2400 + b*150 + j];
        dst = dout + OUT_EB + (size_t)rr * Fd;
        if (j < 148) set = 4 + j / 37;
    } else if (r < 5392) {
        int rr = r - 4800; b = rr/37; j = rr%37; srcidx = g_idx[4800 + rr];
        dst = dout + OUT_HA + (size_t)rr * Fd; set = 8;
    } else {
        int rr = r - 5392; b = rr/37; j = rr%37; srcidx = g_idx[5392 + rr];
        dst = dout + OUT_HB + (size_t)rr * Fd; set = 9;
    }
    const float4* src = reinterpret_cast<const float4*>(g_emb + ((size_t)b*Tn + srcidx)*Fd);
    float4* d4 = reinterpret_cast<float4*>(dst);
    __nv_bfloat16* th = nullptr; __nv_bfloat16* tl = nullptr;
    if (set >= 0) {
        size_t tb = ((size_t)set*SROWS + b*37 + (j % 37))*Fd;
        th = g_tok2 + tb;
        tl = g_tok2 + (size_t)TOKROWS*Fd + tb;
    }
    for (int i = threadIdx.x; i < Fd/4; i += 256) {
        float4 v = src[i];
        d4[i] = v;
        if (th) {
            float vv[4] = {v.x, v.y, v.z, v.w};
#pragma unroll
            for (int q = 0; q < 4; ++q) {
                __nv_bfloat16 h = __float2bfloat16(vv[q]);
                th[i*4 + q] = h;
                tl[i*4 + q] = __float2bfloat16(vv[q] - __bfloat162float(h));
            }
        }
    }
}

// ================= attention (writes aopre split-2 planes) =================
__global__ void __launch_bounds__(256) attn_kernel() {
    __shared__ float qt[37*64];
    __shared__ float kt[37*64];
    __shared__ float s[37*37];
    const int id = blockIdx.x;
    const int h = id & 3, b = (id >> 2) & 15, m = id >> 6;
    const int rh = m >> 1, role = m & 1;
    const int as = d_aset[rh], bs = d_bset[rh];
    const int qset = role ? as : bs;
    const int kvset = role ? bs : as;
    const int trowbase = role ? 37 : 0;
    const int tid = threadIdx.x;
    const float scale = 0.044194173824159216f; // 1/sqrt(512)

    const float* Qb = g_qkv + ((size_t)(qset*SROWS + b*37)) * K6 + h*512;
    const float* Kb = g_qkv + ((size_t)(kvset*SROWS + b*37)) * K6 + 2048 + h*512;
    const float* Vb = g_qkv + ((size_t)(kvset*SROWS + b*37)) * K6 + 4096 + h*512;

    for (int i = tid; i < 1369; i += 256) s[i] = 0.f;
    for (int dt = 0; dt < 8; ++dt) {
        __syncthreads();
        for (int i = tid; i < 2368; i += 256) {
            int q = i >> 6, d = i & 63;
            qt[i] = Qb[(size_t)q*K6 + dt*64 + d];
            kt[i] = Kb[(size_t)q*K6 + dt*64 + d];
        }
        __syncthreads();
        for (int p = tid; p < 1369; p += 256) {
            int q = p / 37, k = p % 37;
            const float* qr = qt + q*64;
            const float* kr = kt + k*64;
            float acc = 0.f;
#pragma unroll
            for (int d = 0; d < 64; ++d) acc += qr[d] * kr[d];
            s[p] += acc;
        }
    }
    __syncthreads();
    {
        const int w = tid >> 5, lane = tid & 31;
        for (int r = w; r < 37; r += 8) {
            float sv0 = s[r*37 + lane] * scale;
            float sv1 = (lane < 5) ? s[r*37 + 32 + lane] * scale : -FLT_MAX;
            float mx = fmaxf(sv0, sv1);
#pragma unroll
            for (int off = 16; off; off >>= 1) mx = fmaxf(mx, __shfl_xor_sync(0xffffffffu, mx, off));
            float e0 = expf(sv0 - mx);
            float e1 = (lane < 5) ? expf(sv1 - mx) : 0.f;
            float sum = e0 + e1;
#pragma unroll
            for (int off = 16; off; off >>= 1) sum += __shfl_xor_sync(0xffffffffu, sum, off);
            float inv = 1.f / sum;
            s[r*37 + lane] = e0 * inv;
            if (lane < 5) s[r*37 + 32 + lane] = e1 * inv;
        }
    }
    const size_t rowbase = (size_t)(rh*1184 + b*74 + trowbase);
    for (int dt = 0; dt < 8; ++dt) {
        __syncthreads();
        for (int i = tid; i < 2368; i += 256) {
            int k = i >> 6, d = i & 63;
            kt[i] = Vb[(size_t)k*K6 + dt*64 + d];
        }
        __syncthreads();
        for (int p = tid; p < 2368; p += 256) {
            int q = p >> 6, d = p & 63;
            const float* sr = s + q*37;
            float acc = 0.f;
#pragma unroll
            for (int k = 0; k < 37; ++k) acc += sr[k] * kt[k*64 + d];
            size_t off = (rowbase + q)*Fd + h*512 + dt*64 + d;
            __nv_bfloat16 hh = __float2bfloat16(acc);
            g_aop2[off] = hh;
            g_aop2[(size_t)AOROWS*Fd + off] = __float2bfloat16(acc - __bfloat162float(hh));
        }
    }
}

// ================= c2 + l1 + l2 fused =================
__global__ void __launch_bounds__(256) tail_kernel(
    const float* __restrict__ c2w, const float* __restrict__ c2b,
    const float* __restrict__ l1w, const float* __restrict__ l1b,
    const float* __restrict__ l2w, const float* __restrict__ l2b,
    float* __restrict__ dout)
{
    __shared__ float sm[74*128];
    const int rb = blockIdx.x;
    const int tid = threadIdx.x;
    for (int i = tid; i < 74*128; i += 256)
        sm[i] = g_c1o[(size_t)rb*74*128 + i];
    __syncthreads();

    const int o = tid & 31;
    const int tbase = tid >> 5;
    float r[10];
    int nt = 0;
    for (int t = tbase; t < 74; t += 8) {
        float v = c2b[o];
#pragma unroll
        for (int k = 0; k < 3; ++k) {
            int tt = t + k - 1;
            if (tt >= 0 && tt < 74) {
                const float* row = sm + tt*128;
                const float* w = c2w + o*384 + k;
#pragma unroll 16
                for (int c = 0; c < 128; ++c) v += row[c] * w[c*3];
            }
        }
        r[nt++] = (v >= 0.f) ? v : 0.2f * v;
    }
    __syncthreads();
    { int i = 0; for (int t = tbase; t < 74; t += 8) sm[o*74 + t] = r[i++]; }
    __syncthreads();

    for (int p = tid; p < 320; p += 256) {
        int c = p / 10, j = p % 10;
        float v = l1b[j];
        const float* y = sm + c*74;
        const float* w = l1w + j*74;
        for (int t = 0; t < 74; ++t) v += y[t] * w[t];
        sm[2368 + p] = (v >= 0.f) ? v : 0.2f * v;
    }
    __syncthreads();
    float ps = 0.f;
    for (int p = tid; p < 320; p += 256) ps += sm[2368 + p] * l2w[p];
    sm[3000 + tid] = ps;
    __syncthreads();
    for (int s = 128; s > 0; s >>= 1) { if (tid < s) sm[3000+tid] += sm[3000+tid+s]; __syncthreads(); }
    if (tid == 0) {
        float x = sm[3000] + l2b[0];
        dout[OUT_RH + rb] = 1.f / (1.f + expf(-x));
    }
}

// ================= video scores =================
__global__ void __launch_bounds__(512) vsort_kernel(const float* __restrict__ dout) {
    __shared__ unsigned int key[1024];
    const int bc = blockIdx.x;
    const int b = bc / NC, c = bc % NC;
    const int tid = threadIdx.x;
    for (int i = tid; i < 1024; i += 512)
        key[i] = (i < Tn) ? ~fkey(dout[OUT_CAS + (size_t)(b*Tn + i)*NC + c]) : 0xFFFFFFFFu;
    bitonic1024_u32(key, tid);
    if (tid == 0) {
        float s = 0.f;
        for (int i = 0; i < 150; ++i) s += fdec(~key[i]);
        g_vmean[bc] = s / 150.f;
    }
}
__global__ void vsoftmax_kernel(float* __restrict__ dout) {
    const int b = blockIdx.x, t = threadIdx.x;
    float v = (t < NC) ? g_vmean[b*NC + t] : -FLT_MAX;
    float mx = v;
#pragma unroll
    for (int off = 16; off; off >>= 1) mx = fmaxf(mx, __shfl_xor_sync(0xffffffffu, mx, off));
    float e = (t < NC) ? expf(v - mx) : 0.f;
    float sum = e;
#pragma unroll
    for (int off = 16; off; off >>= 1) sum += __shfl_xor_sync(0xffffffffu, sum, off);
    if (t < NC) dout[OUT_VS + b*NC + t] = e / sum;
}

// ================= launch =================
extern "C" void kernel_launch(void* const* d_in, const int* in_sizes, int n_in,
                              void* d_out, int out_size) {
    const float* x    = (const float*)d_in[0];
    const float* wemb = (const float*)d_in[1];
    const float* bemb = (const float*)d_in[2];
    const float* wcls = (const float*)d_in[3];
    const float* tf1w = (const float*)d_in[4];
    const float* tf1b = (const float*)d_in[5];
    const float* tf2w = (const float*)d_in[6];
    const float* tf2b = (const float*)d_in[7];
    const float* inw  = (const float*)d_in[8];
    const float* inb  = (const float*)d_in[9];
    const float* outw = (const float*)d_in[10];
    const float* outb = (const float*)d_in[11];
    const float* c1w  = (const float*)d_in[12];
    const float* c1b  = (const float*)d_in[13];
    const float* c2w  = (const float*)d_in[14];
    const float* c2b  = (const float*)d_in[15];
    const float* l1w  = (const float*)d_in[16];
    const float* l1b  = (const float*)d_in[17];
    const float* l2w  = (const float*)d_in[18];
    const float* l2b  = (const float*)d_in[19];
    float* dout = (float*)d_out;

    float *p_emb, *p_qkv, *p_c1o, *p_c1p;
    __half *p_xh, *p_wkh;
    __nv_bfloat16 *p_tok2, *p_inw2, *p_aop2, *p_outw2, *p_ao2, *p_c1w2;
    cudaGetSymbolAddress((void**)&p_emb,  g_emb);
    cudaGetSymbolAddress((void**)&p_qkv,  g_qkv);
    cudaGetSymbolAddress((void**)&p_c1o,  g_c1o);
    cudaGetSymbolAddress((void**)&p_c1p,  g_c1p);
    cudaGetSymbolAddress((void**)&p_xh,   g_xh);
    cudaGetSymbolAddress((void**)&p_wkh,  g_wkh);
    cudaGetSymbolAddress((void**)&p_tok2, g_tok2);
    cudaGetSymbolAddress((void**)&p_inw2, g_inw2);
    cudaGetSymbolAddress((void**)&p_aop2, g_aop2);
    cudaGetSymbolAddress((void**)&p_outw2,g_outw2);
    cudaGetSymbolAddress((void**)&p_c1w2, g_c1w2);
    cudaGetSymbolAddress((void**)&p_ao2,  g_ao2);

    cudaFuncSetAttribute(tgemm, cudaFuncAttributeMaxDynamicSharedMemorySize, TG_SMEM);
    cudaFuncSetAttribute(tgemm_c1, cudaFuncAttributeMaxDynamicSharedMemorySize, TG_SMEM);
    cudaFuncSetAttribute(tgemm_emb, cudaFuncAttributeMaxDynamicSharedMemorySize, TG_SMEM);

    const size_t XP   = (size_t)M_EMB * Fd;
    const size_t WKP  = (size_t)3 * Fd * Fd;
    const size_t TOKP = (size_t)TOKROWS * Fd;
    const size_t INWP = (size_t)K6 * Fd;
    const size_t AOP  = (size_t)AOROWS * Fd;
    const size_t OWP  = (size_t)Fd * Fd;
    const size_t C1P  = (size_t)3 * 128 * Fd;

    // splits
    split2h_x<<<2048, 256>>>(x, p_xh, p_xh + XP, (long)XP);
    split2h_wk<<<2048, 256>>>(wemb, p_wkh, p_wkh + WKP);
    split2_kernel<<<2048, 256>>>(inw, p_inw2, p_inw2 + INWP, (long)INWP);
    split2_kernel<<<1024, 256>>>(outw, p_outw2, p_outw2 + OWP, (long)OWP);
    split2_c1w_kernel<<<256, 256>>>(c1w, p_c1w2, p_c1w2 + C1P);

    // embed conv GEMM: fp16 split-2 {hh, hl, lh} x 3 shifts, drained every 4 chunks
    {
        HArgs ha = {};
        const float S = 1.f / RSCALE;
        const int pa[3] = {0, 0, 1};
        const int pb[3] = {0, 1, 0};
        const float ps[3] = {1.f, S, S};
        int q = 0;
        for (int sh = 0; sh < 3; ++sh)
            for (int pr = 0; pr < 3; ++pr) {
                ha.segs[q].A = p_xh + (size_t)pa[pr] * XP;
                ha.segs[q].B = p_wkh + (size_t)pb[pr] * WKP + (size_t)sh * Fd * Fd;
                ha.segs[q].shift = sh - 1;
                ha.segs[q].scale = ps[pr];
                ++q;
            }
        ha.bias = bemb; ha.C = p_emb;
        tgemm_emb<<<dim3(Fd/128, (M_EMB + 127)/128), 512, TG_SMEM>>>(ha);
    }

    cas_kernel<<<Bn*150, 320>>>(wcls, dout);
    a2_kernel<<<Bn, 256>>>(tf1w, tf1b, tf2w, tf2b, dout);
    sortmorph_kernel<<<Bn, 512>>>(dout);
    sort_gen_kernel<<<48, 512>>>();
    gather_kernel<<<5984, 256>>>(dout);

    // QKV GEMM: bf16 split-2 x 3 products (undrained, proven fast)
    {
        GArgs ga = {};
        const int pa[3] = {0,0,1}, pb[3] = {0,1,0};
        for (int pr = 0; pr < 3; ++pr) {
            ga.segs[pr].A = p_tok2 + (size_t)pa[pr]*TOKP;
            ga.segs[pr].B = p_inw2 + (size_t)pb[pr]*INWP;
            ga.segs[pr].shift = 0;
        }
        ga.nseg = 3; ga.M = TOKROWS; ga.N = K6; ga.Tper = 0;
        ga.C = p_qkv; ga.bias = inb; ga.act = 0; ga.ldc = K6;
        tgemm<<<dim3(K6/128, (TOKROWS+127)/128), 256, TG_SMEM>>>(ga);
    }

    attn_kernel<<<1536, 256>>>();

    // out-proj GEMM: bf16 split-2, epilogue writes split-2 planes
    {
        GArgs ga = {};
        const int pa[3] = {0,0,1}, pb[3] = {0,1,0};
        for (int pr = 0; pr < 3; ++pr) {
            ga.segs[pr].A = p_aop2 + (size_t)pa[pr]*AOP;
            ga.segs[pr].B = p_outw2 + (size_t)pb[pr]*OWP;
            ga.segs[pr].shift = 0;
        }
        ga.nseg = 3; ga.M = AOROWS; ga.N = Fd; ga.Tper = 0;
        ga.C = nullptr; ga.bias = outb; ga.act = 0; ga.ldc = Fd;
        ga.So_h = p_ao2; ga.So_l = p_ao2 + AOP;
        tgemm<<<dim3(Fd/128, AOROWS/128), 256, TG_SMEM>>>(ga);
    }

    // c1 conv GEMM: bf16 split-2 x 3 products x 3 shifts, N=128 — split-K across
    // 2 grid-x parts (segs 0-4 / 5-8) into raw partials, then combine.
    {
        GArgs ga = {};
        const int pa[3] = {0,0,1}, pb[3] = {0,1,0};
        int q = 0;
        for (int sh = 0; sh < 3; ++sh)
            for (int pr = 0; pr < 3; ++pr) {
                ga.segs[q].A = p_ao2 + (size_t)pa[pr]*AOP;
                ga.segs[q].B = p_c1w2 + (size_t)pb[pr]*C1P + (size_t)sh*128*Fd;
                ga.segs[q].shift = sh - 1;
                ++q;
            }
        ga.nseg = 9; ga.M = AOROWS; ga.N = 128; ga.Tper = 74;
        ga.C = p_c1p; ga.bias = nullptr; ga.act = 0; ga.ldc = 128;
        tgemm_c1<<<dim3(2, AOROWS/128), 256, TG_SMEM>>>(ga);
        c1red_kernel<<<2048, 256>>>(c1b);
    }

    tail_kernel<<<192, 256>>>(c2w, c2b, l1w, l1b, l2w, l2b, dout);
    vsort_kernel<<<Bn*NC, 512>>>(dout);
    vsoftmax_kernel<<<Bn, 32>>>(dout);
}